// round 1
// baseline (speedup 1.0000x reference)
#include <cuda_runtime.h>
#include <cuda_bf16.h>
#include <math.h>

// ---------------- problem constants (fixed by reference generator) -----------
#define BATCH   8
#define SEQ_L   32
#define DIM     2048
#define KVR     512
#define QR      768
#define NH      16
#define DNR     128
#define DR      64
#define DV      128
#define MAXT    4096
#define START_P 4064          // MAXT - SEQ_L
#define QKD     192           // DNR + DR
#define CATD    576           // KVR + DR
#define MBL     256           // BATCH*SEQ_L
#define ROWSPB  512           // SEQ_L*NH
#define SCALE_F 0.07216878364870323f   // 1/sqrt(192)

// ---------------- scratch (device globals; allocation-free) -----------------
__device__ float g_qd  [MBL * QR];            // x @ Wqd^T
__device__ float g_qn  [MBL * QR];            // rmsnorm(qd)
__device__ float g_q   [MBL * NH * QKD];      // qn @ Wqu^T  (256 x 3072)
__device__ float g_kv  [MBL * CATD];          // fresh kv rows, cols 512..575 roped
__device__ float g_qcat[BATCH * ROWSPB * CATD]; // per-b (512 x 576): q_abs | roped q_rope
__device__ float g_S   [(size_t)BATCH * ROWSPB * MAXT]; // scores -> P (64 MB)
__device__ float g_O   [BATCH * ROWSPB * KVR];          // P @ KV
__device__ float g_o2  [MBL * (NH * DV)];               // value up-proj (256 x 2048)

// ================= generic NT GEMM: C = A(M,K) * B(N,K)^T ====================
// 64x64 tile, BK=8, 256 threads, 4x4 micro. M,N multiples of 64; K mult of 8.
__global__ void gemm_nt64(const float* __restrict__ A, int lda,
                          const float* __restrict__ B, int ldb,
                          float* __restrict__ C, int ldc, int K) {
    __shared__ float As[8][64];
    __shared__ float Bs[8][64];
    const int m0 = blockIdx.y * 64, n0 = blockIdx.x * 64;
    const int tid = threadIdx.x;
    const int ty = tid >> 4, tx = tid & 15;
    const int lr = tid >> 2, lc = (tid & 3) * 2;
    float acc[4][4] = {};
    for (int k0 = 0; k0 < K; k0 += 8) {
        float2 av = *(const float2*)&A[(size_t)(m0 + lr) * lda + k0 + lc];
        float2 bv = *(const float2*)&B[(size_t)(n0 + lr) * ldb + k0 + lc];
        As[lc][lr] = av.x; As[lc + 1][lr] = av.y;
        Bs[lc][lr] = bv.x; Bs[lc + 1][lr] = bv.y;
        __syncthreads();
#pragma unroll
        for (int kk = 0; kk < 8; kk++) {
            float a[4], b[4];
#pragma unroll
            for (int i = 0; i < 4; i++) a[i] = As[kk][ty * 4 + i];
#pragma unroll
            for (int j = 0; j < 4; j++) b[j] = Bs[kk][tx * 4 + j];
#pragma unroll
            for (int i = 0; i < 4; i++)
#pragma unroll
                for (int j = 0; j < 4; j++) acc[i][j] += a[i] * b[j];
        }
        __syncthreads();
    }
#pragma unroll
    for (int i = 0; i < 4; i++)
#pragma unroll
        for (int j = 0; j < 4; j++)
            C[(size_t)(m0 + ty * 4 + i) * ldc + n0 + tx * 4 + j] = acc[i][j];
}

// ================= RMSNorm over rows of 768 ==================================
__global__ void rms_kernel(const float* __restrict__ w) {
    const int row = blockIdx.x;
    const float* xr = g_qd + row * QR;
    float* yr = g_qn + row * QR;
    __shared__ float red[256];
    const int tid = threadIdx.x;
    float v[3], s = 0.f;
#pragma unroll
    for (int i = 0; i < 3; i++) { v[i] = xr[tid + i * 256]; s += v[i] * v[i]; }
    red[tid] = s; __syncthreads();
    for (int o = 128; o > 0; o >>= 1) {
        if (tid < o) red[tid] += red[tid + o];
        __syncthreads();
    }
    const float r = rsqrtf(red[0] / (float)QR + 1.1920929e-07f);
    __syncthreads();
#pragma unroll
    for (int i = 0; i < 3; i++) yr[tid + i * 256] = v[i] * r * w[tid + i * 256];
}

// ================= rope: q_rope -> qcat[512..575], k_rope in-place ===========
__global__ void rope_kernel(const float* __restrict__ fc, const float* __restrict__ fs) {
    const int idx = blockIdx.x * 256 + threadIdx.x;
    const int NQ = BATCH * SEQ_L * NH * (DR / 2); // 131072
    if (idx < NQ) {
        const int j = idx & 31, h = (idx >> 5) & 15, l = (idx >> 9) & 31, b = idx >> 14;
        const float* src = &g_q[(size_t)(b * SEQ_L + l) * (NH * QKD) + h * QKD + DNR + 2 * j];
        const float xr = src[0], xi = src[1];
        const float c = fc[l * 32 + j], s = fs[l * 32 + j];
        float* dst = &g_qcat[(size_t)(b * ROWSPB + l * NH + h) * CATD + KVR + 2 * j];
        dst[0] = xr * c - xi * s;
        dst[1] = xr * s + xi * c;
    } else if (idx < NQ + BATCH * SEQ_L * (DR / 2)) {
        const int k = idx - NQ;
        const int j = k & 31, l = (k >> 5) & 31, b = k >> 10;
        float* p = &g_kv[(size_t)(b * SEQ_L + l) * CATD + KVR + 2 * j];
        const float xr = p[0], xi = p[1];
        const float c = fc[l * 32 + j], s = fs[l * 32 + j];
        p[0] = xr * c - xi * s;
        p[1] = xr * s + xi * c;
    }
}

// ================= q_abs: per-head NN gemm into qcat[0..511] =================
// A = g_q (rows (b,l), cols h*192..h*192+127), B = w_kv_up[h*256+d][k] (NN)
__global__ void qabs_kernel(const float* __restrict__ wkv) {
    const int h = blockIdx.z;
    const int m0 = blockIdx.y * 64, n0 = blockIdx.x * 64;
    const float* A = g_q + h * QKD;                 // lda = 3072
    const float* Bm = wkv + (size_t)h * 256 * KVR;  // B[d][k], ldb = 512
    __shared__ float As[8][64];
    __shared__ float Bs[8][64];
    const int tid = threadIdx.x;
    const int ty = tid >> 4, tx = tid & 15;
    const int lr = tid >> 2, lc = (tid & 3) * 2;
    const int br = tid >> 5, bc = (tid & 31) * 2;
    float acc[4][4] = {};
    for (int k0 = 0; k0 < DNR; k0 += 8) {
        float2 av = *(const float2*)&A[(size_t)(m0 + lr) * (NH * QKD) + k0 + lc];
        As[lc][lr] = av.x; As[lc + 1][lr] = av.y;
        float2 bv = *(const float2*)&Bm[(size_t)(k0 + br) * KVR + n0 + bc];
        Bs[br][bc] = bv.x; Bs[br][bc + 1] = bv.y;
        __syncthreads();
#pragma unroll
        for (int kk = 0; kk < 8; kk++) {
            float a[4], b[4];
#pragma unroll
            for (int i = 0; i < 4; i++) a[i] = As[kk][ty * 4 + i];
#pragma unroll
            for (int j = 0; j < 4; j++) b[j] = Bs[kk][tx * 4 + j];
#pragma unroll
            for (int i = 0; i < 4; i++)
#pragma unroll
                for (int j = 0; j < 4; j++) acc[i][j] += a[i] * b[j];
        }
        __syncthreads();
    }
#pragma unroll
    for (int i = 0; i < 4; i++) {
        const int m = m0 + ty * 4 + i;
        const int row = (m >> 5) * ROWSPB + (m & 31) * NH + h;
#pragma unroll
        for (int j = 0; j < 4; j++)
            g_qcat[(size_t)row * CATD + n0 + tx * 4 + j] = acc[i][j];
    }
}

// ================= scores: S = Qcat * KVcat^T, fused *SCALE + mask ===========
// 128x128 tile, BK=8, 256 threads, 8x8 micro. KV row-select: t>=4064 -> fresh.
__global__ void scores_kernel(const float* __restrict__ kvc,
                              const float* __restrict__ krc,
                              const float* __restrict__ mask) {
    const int b = blockIdx.z;
    const int m0 = blockIdx.y * 128;
    const int t0 = blockIdx.x * 128;
    __shared__ float Qs[8][128];
    __shared__ float Ks[8][128];
    const float* Aq = g_qcat + (size_t)b * ROWSPB * CATD;
    const int tid = threadIdx.x;
    const int ty = tid >> 4, tx = tid & 15;
    const int lr = tid >> 1, lc = (tid & 1) * 4;
    float acc[8][8] = {};
    for (int c0 = 0; c0 < CATD; c0 += 8) {
        float4 av = *(const float4*)&Aq[(size_t)(m0 + lr) * CATD + c0 + lc];
        Qs[lc][lr] = av.x; Qs[lc + 1][lr] = av.y; Qs[lc + 2][lr] = av.z; Qs[lc + 3][lr] = av.w;
        const int t = t0 + lr;
        const int c = c0 + lc;
        float4 kv;
        if (t >= START_P)
            kv = *(const float4*)&g_kv[(size_t)((b << 5) + (t - START_P)) * CATD + c];
        else if (c < KVR)
            kv = *(const float4*)&kvc[((size_t)b * MAXT + t) * KVR + c];
        else
            kv = *(const float4*)&krc[((size_t)b * MAXT + t) * DR + (c - KVR)];
        Ks[lc][lr] = kv.x; Ks[lc + 1][lr] = kv.y; Ks[lc + 2][lr] = kv.z; Ks[lc + 3][lr] = kv.w;
        __syncthreads();
#pragma unroll
        for (int kk = 0; kk < 8; kk++) {
            float a[8], bb[8];
#pragma unroll
            for (int i = 0; i < 8; i++) a[i] = Qs[kk][ty * 8 + i];
#pragma unroll
            for (int j = 0; j < 8; j++) bb[j] = Ks[kk][tx * 8 + j];
#pragma unroll
            for (int i = 0; i < 8; i++)
#pragma unroll
                for (int j = 0; j < 8; j++) acc[i][j] += a[i] * bb[j];
        }
        __syncthreads();
    }
#pragma unroll
    for (int i = 0; i < 8; i++) {
        const int m = m0 + ty * 8 + i;
        const int l = m >> 4;
        float* out = &g_S[((size_t)b * ROWSPB + m) * MAXT + t0 + tx * 8];
        const float* mrow = &mask[(size_t)l * MAXT + t0 + tx * 8];
#pragma unroll
        for (int j = 0; j < 8; j++)
            out[j] = acc[i][j] * SCALE_F + mrow[j];
    }
}

// ================= row softmax over 4096 (in place) ==========================
__global__ void softmax_kernel() {
    const int row = blockIdx.x;                 // 0..4095
    float* s = g_S + (size_t)row * MAXT;
    __shared__ float red[256];
    const int tid = threadIdx.x;
    float v[16];
    float mx = -INFINITY;
#pragma unroll
    for (int i = 0; i < 16; i++) { v[i] = s[tid + i * 256]; mx = fmaxf(mx, v[i]); }
    red[tid] = mx; __syncthreads();
    for (int o = 128; o > 0; o >>= 1) {
        if (tid < o) red[tid] = fmaxf(red[tid], red[tid + o]);
        __syncthreads();
    }
    mx = red[0]; __syncthreads();
    float sum = 0.f;
#pragma unroll
    for (int i = 0; i < 16; i++) { v[i] = __expf(v[i] - mx); sum += v[i]; }
    red[tid] = sum; __syncthreads();
    for (int o = 128; o > 0; o >>= 1) {
        if (tid < o) red[tid] += red[tid + o];
        __syncthreads();
    }
    const float inv = 1.f / red[0];
#pragma unroll
    for (int i = 0; i < 16; i++) s[tid + i * 256] = v[i] * inv;
}

// ================= O = P * KV  (NN over t, KV row-select) ====================
__global__ void ogemm_kernel(const float* __restrict__ kvc) {
    const int b = blockIdx.z;
    const int m0 = blockIdx.y * 128;
    const int n0 = blockIdx.x * 128;            // n = latent k (512)
    __shared__ float Ps[8][128];
    __shared__ float Ks[8][128];
    const float* P = g_S + (size_t)b * ROWSPB * MAXT;
    const int tid = threadIdx.x;
    const int ty = tid >> 4, tx = tid & 15;
    const int lr = tid >> 1, lc = (tid & 1) * 4; // P loader: 128 m x 8 t
    const int br = tid >> 5, bc = (tid & 31) * 4; // KV loader: 8 t x 128 k
    float acc[8][8] = {};
    for (int tk = 0; tk < MAXT; tk += 8) {
        float4 pv = *(const float4*)&P[(size_t)(m0 + lr) * MAXT + tk + lc];
        Ps[lc][lr] = pv.x; Ps[lc + 1][lr] = pv.y; Ps[lc + 2][lr] = pv.z; Ps[lc + 3][lr] = pv.w;
        const int t = tk + br;
        float4 kv;
        if (t >= START_P)
            kv = *(const float4*)&g_kv[(size_t)((b << 5) + (t - START_P)) * CATD + n0 + bc];
        else
            kv = *(const float4*)&kvc[((size_t)b * MAXT + t) * KVR + n0 + bc];
        *(float4*)&Ks[br][bc] = kv;
        __syncthreads();
#pragma unroll
        for (int kk = 0; kk < 8; kk++) {
            float a[8], bb[8];
#pragma unroll
            for (int i = 0; i < 8; i++) a[i] = Ps[kk][ty * 8 + i];
#pragma unroll
            for (int j = 0; j < 8; j++) bb[j] = Ks[kk][tx * 8 + j];
#pragma unroll
            for (int i = 0; i < 8; i++)
#pragma unroll
                for (int j = 0; j < 8; j++) acc[i][j] += a[i] * bb[j];
        }
        __syncthreads();
    }
#pragma unroll
    for (int i = 0; i < 8; i++) {
        const int m = m0 + ty * 8 + i;
        float* out = &g_O[((size_t)b * ROWSPB + m) * KVR + n0 + tx * 8];
#pragma unroll
        for (int j = 0; j < 8; j++) out[j] = acc[i][j];
    }
}

// ================= value up-proj: per head NT, A row remap ===================
__global__ void oup_kernel(const float* __restrict__ wkv) {
    const int h = blockIdx.z;
    const int m0 = blockIdx.y * 64, n0 = blockIdx.x * 64;  // m over (b,l), n over dv (128)
    const float* Bw = wkv + (size_t)(h * 256 + DNR) * KVR; // NT rows, ldb 512
    __shared__ float As[8][64];
    __shared__ float Bs[8][64];
    const int tid = threadIdx.x;
    const int ty = tid >> 4, tx = tid & 15;
    const int lr = tid >> 2, lc = (tid & 3) * 2;
    float acc[4][4] = {};
    const int mrow = m0 + lr;
    const int arow = (mrow >> 5) * ROWSPB + (mrow & 31) * NH + h;
    for (int k0 = 0; k0 < KVR; k0 += 8) {
        float2 av = *(const float2*)&g_O[(size_t)arow * KVR + k0 + lc];
        float2 bv = *(const float2*)&Bw[(size_t)(n0 + lr) * KVR + k0 + lc];
        As[lc][lr] = av.x; As[lc + 1][lr] = av.y;
        Bs[lc][lr] = bv.x; Bs[lc + 1][lr] = bv.y;
        __syncthreads();
#pragma unroll
        for (int kk = 0; kk < 8; kk++) {
            float a[4], b[4];
#pragma unroll
            for (int i = 0; i < 4; i++) a[i] = As[kk][ty * 4 + i];
#pragma unroll
            for (int j = 0; j < 4; j++) b[j] = Bs[kk][tx * 4 + j];
#pragma unroll
            for (int i = 0; i < 4; i++)
#pragma unroll
                for (int j = 0; j < 4; j++) acc[i][j] += a[i] * b[j];
        }
        __syncthreads();
    }
#pragma unroll
    for (int i = 0; i < 4; i++)
#pragma unroll
        for (int j = 0; j < 4; j++)
            g_o2[(size_t)(m0 + ty * 4 + i) * (NH * DV) + h * DV + n0 + tx * 4 + j] = acc[i][j];
}

// ============================== launcher =====================================
extern "C" void kernel_launch(void* const* d_in, const int* in_sizes, int n_in,
                              void* d_out, int out_size) {
    const float* x      = (const float*)d_in[0];
    const float* fc     = (const float*)d_in[2];
    const float* fs     = (const float*)d_in[3];
    const float* mask   = (const float*)d_in[4];
    const float* kvc    = (const float*)d_in[5];
    const float* krc    = (const float*)d_in[6];
    const float* w_kvd  = (const float*)d_in[7];
    const float* w_qd   = (const float*)d_in[8];
    const float* rms_w  = (const float*)d_in[9];
    const float* w_qu   = (const float*)d_in[10];
    const float* w_kvu  = (const float*)d_in[11];
    const float* w_out  = (const float*)d_in[12];
    float* out = (float*)d_out;

    float *p_qd, *p_qn, *p_q, *p_kv, *p_o2;
    cudaGetSymbolAddress((void**)&p_qd, g_qd);
    cudaGetSymbolAddress((void**)&p_qn, g_qn);
    cudaGetSymbolAddress((void**)&p_q,  g_q);
    cudaGetSymbolAddress((void**)&p_kv, g_kv);
    cudaGetSymbolAddress((void**)&p_o2, g_o2);

    // 1. qd = x @ Wqd^T   (256 x 768 x 2048)
    gemm_nt64<<<dim3(QR / 64, MBL / 64), 256>>>(x, DIM, w_qd, DIM, p_qd, QR, DIM);
    // 2. rmsnorm
    rms_kernel<<<MBL, 256>>>(rms_w);
    // 3. q = qn @ Wqu^T   (256 x 3072 x 768)
    gemm_nt64<<<dim3(NH * QKD / 64, MBL / 64), 256>>>(p_qn, QR, w_qu, QR, p_q, NH * QKD, QR);
    // 4. kv = x @ Wkvd^T  (256 x 576 x 2048)
    gemm_nt64<<<dim3(CATD / 64, MBL / 64), 256>>>(x, DIM, w_kvd, DIM, p_kv, CATD, DIM);
    // 5. rope (q -> qcat tail; kv tail in place)
    rope_kernel<<<(BATCH * SEQ_L * NH * 32 + BATCH * SEQ_L * 32 + 255) / 256, 256>>>(fc, fs);
    // 6. q_abs -> qcat head  (per-head 256 x 512 x 128 NN)
    qabs_kernel<<<dim3(KVR / 64, MBL / 64, NH), 256>>>(w_kvu);
    // 7. scores (+scale +mask)
    scores_kernel<<<dim3(MAXT / 128, ROWSPB / 128, BATCH), 256>>>(kvc, krc, mask);
    // 8. softmax
    softmax_kernel<<<BATCH * ROWSPB, 256>>>();
    // 9. O = P @ KV
    ogemm_kernel<<<dim3(KVR / 128, ROWSPB / 128, BATCH), 256>>>(kvc);
    // 10. value up-proj (per-head 256 x 128 x 512 NT)
    oup_kernel<<<dim3(DV / 64, MBL / 64, NH), 256>>>(w_kvu);
    // 11. out = o2 @ Wout^T  (256 x 2048 x 2048)
    gemm_nt64<<<dim3(DIM / 64, MBL / 64), 256>>>(p_o2, NH * DV, w_out, DIM, out, DIM, NH * DV);
}

// round 3
// speedup vs baseline: 1.1597x; 1.1597x over previous
#include <cuda_runtime.h>
#include <cuda_bf16.h>
#include <math.h>
#include <stdint.h>

// ---------------- problem constants -----------------------------------------
#define BATCH   8
#define SEQ_L   32
#define DIM     2048
#define KVR     512
#define QR      768
#define NH      16
#define DNR     128
#define DR      64
#define DV      128
#define MAXT    4096
#define START_P 4064
#define QKD     192
#define CATD    576
#define MBL     256
#define ROWSPB  512
#define SCALE_F 0.07216878364870323f
#define KVD_PAD 640     // 576 padded to 5*128 for gemm N-tiles

// ---------------- fp32 scratch ----------------------------------------------
__device__ __align__(16) float g_qd  [MBL * QR];
__device__ __align__(16) float g_qn  [MBL * QR];
__device__ __align__(16) float g_q   [MBL * NH * QKD];
__device__ __align__(16) float g_kv  [MBL * CATD];
__device__ __align__(16) float g_qcat[BATCH * ROWSPB * CATD];
__device__ __align__(16) float g_S   [(size_t)BATCH * ROWSPB * MAXT];
__device__ __align__(16) float g_O   [BATCH * ROWSPB * KVR];
__device__ __align__(16) float g_o2  [MBL * (NH * DV)];
// ---------------- bf16 hi/lo operands ----------------------------------------
__device__ __align__(16) __nv_bfloat16 g_qc_h[BATCH * ROWSPB * CATD];
__device__ __align__(16) __nv_bfloat16 g_qc_l[BATCH * ROWSPB * CATD];
__device__ __align__(16) __nv_bfloat16 g_kc_h[(size_t)BATCH * MAXT * CATD];
__device__ __align__(16) __nv_bfloat16 g_kc_l[(size_t)BATCH * MAXT * CATD];
__device__ __align__(16) __nv_bfloat16 g_kt_h[(size_t)BATCH * KVR * MAXT];
__device__ __align__(16) __nv_bfloat16 g_kt_l[(size_t)BATCH * KVR * MAXT];
__device__ __align__(16) __nv_bfloat16 g_p_h [(size_t)BATCH * ROWSPB * MAXT];
__device__ __align__(16) __nv_bfloat16 g_p_l [(size_t)BATCH * ROWSPB * MAXT];
__device__ __align__(16) __nv_bfloat16 g_xh  [MBL * DIM];
__device__ __align__(16) __nv_bfloat16 g_xl  [MBL * DIM];
__device__ __align__(16) __nv_bfloat16 g_qnh [MBL * QR];
__device__ __align__(16) __nv_bfloat16 g_qnl [MBL * QR];
__device__ __align__(16) __nv_bfloat16 g_o2h [MBL * NH * DV];
__device__ __align__(16) __nv_bfloat16 g_o2l [MBL * NH * DV];
__device__ __align__(16) __nv_bfloat16 g_wqdh[QR * DIM];
__device__ __align__(16) __nv_bfloat16 g_wqdl[QR * DIM];
__device__ __align__(16) __nv_bfloat16 g_wquh[NH * QKD * QR];
__device__ __align__(16) __nv_bfloat16 g_wqul[NH * QKD * QR];
__device__ __align__(16) __nv_bfloat16 g_wkvdh[KVD_PAD * DIM];
__device__ __align__(16) __nv_bfloat16 g_wkvdl[KVD_PAD * DIM];
__device__ __align__(16) __nv_bfloat16 g_wouth[DIM * NH * DV];
__device__ __align__(16) __nv_bfloat16 g_woutl[DIM * NH * DV];

// ================= helpers ===================================================
__device__ __forceinline__ uint32_t smem_u32(const void* p) {
    uint32_t a;
    asm("{ .reg .u64 t; cvta.to.shared.u64 t, %1; cvt.u32.u64 %0, t; }" : "=r"(a) : "l"(p));
    return a;
}
__device__ __forceinline__ uint32_t sw128(uint32_t o) { return o ^ ((o >> 3) & 0x70); }

// copy one 128-byte row (64 bf16) of K-chunk into SW128 smem tile
__device__ __forceinline__ void ld_row(const __nv_bfloat16* g, char* tile, int row) {
    const uint4* src = (const uint4*)g;
    uint32_t base = (uint32_t)row * 128u;
#pragma unroll
    for (int i = 0; i < 8; i++) {
        uint4 v = src[i];
        *(uint4*)(tile + sw128(base + i * 16u)) = v;
    }
}

__device__ __forceinline__ void ldm_x4(uint32_t* r, uint32_t addr) {
    asm volatile("ldmatrix.sync.aligned.m8n8.x4.shared.b16 {%0,%1,%2,%3}, [%4];"
                 : "=r"(r[0]), "=r"(r[1]), "=r"(r[2]), "=r"(r[3]) : "r"(addr));
}
__device__ __forceinline__ void mma_bf16(float* c, const uint32_t* a, const uint32_t* b) {
    asm volatile("mma.sync.aligned.m16n8k16.row.col.f32.bf16.bf16.f32 "
                 "{%0,%1,%2,%3}, {%4,%5,%6,%7}, {%8,%9}, {%0,%1,%2,%3};"
                 : "+f"(c[0]), "+f"(c[1]), "+f"(c[2]), "+f"(c[3])
                 : "r"(a[0]), "r"(a[1]), "r"(a[2]), "r"(a[3]), "r"(b[0]), "r"(b[1]));
}

__device__ __forceinline__ void split_write(float x, __nv_bfloat16* h, __nv_bfloat16* l, size_t i) {
    __nv_bfloat16 hv = __float2bfloat16(x);
    h[i] = hv;
    l[i] = __float2bfloat16(x - __bfloat162float(hv));
}

// ====== split-bf16 HMMA GEMM: C(M,N) = A(M,K) * B(N,K)^T (fp32-equivalent) ===
// CTA tile 128x128, 8 warps (2x4) of 64x32, K-chunk 64, SW128 smem + ldmatrix.
// 3 accumulation segments: Ah*Bh + Al*Bh + Ah*Bl. Optional fused scale+mask.
__global__ void __launch_bounds__(256)
gemm_mma(const __nv_bfloat16* __restrict__ Ah, const __nv_bfloat16* __restrict__ Al, size_t sAz,
         const __nv_bfloat16* __restrict__ Bh, const __nv_bfloat16* __restrict__ Bl, size_t sBz,
         float* __restrict__ C, int ldc, size_t sCz,
         int K, int N, const float* __restrict__ mask, float scale)
{
    __shared__ __nv_bfloat16 As[128 * 64];
    __shared__ __nv_bfloat16 Bs[128 * 64];
    const int z = blockIdx.z;
    const int m0 = blockIdx.y * 128, n0 = blockIdx.x * 128;
    Ah += (size_t)z * sAz;  Al += (size_t)z * sAz;
    Bh += (size_t)z * sBz;  Bl += (size_t)z * sBz;
    C  += (size_t)z * sCz;

    const int tid = threadIdx.x;
    const int warp = tid >> 5, lane = tid & 31;
    const int wm = (warp >> 2) * 64, wn = (warp & 3) * 32;
    const int lrow = tid & 127;
    const bool isB = tid >= 128;
    char* myTile = (char*)(isB ? Bs : As);
    const int grow = (isB ? n0 : m0) + lrow;

    const int qrow = lane & 15, qsel = lane >> 4;
    const uint32_t As32 = smem_u32(As), Bs32 = smem_u32(Bs);

    float acc[4][4][4];
#pragma unroll
    for (int i = 0; i < 4; i++)
#pragma unroll
        for (int j = 0; j < 4; j++)
#pragma unroll
            for (int r = 0; r < 4; r++) acc[i][j][r] = 0.f;

    const __nv_bfloat16* Aseg[3] = {Ah, Al, Ah};
    const __nv_bfloat16* Bseg[3] = {Bh, Bh, Bl};

    for (int seg = 0; seg < 3; seg++) {
        const __nv_bfloat16* src = isB ? Bseg[seg] : Aseg[seg];
        for (int k0 = 0; k0 < K; k0 += 64) {
            __syncthreads();
            ld_row(src + (size_t)grow * K + k0, myTile, lrow);
            __syncthreads();
#pragma unroll
            for (int ks = 0; ks < 4; ks++) {
                uint32_t a[4][4];
#pragma unroll
                for (int mf = 0; mf < 4; mf++) {
                    int row = wm + mf * 16 + qrow;
                    ldm_x4(a[mf], As32 + sw128((uint32_t)row * 128u + ks * 32u + qsel * 16u));
                }
                uint32_t b[4][2];
#pragma unroll
                for (int nh = 0; nh < 2; nh++) {
                    int row = wn + nh * 16 + qrow;
                    uint32_t t[4];
                    ldm_x4(t, Bs32 + sw128((uint32_t)row * 128u + ks * 32u + qsel * 16u));
                    b[nh * 2 + 0][0] = t[0]; b[nh * 2 + 0][1] = t[2];
                    b[nh * 2 + 1][0] = t[1]; b[nh * 2 + 1][1] = t[3];
                }
#pragma unroll
                for (int mf = 0; mf < 4; mf++)
#pragma unroll
                    for (int nf = 0; nf < 4; nf++)
                        mma_bf16(acc[mf][nf], a[mf], b[nf]);
            }
        }
    }

    // epilogue
    const int r0 = lane >> 2, c0 = (lane & 3) * 2;
#pragma unroll
    for (int mf = 0; mf < 4; mf++) {
        const int mA = m0 + wm + mf * 16 + r0;   // rows mA and mA+8
        const float* mrow = mask ? (mask + (size_t)((mA) >> 4) * MAXT) : (const float*)0;
#pragma unroll
        for (int nf = 0; nf < 4; nf++) {
            const int n = n0 + wn + nf * 8 + c0;
            if (n < N) {
                float v0 = acc[mf][nf][0], v1 = acc[mf][nf][1];
                float v2 = acc[mf][nf][2], v3 = acc[mf][nf][3];
                if (mask) {
                    v0 = v0 * scale + mrow[n];
                    v1 = v1 * scale + mrow[n + 1];
                    v2 = v2 * scale + mrow[n];
                    v3 = v3 * scale + mrow[n + 1];
                }
                *(float2*)&C[(size_t)mA * ldc + n]       = make_float2(v0, v1);
                *(float2*)&C[(size_t)(mA + 8) * ldc + n] = make_float2(v2, v3);
            }
        }
    }
}

// ================= conversions ===============================================
__global__ void conv_split(const float* __restrict__ src, __nv_bfloat16* h, __nv_bfloat16* l, int n) {
    const int i = blockIdx.x * 256 + threadIdx.x;
    if (i < n) split_write(src[i], h, l, i);
}
__global__ void conv_split_pad(const float* __restrict__ src, __nv_bfloat16* h, __nv_bfloat16* l,
                               int nsrc, int ntot) {
    const int i = blockIdx.x * 256 + threadIdx.x;
    if (i < ntot) {
        float v = (i < nsrc) ? src[i] : 0.f;
        split_write(v, h, l, i);
    }
}
__global__ void conv_qcat() {
    const size_t i = (size_t)blockIdx.x * 256 + threadIdx.x;
    split_write(g_qcat[i], g_qc_h, g_qc_l, i);
}
__global__ void build_kvcat(const float* __restrict__ kvc, const float* __restrict__ krc) {
    const size_t idx = (size_t)blockIdx.x * 256 + threadIdx.x;
    const int c = (int)(idx % CATD);
    const size_t bt = idx / CATD;
    const int t = (int)(bt % MAXT);
    const int b = (int)(bt / MAXT);
    float v;
    if (t >= START_P)
        v = g_kv[(size_t)((b << 5) + (t - START_P)) * CATD + c];
    else if (c < KVR)
        v = kvc[((size_t)b * MAXT + t) * KVR + c];
    else
        v = krc[((size_t)b * MAXT + t) * DR + (c - KVR)];
    split_write(v, g_kc_h, g_kc_l, idx);
}
__global__ void build_kvt(const float* __restrict__ kvc) {
    __shared__ float tile[32][33];
    const int b = blockIdx.z;
    const int t0 = blockIdx.x * 32, n0 = blockIdx.y * 32;
    const int tx = threadIdx.x, ty = threadIdx.y;
#pragma unroll
    for (int i = 0; i < 4; i++) {
        const int t = t0 + ty + i * 8;
        float v;
        if (t >= START_P)
            v = g_kv[(size_t)((b << 5) + (t - START_P)) * CATD + n0 + tx];
        else
            v = kvc[((size_t)b * MAXT + t) * KVR + n0 + tx];
        tile[ty + i * 8][tx] = v;
    }
    __syncthreads();
#pragma unroll
    for (int i = 0; i < 4; i++) {
        const int n = n0 + ty + i * 8;
        const float x = tile[tx][ty + i * 8];
        const size_t o = ((size_t)(b * KVR + n)) * MAXT + t0 + tx;
        split_write(x, g_kt_h, g_kt_l, o);
    }
}

// ================= RMSNorm ===================================================
__global__ void rms_kernel(const float* __restrict__ w) {
    const int row = blockIdx.x;
    const float* xr = g_qd + row * QR;
    __shared__ float red[256];
    const int tid = threadIdx.x;
    float v[3], s = 0.f;
#pragma unroll
    for (int i = 0; i < 3; i++) { v[i] = xr[tid + i * 256]; s += v[i] * v[i]; }
    red[tid] = s; __syncthreads();
    for (int o = 128; o > 0; o >>= 1) {
        if (tid < o) red[tid] += red[tid + o];
        __syncthreads();
    }
    const float r = rsqrtf(red[0] / (float)QR + 1.1920929e-07f);
    __syncthreads();
#pragma unroll
    for (int i = 0; i < 3; i++) {
        const float y = v[i] * r * w[tid + i * 256];
        g_qn[row * QR + tid + i * 256] = y;
        split_write(y, g_qnh, g_qnl, (size_t)row * QR + tid + i * 256);
    }
}

// ================= rope ======================================================
__global__ void rope_kernel(const float* __restrict__ fc, const float* __restrict__ fs) {
    const int idx = blockIdx.x * 256 + threadIdx.x;
    const int NQ = BATCH * SEQ_L * NH * (DR / 2);
    if (idx < NQ) {
        const int j = idx & 31, h = (idx >> 5) & 15, l = (idx >> 9) & 31, b = idx >> 14;
        const float* src = &g_q[(size_t)(b * SEQ_L + l) * (NH * QKD) + h * QKD + DNR + 2 * j];
        const float xr = src[0], xi = src[1];
        const float c = fc[l * 32 + j], s = fs[l * 32 + j];
        float* dst = &g_qcat[(size_t)(b * ROWSPB + l * NH + h) * CATD + KVR + 2 * j];
        dst[0] = xr * c - xi * s;
        dst[1] = xr * s + xi * c;
    } else if (idx < NQ + BATCH * SEQ_L * (DR / 2)) {
        const int k = idx - NQ;
        const int j = k & 31, l = (k >> 5) & 31, b = k >> 10;
        float* p = &g_kv[(size_t)(b * SEQ_L + l) * CATD + KVR + 2 * j];
        const float xr = p[0], xi = p[1];
        const float c = fc[l * 32 + j], s = fs[l * 32 + j];
        p[0] = xr * c - xi * s;
        p[1] = xr * s + xi * c;
    }
}

// ================= q_abs (fp32, per-head NN, small) ==========================
__global__ void qabs_kernel(const float* __restrict__ wkv) {
    const int h = blockIdx.z;
    const int m0 = blockIdx.y * 64, n0 = blockIdx.x * 64;
    const float* A = g_q + h * QKD;
    const float* Bm = wkv + (size_t)h * 256 * KVR;
    __shared__ float As[8][64];
    __shared__ float Bs[8][64];
    const int tid = threadIdx.x;
    const int ty = tid >> 4, tx = tid & 15;
    const int lr = tid >> 2, lc = (tid & 3) * 2;
    const int br = tid >> 5, bc = (tid & 31) * 2;
    float acc[4][4] = {};
    for (int k0 = 0; k0 < DNR; k0 += 8) {
        float2 av = *(const float2*)&A[(size_t)(m0 + lr) * (NH * QKD) + k0 + lc];
        As[lc][lr] = av.x; As[lc + 1][lr] = av.y;
        float2 bv = *(const float2*)&Bm[(size_t)(k0 + br) * KVR + n0 + bc];
        Bs[br][bc] = bv.x; Bs[br][bc + 1] = bv.y;
        __syncthreads();
#pragma unroll
        for (int kk = 0; kk < 8; kk++) {
            float a[4], b[4];
#pragma unroll
            for (int i = 0; i < 4; i++) a[i] = As[kk][ty * 4 + i];
#pragma unroll
            for (int j = 0; j < 4; j++) b[j] = Bs[kk][tx * 4 + j];
#pragma unroll
            for (int i = 0; i < 4; i++)
#pragma unroll
                for (int j = 0; j < 4; j++) acc[i][j] += a[i] * b[j];
        }
        __syncthreads();
    }
#pragma unroll
    for (int i = 0; i < 4; i++) {
        const int m = m0 + ty * 4 + i;
        const int row = (m >> 5) * ROWSPB + (m & 31) * NH + h;
#pragma unroll
        for (int j = 0; j < 4; j++)
            g_qcat[(size_t)row * CATD + n0 + tx * 4 + j] = acc[i][j];
    }
}

// ================= softmax -> bf16 hi/lo P ===================================
__global__ void softmax_split() {
    const int row = blockIdx.x;
    float* s = g_S + (size_t)row * MAXT;
    __shared__ float red[256];
    const int tid = threadIdx.x;
    float v[16];
    float mx = -INFINITY;
#pragma unroll
    for (int i = 0; i < 16; i++) { v[i] = s[tid + i * 256]; mx = fmaxf(mx, v[i]); }
    red[tid] = mx; __syncthreads();
    for (int o = 128; o > 0; o >>= 1) {
        if (tid < o) red[tid] = fmaxf(red[tid], red[tid + o]);
        __syncthreads();
    }
    mx = red[0]; __syncthreads();
    float sum = 0.f;
#pragma unroll
    for (int i = 0; i < 16; i++) { v[i] = __expf(v[i] - mx); sum += v[i]; }
    red[tid] = sum; __syncthreads();
    for (int o = 128; o > 0; o >>= 1) {
        if (tid < o) red[tid] += red[tid + o];
        __syncthreads();
    }
    const float inv = 1.f / red[0];
#pragma unroll
    for (int i = 0; i < 16; i++) {
        const size_t idx = (size_t)row * MAXT + tid + i * 256;
        split_write(v[i] * inv, g_p_h, g_p_l, idx);
    }
}

// ================= value up-proj (fp32, per-head NT, small) ==================
__global__ void oup_kernel(const float* __restrict__ wkv) {
    const int h = blockIdx.z;
    const int m0 = blockIdx.y * 64, n0 = blockIdx.x * 64;
    const float* Bw = wkv + (size_t)(h * 256 + DNR) * KVR;
    __shared__ float As[8][64];
    __shared__ float Bs[8][64];
    const int tid = threadIdx.x;
    const int ty = tid >> 4, tx = tid & 15;
    const int lr = tid >> 2, lc = (tid & 3) * 2;
    float acc[4][4] = {};
    const int mrow = m0 + lr;
    const int arow = (mrow >> 5) * ROWSPB + (mrow & 31) * NH + h;
    for (int k0 = 0; k0 < KVR; k0 += 8) {
        float2 av = *(const float2*)&g_O[(size_t)arow * KVR + k0 + lc];
        float2 bv = *(const float2*)&Bw[(size_t)(n0 + lr) * KVR + k0 + lc];
        As[lc][lr] = av.x; As[lc + 1][lr] = av.y;
        Bs[lc][lr] = bv.x; Bs[lc + 1][lr] = bv.y;
        __syncthreads();
#pragma unroll
        for (int kk = 0; kk < 8; kk++) {
            float a[4], b[4];
#pragma unroll
            for (int i = 0; i < 4; i++) a[i] = As[kk][ty * 4 + i];
#pragma unroll
            for (int j = 0; j < 4; j++) b[j] = Bs[kk][tx * 4 + j];
#pragma unroll
            for (int i = 0; i < 4; i++)
#pragma unroll
                for (int j = 0; j < 4; j++) acc[i][j] += a[i] * b[j];
        }
        __syncthreads();
    }
#pragma unroll
    for (int i = 0; i < 4; i++)
#pragma unroll
        for (int j = 0; j < 4; j++)
            g_o2[(size_t)(m0 + ty * 4 + i) * (NH * DV) + h * DV + n0 + tx * 4 + j] = acc[i][j];
}

// ============================== launcher =====================================
extern "C" void kernel_launch(void* const* d_in, const int* in_sizes, int n_in,
                              void* d_out, int out_size) {
    const float* x      = (const float*)d_in[0];
    const float* fc     = (const float*)d_in[2];
    const float* fs     = (const float*)d_in[3];
    const float* mask   = (const float*)d_in[4];
    const float* kvc    = (const float*)d_in[5];
    const float* krc    = (const float*)d_in[6];
    const float* w_kvd  = (const float*)d_in[7];
    const float* w_qd   = (const float*)d_in[8];
    const float* rms_w  = (const float*)d_in[9];
    const float* w_qu   = (const float*)d_in[10];
    const float* w_kvu  = (const float*)d_in[11];
    const float* w_out  = (const float*)d_in[12];
    float* out = (float*)d_out;

    float *p_qd, *p_q, *p_kv;
    cudaGetSymbolAddress((void**)&p_qd, g_qd);
    cudaGetSymbolAddress((void**)&p_q,  g_q);
    cudaGetSymbolAddress((void**)&p_kv, g_kv);

    __nv_bfloat16 *xh, *xl, *qnh, *qnl, *o2h, *o2l;
    __nv_bfloat16 *wqdh, *wqdl, *wquh, *wqul, *wkvdh, *wkvdl, *wouth, *woutl;
    __nv_bfloat16 *qch, *qcl, *kch, *kcl, *kth, *ktl, *ph, *pl;
    cudaGetSymbolAddress((void**)&xh, g_xh);     cudaGetSymbolAddress((void**)&xl, g_xl);
    cudaGetSymbolAddress((void**)&qnh, g_qnh);   cudaGetSymbolAddress((void**)&qnl, g_qnl);
    cudaGetSymbolAddress((void**)&o2h, g_o2h);   cudaGetSymbolAddress((void**)&o2l, g_o2l);
    cudaGetSymbolAddress((void**)&wqdh, g_wqdh); cudaGetSymbolAddress((void**)&wqdl, g_wqdl);
    cudaGetSymbolAddress((void**)&wquh, g_wquh); cudaGetSymbolAddress((void**)&wqul, g_wqul);
    cudaGetSymbolAddress((void**)&wkvdh, g_wkvdh); cudaGetSymbolAddress((void**)&wkvdl, g_wkvdl);
    cudaGetSymbolAddress((void**)&wouth, g_wouth); cudaGetSymbolAddress((void**)&woutl, g_woutl);
    cudaGetSymbolAddress((void**)&qch, g_qc_h);  cudaGetSymbolAddress((void**)&qcl, g_qc_l);
    cudaGetSymbolAddress((void**)&kch, g_kc_h);  cudaGetSymbolAddress((void**)&kcl, g_kc_l);
    cudaGetSymbolAddress((void**)&kth, g_kt_h);  cudaGetSymbolAddress((void**)&ktl, g_kt_l);
    cudaGetSymbolAddress((void**)&ph, g_p_h);    cudaGetSymbolAddress((void**)&pl, g_p_l);

    float *p_S, *p_O, *p_o2;
    cudaGetSymbolAddress((void**)&p_S, g_S);
    cudaGetSymbolAddress((void**)&p_O, g_O);
    cudaGetSymbolAddress((void**)&p_o2, g_o2);

    // ---- operand conversions (weights + x) ----
    conv_split<<<(MBL * DIM) / 256, 256>>>(x, xh, xl, MBL * DIM);
    conv_split<<<(QR * DIM) / 256, 256>>>(w_qd, wqdh, wqdl, QR * DIM);
    conv_split<<<(NH * QKD * QR) / 256, 256>>>(w_qu, wquh, wqul, NH * QKD * QR);
    conv_split_pad<<<(KVD_PAD * DIM) / 256, 256>>>(w_kvd, wkvdh, wkvdl, CATD * DIM, KVD_PAD * DIM);
    conv_split<<<(DIM * NH * DV) / 256, 256>>>(w_out, wouth, woutl, DIM * NH * DV);

    // ---- q path ----
    gemm_mma<<<dim3(QR / 128, MBL / 128, 1), 256>>>(xh, xl, 0, wqdh, wqdl, 0,
        p_qd, QR, 0, DIM, QR, nullptr, 1.f);
    rms_kernel<<<MBL, 256>>>(rms_w);
    gemm_mma<<<dim3(NH * QKD / 128, MBL / 128, 1), 256>>>(qnh, qnl, 0, wquh, wqul, 0,
        p_q, NH * QKD, 0, QR, NH * QKD, nullptr, 1.f);

    // ---- kv path ----
    gemm_mma<<<dim3(KVD_PAD / 128, MBL / 128, 1), 256>>>(xh, xl, 0, wkvdh, wkvdl, 0,
        p_kv, CATD, 0, DIM, CATD, nullptr, 1.f);

    rope_kernel<<<(BATCH * SEQ_L * NH * 32 + BATCH * SEQ_L * 32 + 255) / 256, 256>>>(fc, fs);
    qabs_kernel<<<dim3(KVR / 64, MBL / 64, NH), 256>>>(w_kvu);

    conv_qcat<<<(BATCH * ROWSPB * CATD) / 256, 256>>>();
    build_kvcat<<<(int)(((size_t)BATCH * MAXT * CATD) / 256), 256>>>(kvc, krc);
    build_kvt<<<dim3(MAXT / 32, KVR / 32, BATCH), dim3(32, 8)>>>(kvc);

    // ---- attention ----
    gemm_mma<<<dim3(MAXT / 128, ROWSPB / 128, BATCH), 256>>>(
        qch, qcl, (size_t)ROWSPB * CATD, kch, kcl, (size_t)MAXT * CATD,
        p_S, MAXT, (size_t)ROWSPB * MAXT, CATD, MAXT, mask, SCALE_F);
    softmax_split<<<BATCH * ROWSPB, 256>>>();
    gemm_mma<<<dim3(KVR / 128, ROWSPB / 128, BATCH), 256>>>(
        ph, pl, (size_t)ROWSPB * MAXT, kth, ktl, (size_t)KVR * MAXT,
        p_O, KVR, (size_t)ROWSPB * KVR, MAXT, KVR, nullptr, 1.f);

    // ---- output path ----
    oup_kernel<<<dim3(DV / 64, MBL / 64, NH), 256>>>(w_kvu);
    conv_split<<<(MBL * NH * DV) / 256, 256>>>(p_o2, o2h, o2l, MBL * NH * DV);
    gemm_mma<<<dim3(DIM / 128, MBL / 128, 1), 256>>>(o2h, o2l, 0, wouth, woutl, 0,
        out, DIM, 0, NH * DV, DIM, nullptr, 1.f);
}

// round 4
// speedup vs baseline: 2.1387x; 1.8442x over previous
#include <cuda_runtime.h>
#include <cuda_bf16.h>
#include <math.h>
#include <stdint.h>

// ---------------- problem constants -----------------------------------------
#define BATCH   8
#define SEQ_L   32
#define DIM     2048
#define KVR     512
#define QR      768
#define NH      16
#define DNR     128
#define DR      64
#define DV      128
#define MAXT    4096
#define START_P 4064
#define QKD     192
#define CATD    576
#define MBL     256
#define ROWSPB  512
#define SCALE_F 0.07216878364870323f
#define KVD_PAD 640

// ---------------- fp32 scratch ----------------------------------------------
__device__ __align__(16) float g_qd  [MBL * QR];
__device__ __align__(16) float g_q   [MBL * NH * QKD];
__device__ __align__(16) float g_kv  [MBL * CATD];
__device__ __align__(16) float g_qcat[BATCH * ROWSPB * CATD];
__device__ __align__(16) float g_S   [(size_t)BATCH * ROWSPB * MAXT];
__device__ __align__(16) float g_O   [BATCH * ROWSPB * KVR];
__device__ __align__(16) float g_o2  [MBL * (NH * DV)];
// ---------------- bf16 hi/lo operands ----------------------------------------
__device__ __align__(16) __nv_bfloat16 g_qc_h[BATCH * ROWSPB * CATD];
__device__ __align__(16) __nv_bfloat16 g_qc_l[BATCH * ROWSPB * CATD];
__device__ __align__(16) __nv_bfloat16 g_kc_h[(size_t)BATCH * MAXT * CATD];
__device__ __align__(16) __nv_bfloat16 g_kc_l[(size_t)BATCH * MAXT * CATD];
__device__ __align__(16) __nv_bfloat16 g_kt_h[(size_t)BATCH * KVR * MAXT];
__device__ __align__(16) __nv_bfloat16 g_kt_l[(size_t)BATCH * KVR * MAXT];
__device__ __align__(16) __nv_bfloat16 g_p_h [(size_t)BATCH * ROWSPB * MAXT];
__device__ __align__(16) __nv_bfloat16 g_p_l [(size_t)BATCH * ROWSPB * MAXT];
__device__ __align__(16) __nv_bfloat16 g_xh  [MBL * DIM];
__device__ __align__(16) __nv_bfloat16 g_xl  [MBL * DIM];
__device__ __align__(16) __nv_bfloat16 g_qnh [MBL * QR];
__device__ __align__(16) __nv_bfloat16 g_qnl [MBL * QR];
__device__ __align__(16) __nv_bfloat16 g_o2h [MBL * NH * DV];
__device__ __align__(16) __nv_bfloat16 g_o2l [MBL * NH * DV];
__device__ __align__(16) __nv_bfloat16 g_wqdh[QR * DIM];
__device__ __align__(16) __nv_bfloat16 g_wqdl[QR * DIM];
__device__ __align__(16) __nv_bfloat16 g_wquh[NH * QKD * QR];
__device__ __align__(16) __nv_bfloat16 g_wqul[NH * QKD * QR];
__device__ __align__(16) __nv_bfloat16 g_wkvdh[KVD_PAD * DIM];
__device__ __align__(16) __nv_bfloat16 g_wkvdl[KVD_PAD * DIM];
__device__ __align__(16) __nv_bfloat16 g_wouth[DIM * NH * DV];
__device__ __align__(16) __nv_bfloat16 g_woutl[DIM * NH * DV];

// ================= helpers ===================================================
__device__ __forceinline__ uint32_t smem_u32(const void* p) {
    uint32_t a;
    asm("{ .reg .u64 t; cvta.to.shared.u64 t, %1; cvt.u32.u64 %0, t; }" : "=r"(a) : "l"(p));
    return a;
}
__device__ __forceinline__ uint32_t sw128(uint32_t o) { return o ^ ((o >> 3) & 0x70); }

__device__ __forceinline__ void cpa16(uint32_t saddr, const void* g) {
    asm volatile("cp.async.cg.shared.global [%0], [%1], 16;" :: "r"(saddr), "l"(g));
}
__device__ __forceinline__ void cpa_commit() {
    asm volatile("cp.async.commit_group;" ::: "memory");
}
__device__ __forceinline__ void cpa_wait1() {
    asm volatile("cp.async.wait_group 1;" ::: "memory");
}
__device__ __forceinline__ void cpa_wait0() {
    asm volatile("cp.async.wait_group 0;" ::: "memory");
}
__device__ __forceinline__ void ldm_x4(uint32_t* r, uint32_t addr) {
    asm volatile("ldmatrix.sync.aligned.m8n8.x4.shared.b16 {%0,%1,%2,%3}, [%4];"
                 : "=r"(r[0]), "=r"(r[1]), "=r"(r[2]), "=r"(r[3]) : "r"(addr));
}
__device__ __forceinline__ void mma_bf16(float* c, const uint32_t* a, const uint32_t* b) {
    asm volatile("mma.sync.aligned.m16n8k16.row.col.f32.bf16.bf16.f32 "
                 "{%0,%1,%2,%3}, {%4,%5,%6,%7}, {%8,%9}, {%0,%1,%2,%3};"
                 : "+f"(c[0]), "+f"(c[1]), "+f"(c[2]), "+f"(c[3])
                 : "r"(a[0]), "r"(a[1]), "r"(a[2]), "r"(a[3]), "r"(b[0]), "r"(b[1]));
}
__device__ __forceinline__ void split_write(float x, __nv_bfloat16* h, __nv_bfloat16* l, size_t i) {
    __nv_bfloat16 hv = __float2bfloat16(x);
    h[i] = hv;
    l[i] = __float2bfloat16(x - __bfloat162float(hv));
}
// split 4 contiguous floats, write 8B each to h/l
__device__ __forceinline__ void split4(float4 v, __nv_bfloat16* h, __nv_bfloat16* l, size_t i4) {
    __nv_bfloat16 h0 = __float2bfloat16(v.x), h1 = __float2bfloat16(v.y);
    __nv_bfloat16 h2 = __float2bfloat16(v.z), h3 = __float2bfloat16(v.w);
    __nv_bfloat16 l0 = __float2bfloat16(v.x - __bfloat162float(h0));
    __nv_bfloat16 l1 = __float2bfloat16(v.y - __bfloat162float(h1));
    __nv_bfloat16 l2 = __float2bfloat16(v.z - __bfloat162float(h2));
    __nv_bfloat16 l3 = __float2bfloat16(v.w - __bfloat162float(h3));
    __nv_bfloat162 hh0 = {h0, h1}, hh1 = {h2, h3};
    __nv_bfloat162 ll0 = {l0, l1}, ll1 = {l2, l3};
    uint2 hw = make_uint2(*(uint32_t*)&hh0, *(uint32_t*)&hh1);
    uint2 lw = make_uint2(*(uint32_t*)&ll0, *(uint32_t*)&ll1);
    *(uint2*)&h[i4 * 4] = hw;
    *(uint2*)&l[i4 * 4] = lw;
}

// ====== split-bf16 HMMA GEMM: C(M,N) = A(M,K)*B(N,K)^T, double-buffered ======
// CTA 128x128, 8 warps (2x4) 64x32 each, K-chunk 64.
// Per chunk stages Ah|Al|Bh|Bl (4x16KB), 2 stages (128KB dynamic smem).
// Products: Ah*Bh + Ah*Bl + Al*Bh accumulated in fp32.
#define STAGE_B 65536
__global__ void __launch_bounds__(256)
gemm_mma(const __nv_bfloat16* __restrict__ Ah, const __nv_bfloat16* __restrict__ Al, size_t sAz,
         const __nv_bfloat16* __restrict__ Bh, const __nv_bfloat16* __restrict__ Bl, size_t sBz,
         float* __restrict__ C, int ldc, size_t sCz,
         int K, int N, const float* __restrict__ mask, float scale)
{
    extern __shared__ char smem[];
    const int z = blockIdx.z;
    const int m0 = blockIdx.y * 128, n0 = blockIdx.x * 128;
    Ah += (size_t)z * sAz;  Al += (size_t)z * sAz;
    Bh += (size_t)z * sBz;  Bl += (size_t)z * sBz;
    C  += (size_t)z * sCz;

    const int tid = threadIdx.x;
    const int warp = tid >> 5, lane = tid & 31;
    const int wm = (warp >> 2) * 64, wn = (warp & 3) * 32;

    // loader: 2 threads per row, 4x16B each per tile
    const int lrow = tid >> 1, lhalf = tid & 1;
    const __nv_bfloat16* srcs[4];
    srcs[0] = Ah + (size_t)(m0 + lrow) * K;
    srcs[1] = Al + (size_t)(m0 + lrow) * K;
    srcs[2] = Bh + (size_t)(n0 + lrow) * K;
    srcs[3] = Bl + (size_t)(n0 + lrow) * K;
    const uint32_t smem32 = smem_u32(smem);
    uint32_t soff[4][4];
#pragma unroll
    for (int t = 0; t < 4; t++)
#pragma unroll
        for (int i = 0; i < 4; i++)
            soff[t][i] = (uint32_t)t * 16384u + sw128((uint32_t)lrow * 128u + lhalf * 64u + i * 16u);

    const int qrow = lane & 15, qsel = lane >> 4;

    float acc[4][4][4];
#pragma unroll
    for (int i = 0; i < 4; i++)
#pragma unroll
        for (int j = 0; j < 4; j++)
#pragma unroll
            for (int r = 0; r < 4; r++) acc[i][j][r] = 0.f;

    const int nch = K >> 6;

    // prefetch chunk 0
    {
        const int ke = lhalf * 32;
#pragma unroll
        for (int t = 0; t < 4; t++)
#pragma unroll
            for (int i = 0; i < 4; i++)
                cpa16(smem32 + soff[t][i], srcs[t] + ke + i * 8);
        cpa_commit();
    }

    for (int c = 0; c < nch; c++) {
        if (c + 1 < nch) {
            const int ke = (c + 1) * 64 + lhalf * 32;
            const uint32_t sb = smem32 + ((c + 1) & 1) * STAGE_B;
#pragma unroll
            for (int t = 0; t < 4; t++)
#pragma unroll
                for (int i = 0; i < 4; i++)
                    cpa16(sb + soff[t][i], srcs[t] + ke + i * 8);
            cpa_commit();
            cpa_wait1();
        } else {
            cpa_wait0();
        }
        __syncthreads();

        const uint32_t st = smem32 + (c & 1) * STAGE_B;
        const uint32_t Ah32 = st, Al32 = st + 16384, Bh32 = st + 32768, Bl32 = st + 49152;
#pragma unroll
        for (int ks = 0; ks < 4; ks++) {
            const uint32_t kofs = ks * 32u + qsel * 16u;
            uint32_t ah[4][4];
#pragma unroll
            for (int mf = 0; mf < 4; mf++) {
                int row = wm + mf * 16 + qrow;
                ldm_x4(ah[mf], Ah32 + sw128((uint32_t)row * 128u + kofs));
            }
            uint32_t bh[4][2], bl[4][2];
#pragma unroll
            for (int nh = 0; nh < 2; nh++) {
                int row = wn + nh * 16 + qrow;
                uint32_t t[4];
                ldm_x4(t, Bh32 + sw128((uint32_t)row * 128u + kofs));
                bh[nh * 2 + 0][0] = t[0]; bh[nh * 2 + 0][1] = t[2];
                bh[nh * 2 + 1][0] = t[1]; bh[nh * 2 + 1][1] = t[3];
                ldm_x4(t, Bl32 + sw128((uint32_t)row * 128u + kofs));
                bl[nh * 2 + 0][0] = t[0]; bl[nh * 2 + 0][1] = t[2];
                bl[nh * 2 + 1][0] = t[1]; bl[nh * 2 + 1][1] = t[3];
            }
#pragma unroll
            for (int mf = 0; mf < 4; mf++)
#pragma unroll
                for (int nf = 0; nf < 4; nf++)
                    mma_bf16(acc[mf][nf], ah[mf], bh[nf]);
#pragma unroll
            for (int mf = 0; mf < 4; mf++)
#pragma unroll
                for (int nf = 0; nf < 4; nf++)
                    mma_bf16(acc[mf][nf], ah[mf], bl[nf]);
            uint32_t al[4][4];
#pragma unroll
            for (int mf = 0; mf < 4; mf++) {
                int row = wm + mf * 16 + qrow;
                ldm_x4(al[mf], Al32 + sw128((uint32_t)row * 128u + kofs));
            }
#pragma unroll
            for (int mf = 0; mf < 4; mf++)
#pragma unroll
                for (int nf = 0; nf < 4; nf++)
                    mma_bf16(acc[mf][nf], al[mf], bh[nf]);
        }
        __syncthreads();
    }

    // epilogue
    const int r0 = lane >> 2, c0 = (lane & 3) * 2;
#pragma unroll
    for (int mf = 0; mf < 4; mf++) {
        const int mA = m0 + wm + mf * 16 + r0;
        const float* mrow = mask ? (mask + (size_t)(mA >> 4) * MAXT) : (const float*)0;
#pragma unroll
        for (int nf = 0; nf < 4; nf++) {
            const int n = n0 + wn + nf * 8 + c0;
            if (n < N) {
                float v0 = acc[mf][nf][0], v1 = acc[mf][nf][1];
                float v2 = acc[mf][nf][2], v3 = acc[mf][nf][3];
                if (mask) {
                    v0 = v0 * scale + mrow[n];
                    v1 = v1 * scale + mrow[n + 1];
                    v2 = v2 * scale + mrow[n];
                    v3 = v3 * scale + mrow[n + 1];
                }
                *(float2*)&C[(size_t)mA * ldc + n]       = make_float2(v0, v1);
                *(float2*)&C[(size_t)(mA + 8) * ldc + n] = make_float2(v2, v3);
            }
        }
    }
}

// ================= conversions (vectorized) ==================================
__global__ void conv_split4(const float4* __restrict__ src, __nv_bfloat16* h, __nv_bfloat16* l, int n4) {
    const int i = blockIdx.x * 256 + threadIdx.x;
    if (i < n4) split4(src[i], h, l, i);
}
__global__ void conv_split_pad4(const float4* __restrict__ src, __nv_bfloat16* h, __nv_bfloat16* l,
                                int n4src, int n4tot) {
    const int i = blockIdx.x * 256 + threadIdx.x;
    if (i < n4tot) {
        float4 v = (i < n4src) ? src[i] : make_float4(0.f, 0.f, 0.f, 0.f);
        split4(v, h, l, i);
    }
}
__global__ void conv_qcat4() {
    const size_t i = (size_t)blockIdx.x * 256 + threadIdx.x;
    split4(*(const float4*)&g_qcat[i * 4], g_qc_h, g_qc_l, i);
}
__global__ void build_kvcat4(const float* __restrict__ kvc, const float* __restrict__ krc) {
    const size_t i4 = (size_t)blockIdx.x * 256 + threadIdx.x;
    const size_t idx = i4 * 4;
    const int c = (int)(idx % CATD);
    const size_t bt = idx / CATD;
    const int t = (int)(bt % MAXT);
    const int b = (int)(bt / MAXT);
    float4 v;
    if (t >= START_P)
        v = *(const float4*)&g_kv[(size_t)((b << 5) + (t - START_P)) * CATD + c];
    else if (c < KVR)
        v = *(const float4*)&kvc[((size_t)b * MAXT + t) * KVR + c];
    else
        v = *(const float4*)&krc[((size_t)b * MAXT + t) * DR + (c - KVR)];
    split4(v, g_kc_h, g_kc_l, i4);
}
__global__ void build_kvt(const float* __restrict__ kvc) {
    __shared__ float tile[32][33];
    const int b = blockIdx.z;
    const int t0 = blockIdx.x * 32, n0 = blockIdx.y * 32;
    const int tx = threadIdx.x, ty = threadIdx.y;
#pragma unroll
    for (int i = 0; i < 4; i++) {
        const int t = t0 + ty + i * 8;
        float v;
        if (t >= START_P)
            v = g_kv[(size_t)((b << 5) + (t - START_P)) * CATD + n0 + tx];
        else
            v = kvc[((size_t)b * MAXT + t) * KVR + n0 + tx];
        tile[ty + i * 8][tx] = v;
    }
    __syncthreads();
#pragma unroll
    for (int i = 0; i < 4; i++) {
        const int n = n0 + ty + i * 8;
        const float x = tile[tx][ty + i * 8];
        const size_t o = ((size_t)(b * KVR + n)) * MAXT + t0 + tx;
        split_write(x, g_kt_h, g_kt_l, o);
    }
}

// ================= RMSNorm (writes split qn) =================================
__global__ void rms_kernel(const float* __restrict__ w) {
    const int row = blockIdx.x;
    const float* xr = g_qd + row * QR;
    __shared__ float red[256];
    const int tid = threadIdx.x;
    float v[3], s = 0.f;
#pragma unroll
    for (int i = 0; i < 3; i++) { v[i] = xr[tid + i * 256]; s += v[i] * v[i]; }
    red[tid] = s; __syncthreads();
    for (int o = 128; o > 0; o >>= 1) {
        if (tid < o) red[tid] += red[tid + o];
        __syncthreads();
    }
    const float r = rsqrtf(red[0] / (float)QR + 1.1920929e-07f);
    __syncthreads();
#pragma unroll
    for (int i = 0; i < 3; i++) {
        const float y = v[i] * r * w[tid + i * 256];
        split_write(y, g_qnh, g_qnl, (size_t)row * QR + tid + i * 256);
    }
}

// ================= rope ======================================================
__global__ void rope_kernel(const float* __restrict__ fc, const float* __restrict__ fs) {
    const int idx = blockIdx.x * 256 + threadIdx.x;
    const int NQ = BATCH * SEQ_L * NH * (DR / 2);
    if (idx < NQ) {
        const int j = idx & 31, h = (idx >> 5) & 15, l = (idx >> 9) & 31, b = idx >> 14;
        const float* src = &g_q[(size_t)(b * SEQ_L + l) * (NH * QKD) + h * QKD + DNR + 2 * j];
        const float xr = src[0], xi = src[1];
        const float c = fc[l * 32 + j], s = fs[l * 32 + j];
        float* dst = &g_qcat[(size_t)(b * ROWSPB + l * NH + h) * CATD + KVR + 2 * j];
        dst[0] = xr * c - xi * s;
        dst[1] = xr * s + xi * c;
    } else if (idx < NQ + BATCH * SEQ_L * (DR / 2)) {
        const int k = idx - NQ;
        const int j = k & 31, l = (k >> 5) & 31, b = k >> 10;
        float* p = &g_kv[(size_t)(b * SEQ_L + l) * CATD + KVR + 2 * j];
        const float xr = p[0], xi = p[1];
        const float c = fc[l * 32 + j], s = fs[l * 32 + j];
        p[0] = xr * c - xi * s;
        p[1] = xr * s + xi * c;
    }
}

// ================= q_abs (fp32, per-head NN) =================================
__global__ void qabs_kernel(const float* __restrict__ wkv) {
    const int h = blockIdx.z;
    const int m0 = blockIdx.y * 64, n0 = blockIdx.x * 64;
    const float* A = g_q + h * QKD;
    const float* Bm = wkv + (size_t)h * 256 * KVR;
    __shared__ float As[8][64];
    __shared__ float Bs[8][64];
    const int tid = threadIdx.x;
    const int ty = tid >> 4, tx = tid & 15;
    const int lr = tid >> 2, lc = (tid & 3) * 2;
    const int br = tid >> 5, bc = (tid & 31) * 2;
    float acc[4][4] = {};
    for (int k0 = 0; k0 < DNR; k0 += 8) {
        float2 av = *(const float2*)&A[(size_t)(m0 + lr) * (NH * QKD) + k0 + lc];
        As[lc][lr] = av.x; As[lc + 1][lr] = av.y;
        float2 bv = *(const float2*)&Bm[(size_t)(k0 + br) * KVR + n0 + bc];
        Bs[br][bc] = bv.x; Bs[br][bc + 1] = bv.y;
        __syncthreads();
#pragma unroll
        for (int kk = 0; kk < 8; kk++) {
            float a[4], b[4];
#pragma unroll
            for (int i = 0; i < 4; i++) a[i] = As[kk][ty * 4 + i];
#pragma unroll
            for (int j = 0; j < 4; j++) b[j] = Bs[kk][tx * 4 + j];
#pragma unroll
            for (int i = 0; i < 4; i++)
#pragma unroll
                for (int j = 0; j < 4; j++) acc[i][j] += a[i] * b[j];
        }
        __syncthreads();
    }
#pragma unroll
    for (int i = 0; i < 4; i++) {
        const int m = m0 + ty * 4 + i;
        const int row = (m >> 5) * ROWSPB + (m & 31) * NH + h;
#pragma unroll
        for (int j = 0; j < 4; j++)
            g_qcat[(size_t)row * CATD + n0 + tx * 4 + j] = acc[i][j];
    }
}

// ================= softmax -> bf16 hi/lo P (vectorized) ======================
__global__ void softmax_split() {
    const int row = blockIdx.x;
    float* s = g_S + (size_t)row * MAXT;
    __shared__ float red[256];
    const int tid = threadIdx.x;
    float4 v[4];
    float mx = -INFINITY;
#pragma unroll
    for (int g = 0; g < 4; g++) {
        v[g] = *(float4*)&s[tid * 4 + g * 1024];
        mx = fmaxf(mx, fmaxf(fmaxf(v[g].x, v[g].y), fmaxf(v[g].z, v[g].w)));
    }
    red[tid] = mx; __syncthreads();
    for (int o = 128; o > 0; o >>= 1) {
        if (tid < o) red[tid] = fmaxf(red[tid], red[tid + o]);
        __syncthreads();
    }
    mx = red[0]; __syncthreads();
    float sum = 0.f;
#pragma unroll
    for (int g = 0; g < 4; g++) {
        v[g].x = __expf(v[g].x - mx); v[g].y = __expf(v[g].y - mx);
        v[g].z = __expf(v[g].z - mx); v[g].w = __expf(v[g].w - mx);
        sum += v[g].x + v[g].y + v[g].z + v[g].w;
    }
    red[tid] = sum; __syncthreads();
    for (int o = 128; o > 0; o >>= 1) {
        if (tid < o) red[tid] += red[tid + o];
        __syncthreads();
    }
    const float inv = 1.f / red[0];
#pragma unroll
    for (int g = 0; g < 4; g++) {
        float4 p = make_float4(v[g].x * inv, v[g].y * inv, v[g].z * inv, v[g].w * inv);
        split4(p, g_p_h, g_p_l, ((size_t)row * MAXT + tid * 4 + g * 1024) >> 2);
    }
}

// ================= value up-proj (fp32, per-head NT) =========================
__global__ void oup_kernel(const float* __restrict__ wkv) {
    const int h = blockIdx.z;
    const int m0 = blockIdx.y * 64, n0 = blockIdx.x * 64;
    const float* Bw = wkv + (size_t)(h * 256 + DNR) * KVR;
    __shared__ float As[8][64];
    __shared__ float Bs[8][64];
    const int tid = threadIdx.x;
    const int ty = tid >> 4, tx = tid & 15;
    const int lr = tid >> 2, lc = (tid & 3) * 2;
    float acc[4][4] = {};
    const int mrow = m0 + lr;
    const int arow = (mrow >> 5) * ROWSPB + (mrow & 31) * NH + h;
    for (int k0 = 0; k0 < KVR; k0 += 8) {
        float2 av = *(const float2*)&g_O[(size_t)arow * KVR + k0 + lc];
        float2 bv = *(const float2*)&Bw[(size_t)(n0 + lr) * KVR + k0 + lc];
        As[lc][lr] = av.x; As[lc + 1][lr] = av.y;
        Bs[lc][lr] = bv.x; Bs[lc + 1][lr] = bv.y;
        __syncthreads();
#pragma unroll
        for (int kk = 0; kk < 8; kk++) {
            float a[4], b[4];
#pragma unroll
            for (int i = 0; i < 4; i++) a[i] = As[kk][ty * 4 + i];
#pragma unroll
            for (int j = 0; j < 4; j++) b[j] = Bs[kk][tx * 4 + j];
#pragma unroll
            for (int i = 0; i < 4; i++)
#pragma unroll
                for (int j = 0; j < 4; j++) acc[i][j] += a[i] * b[j];
        }
        __syncthreads();
    }
#pragma unroll
    for (int i = 0; i < 4; i++)
#pragma unroll
        for (int j = 0; j < 4; j++)
            g_o2[(size_t)(m0 + ty * 4 + i) * (NH * DV) + h * DV + n0 + tx * 4 + j] = acc[i][j];
}

// ============================== launcher =====================================
extern "C" void kernel_launch(void* const* d_in, const int* in_sizes, int n_in,
                              void* d_out, int out_size) {
    const float* x      = (const float*)d_in[0];
    const float* fc     = (const float*)d_in[2];
    const float* fs     = (const float*)d_in[3];
    const float* mask   = (const float*)d_in[4];
    const float* kvc    = (const float*)d_in[5];
    const float* krc    = (const float*)d_in[6];
    const float* w_kvd  = (const float*)d_in[7];
    const float* w_qd   = (const float*)d_in[8];
    const float* rms_w  = (const float*)d_in[9];
    const float* w_qu   = (const float*)d_in[10];
    const float* w_kvu  = (const float*)d_in[11];
    const float* w_out  = (const float*)d_in[12];
    float* out = (float*)d_out;

    float *p_qd, *p_q, *p_kv, *p_S, *p_O, *p_o2;
    cudaGetSymbolAddress((void**)&p_qd, g_qd);
    cudaGetSymbolAddress((void**)&p_q,  g_q);
    cudaGetSymbolAddress((void**)&p_kv, g_kv);
    cudaGetSymbolAddress((void**)&p_S, g_S);
    cudaGetSymbolAddress((void**)&p_O, g_O);
    cudaGetSymbolAddress((void**)&p_o2, g_o2);

    __nv_bfloat16 *xh, *xl, *qnh, *qnl, *o2h, *o2l;
    __nv_bfloat16 *wqdh, *wqdl, *wquh, *wqul, *wkvdh, *wkvdl, *wouth, *woutl;
    __nv_bfloat16 *qch, *qcl, *kch, *kcl, *kth, *ktl, *ph, *pl;
    cudaGetSymbolAddress((void**)&xh, g_xh);     cudaGetSymbolAddress((void**)&xl, g_xl);
    cudaGetSymbolAddress((void**)&qnh, g_qnh);   cudaGetSymbolAddress((void**)&qnl, g_qnl);
    cudaGetSymbolAddress((void**)&o2h, g_o2h);   cudaGetSymbolAddress((void**)&o2l, g_o2l);
    cudaGetSymbolAddress((void**)&wqdh, g_wqdh); cudaGetSymbolAddress((void**)&wqdl, g_wqdl);
    cudaGetSymbolAddress((void**)&wquh, g_wquh); cudaGetSymbolAddress((void**)&wqul, g_wqul);
    cudaGetSymbolAddress((void**)&wkvdh, g_wkvdh); cudaGetSymbolAddress((void**)&wkvdl, g_wkvdl);
    cudaGetSymbolAddress((void**)&wouth, g_wouth); cudaGetSymbolAddress((void**)&woutl, g_woutl);
    cudaGetSymbolAddress((void**)&qch, g_qc_h);  cudaGetSymbolAddress((void**)&qcl, g_qc_l);
    cudaGetSymbolAddress((void**)&kch, g_kc_h);  cudaGetSymbolAddress((void**)&kcl, g_kc_l);
    cudaGetSymbolAddress((void**)&kth, g_kt_h);  cudaGetSymbolAddress((void**)&ktl, g_kt_l);
    cudaGetSymbolAddress((void**)&ph, g_p_h);    cudaGetSymbolAddress((void**)&pl, g_p_l);

    static bool attr_set = false;
    if (!attr_set) {
        cudaFuncSetAttribute(gemm_mma, cudaFuncAttributeMaxDynamicSharedMemorySize, 2 * STAGE_B);
        attr_set = true;
    }
    const int DSM = 2 * STAGE_B;

    // ---- operand conversions ----
    conv_split4<<<(MBL * DIM / 4 + 255) / 256, 256>>>((const float4*)x, xh, xl, MBL * DIM / 4);
    conv_split4<<<(QR * DIM / 4 + 255) / 256, 256>>>((const float4*)w_qd, wqdh, wqdl, QR * DIM / 4);
    conv_split4<<<(NH * QKD * QR / 4 + 255) / 256, 256>>>((const float4*)w_qu, wquh, wqul, NH * QKD * QR / 4);
    conv_split_pad4<<<(KVD_PAD * DIM / 4 + 255) / 256, 256>>>((const float4*)w_kvd, wkvdh, wkvdl,
                                                              CATD * DIM / 4, KVD_PAD * DIM / 4);
    conv_split4<<<(DIM * NH * DV / 4 + 255) / 256, 256>>>((const float4*)w_out, wouth, woutl, DIM * NH * DV / 4);

    // ---- q path ----
    gemm_mma<<<dim3(QR / 128, MBL / 128, 1), 256, DSM>>>(xh, xl, 0, wqdh, wqdl, 0,
        p_qd, QR, 0, DIM, QR, nullptr, 1.f);
    rms_kernel<<<MBL, 256>>>(rms_w);
    gemm_mma<<<dim3(NH * QKD / 128, MBL / 128, 1), 256, DSM>>>(qnh, qnl, 0, wquh, wqul, 0,
        p_q, NH * QKD, 0, QR, NH * QKD, nullptr, 1.f);

    // ---- kv path ----
    gemm_mma<<<dim3(KVD_PAD / 128, MBL / 128, 1), 256, DSM>>>(xh, xl, 0, wkvdh, wkvdl, 0,
        p_kv, CATD, 0, DIM, CATD, nullptr, 1.f);

    rope_kernel<<<(BATCH * SEQ_L * NH * 32 + BATCH * SEQ_L * 32 + 255) / 256, 256>>>(fc, fs);
    qabs_kernel<<<dim3(KVR / 64, MBL / 64, NH), 256>>>(w_kvu);

    conv_qcat4<<<(BATCH * ROWSPB * CATD / 4) / 256, 256>>>();
    build_kvcat4<<<(int)(((size_t)BATCH * MAXT * CATD / 4) / 256), 256>>>(kvc, krc);
    build_kvt<<<dim3(MAXT / 32, KVR / 32, BATCH), dim3(32, 8)>>>(kvc);

    // ---- attention ----
    gemm_mma<<<dim3(MAXT / 128, ROWSPB / 128, BATCH), 256, DSM>>>(
        qch, qcl, (size_t)ROWSPB * CATD, kch, kcl, (size_t)MAXT * CATD,
        p_S, MAXT, (size_t)ROWSPB * MAXT, CATD, MAXT, mask, SCALE_F);
    softmax_split<<<BATCH * ROWSPB, 256>>>();
    gemm_mma<<<dim3(KVR / 128, ROWSPB / 128, BATCH), 256, DSM>>>(
        ph, pl, (size_t)ROWSPB * MAXT, kth, ktl, (size_t)KVR * MAXT,
        p_O, KVR, (size_t)ROWSPB * KVR, MAXT, KVR, nullptr, 1.f);

    // ---- output path ----
    oup_kernel<<<dim3(DV / 64, MBL / 64, NH), 256>>>(w_kvu);
    conv_split4<<<(MBL * NH * DV / 4 + 255) / 256, 256>>>((const float4*)p_o2, o2h, o2l, MBL * NH * DV / 4);
    gemm_mma<<<dim3(DIM / 128, MBL / 128, 1), 256, DSM>>>(o2h, o2l, 0, wouth, woutl, 0,
        out, DIM, 0, NH * DV, DIM, nullptr, 1.f);
}

// round 5
// speedup vs baseline: 2.8922x; 1.3523x over previous
#include <cuda_runtime.h>
#include <cuda_bf16.h>
#include <math.h>
#include <stdint.h>

// ---------------- problem constants -----------------------------------------
#define BATCH   8
#define SEQ_L   32
#define DIM     2048
#define KVR     512
#define QR      768
#define NH      16
#define DNR     128
#define DR      64
#define DV      128
#define MAXT    4096
#define START_P 4064
#define QKD     192
#define CATD    576
#define MBL     256
#define ROWSPB  512
#define SCALE_F 0.07216878364870323f
#define KVD_PAD 640

// ---------------- fp32 scratch ----------------------------------------------
__device__ __align__(16) float g_qd  [MBL * QR];
__device__ __align__(16) float g_q   [MBL * NH * QKD];
__device__ __align__(16) float g_kv  [MBL * CATD];
__device__ __align__(16) float g_qcat[BATCH * ROWSPB * CATD];
__device__ __align__(16) float g_S   [(size_t)BATCH * ROWSPB * MAXT];
__device__ __align__(16) float g_O   [BATCH * ROWSPB * KVR];
__device__ __align__(16) float g_o2  [MBL * (NH * DV)];
// ---------------- bf16 hi/lo operands ----------------------------------------
__device__ __align__(16) __nv_bfloat16 g_qc_h[BATCH * ROWSPB * CATD];
__device__ __align__(16) __nv_bfloat16 g_qc_l[BATCH * ROWSPB * CATD];
__device__ __align__(16) __nv_bfloat16 g_kc_h[(size_t)BATCH * MAXT * CATD];
__device__ __align__(16) __nv_bfloat16 g_kc_l[(size_t)BATCH * MAXT * CATD];
__device__ __align__(16) __nv_bfloat16 g_kt_h[(size_t)BATCH * KVR * MAXT];
__device__ __align__(16) __nv_bfloat16 g_kt_l[(size_t)BATCH * KVR * MAXT];
__device__ __align__(16) __nv_bfloat16 g_p_h [(size_t)BATCH * ROWSPB * MAXT];
__device__ __align__(16) __nv_bfloat16 g_p_l [(size_t)BATCH * ROWSPB * MAXT];
__device__ __align__(16) __nv_bfloat16 g_xh  [MBL * DIM];
__device__ __align__(16) __nv_bfloat16 g_xl  [MBL * DIM];
__device__ __align__(16) __nv_bfloat16 g_qnh [MBL * QR];
__device__ __align__(16) __nv_bfloat16 g_qnl [MBL * QR];
__device__ __align__(16) __nv_bfloat16 g_o2h [MBL * NH * DV];
__device__ __align__(16) __nv_bfloat16 g_o2l [MBL * NH * DV];
__device__ __align__(16) __nv_bfloat16 g_wqdh[QR * DIM];
__device__ __align__(16) __nv_bfloat16 g_wqdl[QR * DIM];
__device__ __align__(16) __nv_bfloat16 g_wquh[NH * QKD * QR];
__device__ __align__(16) __nv_bfloat16 g_wqul[NH * QKD * QR];
__device__ __align__(16) __nv_bfloat16 g_wkvdh[KVD_PAD * DIM];
__device__ __align__(16) __nv_bfloat16 g_wkvdl[KVD_PAD * DIM];
__device__ __align__(16) __nv_bfloat16 g_wouth[DIM * NH * DV];
__device__ __align__(16) __nv_bfloat16 g_woutl[DIM * NH * DV];

// ================= helpers ===================================================
__device__ __forceinline__ uint32_t smem_u32(const void* p) {
    uint32_t a;
    asm("{ .reg .u64 t; cvta.to.shared.u64 t, %1; cvt.u32.u64 %0, t; }" : "=r"(a) : "l"(p));
    return a;
}
__device__ __forceinline__ uint32_t sw128(uint32_t o) { return o ^ ((o >> 3) & 0x70); }

__device__ __forceinline__ void cpa16(uint32_t saddr, const void* g) {
    asm volatile("cp.async.cg.shared.global [%0], [%1], 16;" :: "r"(saddr), "l"(g));
}
__device__ __forceinline__ void cpa_commit() {
    asm volatile("cp.async.commit_group;" ::: "memory");
}
__device__ __forceinline__ void cpa_wait1() {
    asm volatile("cp.async.wait_group 1;" ::: "memory");
}
__device__ __forceinline__ void cpa_wait0() {
    asm volatile("cp.async.wait_group 0;" ::: "memory");
}
__device__ __forceinline__ void ldm_x4(uint32_t* r, uint32_t addr) {
    asm volatile("ldmatrix.sync.aligned.m8n8.x4.shared.b16 {%0,%1,%2,%3}, [%4];"
                 : "=r"(r[0]), "=r"(r[1]), "=r"(r[2]), "=r"(r[3]) : "r"(addr));
}
__device__ __forceinline__ void mma_bf16(float* c, const uint32_t* a, const uint32_t* b) {
    asm volatile("mma.sync.aligned.m16n8k16.row.col.f32.bf16.bf16.f32 "
                 "{%0,%1,%2,%3}, {%4,%5,%6,%7}, {%8,%9}, {%0,%1,%2,%3};"
                 : "+f"(c[0]), "+f"(c[1]), "+f"(c[2]), "+f"(c[3])
                 : "r"(a[0]), "r"(a[1]), "r"(a[2]), "r"(a[3]), "r"(b[0]), "r"(b[1]));
}
__device__ __forceinline__ void split_write(float x, __nv_bfloat16* h, __nv_bfloat16* l, size_t i) {
    __nv_bfloat16 hv = __float2bfloat16(x);
    h[i] = hv;
    l[i] = __float2bfloat16(x - __bfloat162float(hv));
}
__device__ __forceinline__ void split4(float4 v, __nv_bfloat16* h, __nv_bfloat16* l, size_t i4) {
    __nv_bfloat16 h0 = __float2bfloat16(v.x), h1 = __float2bfloat16(v.y);
    __nv_bfloat16 h2 = __float2bfloat16(v.z), h3 = __float2bfloat16(v.w);
    __nv_bfloat16 l0 = __float2bfloat16(v.x - __bfloat162float(h0));
    __nv_bfloat16 l1 = __float2bfloat16(v.y - __bfloat162float(h1));
    __nv_bfloat16 l2 = __float2bfloat16(v.z - __bfloat162float(h2));
    __nv_bfloat16 l3 = __float2bfloat16(v.w - __bfloat162float(h3));
    __nv_bfloat162 hh0 = {h0, h1}, hh1 = {h2, h3};
    __nv_bfloat162 ll0 = {l0, l1}, ll1 = {l2, l3};
    uint2 hw = make_uint2(*(uint32_t*)&hh0, *(uint32_t*)&hh1);
    uint2 lw = make_uint2(*(uint32_t*)&ll0, *(uint32_t*)&ll1);
    *(uint2*)&h[i4 * 4] = hw;
    *(uint2*)&l[i4 * 4] = lw;
}

// ====== split-bf16 HMMA GEMM 128x128 (used by ogemm): double-buffered ========
#define STAGE_B 65536
__global__ void __launch_bounds__(256)
gemm_mma(const __nv_bfloat16* __restrict__ Ah, const __nv_bfloat16* __restrict__ Al, size_t sAz,
         const __nv_bfloat16* __restrict__ Bh, const __nv_bfloat16* __restrict__ Bl, size_t sBz,
         float* __restrict__ C, int ldc, size_t sCz,
         int K, int N, const float* __restrict__ mask, float scale)
{
    extern __shared__ char smem[];
    const int z = blockIdx.z;
    const int m0 = blockIdx.y * 128, n0 = blockIdx.x * 128;
    Ah += (size_t)z * sAz;  Al += (size_t)z * sAz;
    Bh += (size_t)z * sBz;  Bl += (size_t)z * sBz;
    C  += (size_t)z * sCz;

    const int tid = threadIdx.x;
    const int warp = tid >> 5, lane = tid & 31;
    const int wm = (warp >> 2) * 64, wn = (warp & 3) * 32;

    const int lrow = tid >> 1, lhalf = tid & 1;
    const __nv_bfloat16* srcs[4];
    srcs[0] = Ah + (size_t)(m0 + lrow) * K;
    srcs[1] = Al + (size_t)(m0 + lrow) * K;
    srcs[2] = Bh + (size_t)(n0 + lrow) * K;
    srcs[3] = Bl + (size_t)(n0 + lrow) * K;
    const uint32_t smem32 = smem_u32(smem);
    uint32_t soff[4][4];
#pragma unroll
    for (int t = 0; t < 4; t++)
#pragma unroll
        for (int i = 0; i < 4; i++)
            soff[t][i] = (uint32_t)t * 16384u + sw128((uint32_t)lrow * 128u + lhalf * 64u + i * 16u);

    const int qrow = lane & 15, qsel = lane >> 4;

    float acc[4][4][4];
#pragma unroll
    for (int i = 0; i < 4; i++)
#pragma unroll
        for (int j = 0; j < 4; j++)
#pragma unroll
            for (int r = 0; r < 4; r++) acc[i][j][r] = 0.f;

    const int nch = K >> 6;
    {
        const int ke = lhalf * 32;
#pragma unroll
        for (int t = 0; t < 4; t++)
#pragma unroll
            for (int i = 0; i < 4; i++)
                cpa16(smem32 + soff[t][i], srcs[t] + ke + i * 8);
        cpa_commit();
    }

    for (int c = 0; c < nch; c++) {
        if (c + 1 < nch) {
            const int ke = (c + 1) * 64 + lhalf * 32;
            const uint32_t sb = smem32 + ((c + 1) & 1) * STAGE_B;
#pragma unroll
            for (int t = 0; t < 4; t++)
#pragma unroll
                for (int i = 0; i < 4; i++)
                    cpa16(sb + soff[t][i], srcs[t] + ke + i * 8);
            cpa_commit();
            cpa_wait1();
        } else {
            cpa_wait0();
        }
        __syncthreads();

        const uint32_t st = smem32 + (c & 1) * STAGE_B;
        const uint32_t Ah32 = st, Al32 = st + 16384, Bh32 = st + 32768, Bl32 = st + 49152;
#pragma unroll
        for (int ks = 0; ks < 4; ks++) {
            const uint32_t kofs = ks * 32u + qsel * 16u;
            uint32_t ah[4][4];
#pragma unroll
            for (int mf = 0; mf < 4; mf++) {
                int row = wm + mf * 16 + qrow;
                ldm_x4(ah[mf], Ah32 + sw128((uint32_t)row * 128u + kofs));
            }
            uint32_t bh[4][2], bl[4][2];
#pragma unroll
            for (int nh = 0; nh < 2; nh++) {
                int row = wn + nh * 16 + qrow;
                uint32_t t[4];
                ldm_x4(t, Bh32 + sw128((uint32_t)row * 128u + kofs));
                bh[nh * 2 + 0][0] = t[0]; bh[nh * 2 + 0][1] = t[2];
                bh[nh * 2 + 1][0] = t[1]; bh[nh * 2 + 1][1] = t[3];
                ldm_x4(t, Bl32 + sw128((uint32_t)row * 128u + kofs));
                bl[nh * 2 + 0][0] = t[0]; bl[nh * 2 + 0][1] = t[2];
                bl[nh * 2 + 1][0] = t[1]; bl[nh * 2 + 1][1] = t[3];
            }
#pragma unroll
            for (int mf = 0; mf < 4; mf++)
#pragma unroll
                for (int nf = 0; nf < 4; nf++)
                    mma_bf16(acc[mf][nf], ah[mf], bh[nf]);
#pragma unroll
            for (int mf = 0; mf < 4; mf++)
#pragma unroll
                for (int nf = 0; nf < 4; nf++)
                    mma_bf16(acc[mf][nf], ah[mf], bl[nf]);
            uint32_t al[4][4];
#pragma unroll
            for (int mf = 0; mf < 4; mf++) {
                int row = wm + mf * 16 + qrow;
                ldm_x4(al[mf], Al32 + sw128((uint32_t)row * 128u + kofs));
            }
#pragma unroll
            for (int mf = 0; mf < 4; mf++)
#pragma unroll
                for (int nf = 0; nf < 4; nf++)
                    mma_bf16(acc[mf][nf], al[mf], bh[nf]);
        }
        __syncthreads();
    }

    const int r0 = lane >> 2, c0 = (lane & 3) * 2;
#pragma unroll
    for (int mf = 0; mf < 4; mf++) {
        const int mA = m0 + wm + mf * 16 + r0;
        const float* mrow = mask ? (mask + (size_t)(mA >> 4) * MAXT) : (const float*)0;
#pragma unroll
        for (int nf = 0; nf < 4; nf++) {
            const int n = n0 + wn + nf * 8 + c0;
            if (n < N) {
                float v0 = acc[mf][nf][0], v1 = acc[mf][nf][1];
                float v2 = acc[mf][nf][2], v3 = acc[mf][nf][3];
                if (mask) {
                    v0 = v0 * scale + mrow[n];
                    v1 = v1 * scale + mrow[n + 1];
                    v2 = v2 * scale + mrow[n];
                    v3 = v3 * scale + mrow[n + 1];
                }
                *(float2*)&C[(size_t)mA * ldc + n]       = make_float2(v0, v1);
                *(float2*)&C[(size_t)(mA + 8) * ldc + n] = make_float2(v2, v3);
            }
        }
    }
}

// ====== wide 128x256 variant (scores): 8 warps, 64x64 warp tile ==============
// stage = Ah(16K)|Al(16K)|Bh(32K)|Bl(32K) = 96KB, 2 stages.
#define WSTAGE_B 98304
__global__ void __launch_bounds__(256)
gemm_mma_wide(const __nv_bfloat16* __restrict__ Ah, const __nv_bfloat16* __restrict__ Al, size_t sAz,
              const __nv_bfloat16* __restrict__ Bh, const __nv_bfloat16* __restrict__ Bl, size_t sBz,
              float* __restrict__ C, int ldc, size_t sCz,
              int K, const float* __restrict__ mask, float scale)
{
    extern __shared__ char smem[];
    const int z = blockIdx.z;
    const int m0 = blockIdx.y * 128, n0 = blockIdx.x * 256;
    Ah += (size_t)z * sAz;  Al += (size_t)z * sAz;
    Bh += (size_t)z * sBz;  Bl += (size_t)z * sBz;
    C  += (size_t)z * sCz;

    const int tid = threadIdx.x;
    const int warp = tid >> 5, lane = tid & 31;
    const int wm = (warp >> 2) * 64, wn = (warp & 3) * 64;

    // loader: 1536 half-rows (64B each), 6 per thread
    const __nv_bfloat16* gsrc[6];
    uint32_t swb[6];
#pragma unroll
    for (int j = 0; j < 6; j++) {
        const int h = tid + j * 256;
        int t, r;
        if (h < 256)       { t = 0; r = h >> 1; }
        else if (h < 512)  { t = 1; r = (h - 256) >> 1; }
        else if (h < 1024) { t = 2; r = (h - 512) >> 1; }
        else               { t = 3; r = (h - 1024) >> 1; }
        const int half = h & 1;
        const uint32_t tbase = (t == 0) ? 0u : (t == 1) ? 16384u : (t == 2) ? 32768u : 65536u;
        swb[j] = tbase + sw128((uint32_t)r * 128u + half * 64u);
        const __nv_bfloat16* base =
            (t == 0) ? Ah + (size_t)(m0 + r) * K :
            (t == 1) ? Al + (size_t)(m0 + r) * K :
            (t == 2) ? Bh + (size_t)(n0 + r) * K :
                       Bl + (size_t)(n0 + r) * K;
        gsrc[j] = base + half * 32;
    }
    const uint32_t smem32 = smem_u32(smem);
    const int qrow = lane & 15, qsel = lane >> 4;

    float acc[4][8][4];
#pragma unroll
    for (int i = 0; i < 4; i++)
#pragma unroll
        for (int j = 0; j < 8; j++)
#pragma unroll
            for (int r = 0; r < 4; r++) acc[i][j][r] = 0.f;

    const int nch = K >> 6;
    {
#pragma unroll
        for (int j = 0; j < 6; j++)
#pragma unroll
            for (int i = 0; i < 4; i++)
                cpa16(smem32 + (swb[j] ^ (i * 16u)), gsrc[j] + i * 8);
        cpa_commit();
    }

    for (int c = 0; c < nch; c++) {
        if (c + 1 < nch) {
            const int ke = (c + 1) * 64;
            const uint32_t sb = smem32 + ((c + 1) & 1) * WSTAGE_B;
#pragma unroll
            for (int j = 0; j < 6; j++)
#pragma unroll
                for (int i = 0; i < 4; i++)
                    cpa16(sb + (swb[j] ^ (i * 16u)), gsrc[j] + ke + i * 8);
            cpa_commit();
            cpa_wait1();
        } else {
            cpa_wait0();
        }
        __syncthreads();

        const uint32_t st = smem32 + (c & 1) * WSTAGE_B;
        const uint32_t Ah32 = st, Al32 = st + 16384, Bh32 = st + 32768, Bl32 = st + 65536;
#pragma unroll
        for (int ks = 0; ks < 4; ks++) {
            const uint32_t kofs = ks * 32u + qsel * 16u;
            uint32_t ah[4][4];
#pragma unroll
            for (int mf = 0; mf < 4; mf++) {
                int row = wm + mf * 16 + qrow;
                ldm_x4(ah[mf], Ah32 + sw128((uint32_t)row * 128u + kofs));
            }
            uint32_t bh[8][2], bl[8][2];
#pragma unroll
            for (int nh = 0; nh < 4; nh++) {
                int row = wn + nh * 16 + qrow;
                uint32_t t[4];
                ldm_x4(t, Bh32 + sw128((uint32_t)row * 128u + kofs));
                bh[nh * 2 + 0][0] = t[0]; bh[nh * 2 + 0][1] = t[2];
                bh[nh * 2 + 1][0] = t[1]; bh[nh * 2 + 1][1] = t[3];
                ldm_x4(t, Bl32 + sw128((uint32_t)row * 128u + kofs));
                bl[nh * 2 + 0][0] = t[0]; bl[nh * 2 + 0][1] = t[2];
                bl[nh * 2 + 1][0] = t[1]; bl[nh * 2 + 1][1] = t[3];
            }
#pragma unroll
            for (int mf = 0; mf < 4; mf++)
#pragma unroll
                for (int nf = 0; nf < 8; nf++)
                    mma_bf16(acc[mf][nf], ah[mf], bh[nf]);
#pragma unroll
            for (int mf = 0; mf < 4; mf++)
#pragma unroll
                for (int nf = 0; nf < 8; nf++)
                    mma_bf16(acc[mf][nf], ah[mf], bl[nf]);
            uint32_t al[4][4];
#pragma unroll
            for (int mf = 0; mf < 4; mf++) {
                int row = wm + mf * 16 + qrow;
                ldm_x4(al[mf], Al32 + sw128((uint32_t)row * 128u + kofs));
            }
#pragma unroll
            for (int mf = 0; mf < 4; mf++)
#pragma unroll
                for (int nf = 0; nf < 8; nf++)
                    mma_bf16(acc[mf][nf], al[mf], bh[nf]);
        }
        __syncthreads();
    }

    const int r0 = lane >> 2, c0 = (lane & 3) * 2;
#pragma unroll
    for (int mf = 0; mf < 4; mf++) {
        const int mA = m0 + wm + mf * 16 + r0;
        const float* mrow = mask ? (mask + (size_t)(mA >> 4) * MAXT) : (const float*)0;
#pragma unroll
        for (int nf = 0; nf < 8; nf++) {
            const int n = n0 + wn + nf * 8 + c0;
            float v0 = acc[mf][nf][0], v1 = acc[mf][nf][1];
            float v2 = acc[mf][nf][2], v3 = acc[mf][nf][3];
            if (mask) {
                v0 = v0 * scale + mrow[n];
                v1 = v1 * scale + mrow[n + 1];
                v2 = v2 * scale + mrow[n];
                v3 = v3 * scale + mrow[n + 1];
            }
            *(float2*)&C[(size_t)mA * ldc + n]       = make_float2(v0, v1);
            *(float2*)&C[(size_t)(mA + 8) * ldc + n] = make_float2(v2, v3);
        }
    }
}

// ====== split-K variant (projections): z = k-part, atomicAdd epilogue ========
__global__ void __launch_bounds__(256)
gemm_mma_sk(const __nv_bfloat16* __restrict__ Ah, const __nv_bfloat16* __restrict__ Al,
            const __nv_bfloat16* __restrict__ Bh, const __nv_bfloat16* __restrict__ Bl,
            float* __restrict__ C, int ldc, int K, int kpart, int N)
{
    extern __shared__ char smem[];
    const int m0 = blockIdx.y * 128, n0 = blockIdx.x * 128;
    const int kb = blockIdx.z * kpart;

    const int tid = threadIdx.x;
    const int warp = tid >> 5, lane = tid & 31;
    const int wm = (warp >> 2) * 64, wn = (warp & 3) * 32;

    const int lrow = tid >> 1, lhalf = tid & 1;
    const __nv_bfloat16* srcs[4];
    srcs[0] = Ah + (size_t)(m0 + lrow) * K + kb;
    srcs[1] = Al + (size_t)(m0 + lrow) * K + kb;
    srcs[2] = Bh + (size_t)(n0 + lrow) * K + kb;
    srcs[3] = Bl + (size_t)(n0 + lrow) * K + kb;
    const uint32_t smem32 = smem_u32(smem);
    uint32_t soff[4][4];
#pragma unroll
    for (int t = 0; t < 4; t++)
#pragma unroll
        for (int i = 0; i < 4; i++)
            soff[t][i] = (uint32_t)t * 16384u + sw128((uint32_t)lrow * 128u + lhalf * 64u + i * 16u);

    const int qrow = lane & 15, qsel = lane >> 4;

    float acc[4][4][4];
#pragma unroll
    for (int i = 0; i < 4; i++)
#pragma unroll
        for (int j = 0; j < 4; j++)
#pragma unroll
            for (int r = 0; r < 4; r++) acc[i][j][r] = 0.f;

    const int nch = kpart >> 6;
    {
        const int ke = lhalf * 32;
#pragma unroll
        for (int t = 0; t < 4; t++)
#pragma unroll
            for (int i = 0; i < 4; i++)
                cpa16(smem32 + soff[t][i], srcs[t] + ke + i * 8);
        cpa_commit();
    }

    for (int c = 0; c < nch; c++) {
        if (c + 1 < nch) {
            const int ke = (c + 1) * 64 + lhalf * 32;
            const uint32_t sb = smem32 + ((c + 1) & 1) * STAGE_B;
#pragma unroll
            for (int t = 0; t < 4; t++)
#pragma unroll
                for (int i = 0; i < 4; i++)
                    cpa16(sb + soff[t][i], srcs[t] + ke + i * 8);
            cpa_commit();
            cpa_wait1();
        } else {
            cpa_wait0();
        }
        __syncthreads();

        const uint32_t st = smem32 + (c & 1) * STAGE_B;
        const uint32_t Ah32 = st, Al32 = st + 16384, Bh32 = st + 32768, Bl32 = st + 49152;
#pragma unroll
        for (int ks = 0; ks < 4; ks++) {
            const uint32_t kofs = ks * 32u + qsel * 16u;
            uint32_t ah[4][4];
#pragma unroll
            for (int mf = 0; mf < 4; mf++) {
                int row = wm + mf * 16 + qrow;
                ldm_x4(ah[mf], Ah32 + sw128((uint32_t)row * 128u + kofs));
            }
            uint32_t bh[4][2], bl[4][2];
#pragma unroll
            for (int nh = 0; nh < 2; nh++) {
                int row = wn + nh * 16 + qrow;
                uint32_t t[4];
                ldm_x4(t, Bh32 + sw128((uint32_t)row * 128u + kofs));
                bh[nh * 2 + 0][0] = t[0]; bh[nh * 2 + 0][1] = t[2];
                bh[nh * 2 + 1][0] = t[1]; bh[nh * 2 + 1][1] = t[3];
                ldm_x4(t, Bl32 + sw128((uint32_t)row * 128u + kofs));
                bl[nh * 2 + 0][0] = t[0]; bl[nh * 2 + 0][1] = t[2];
                bl[nh * 2 + 1][0] = t[1]; bl[nh * 2 + 1][1] = t[3];
            }
#pragma unroll
            for (int mf = 0; mf < 4; mf++)
#pragma unroll
                for (int nf = 0; nf < 4; nf++)
                    mma_bf16(acc[mf][nf], ah[mf], bh[nf]);
#pragma unroll
            for (int mf = 0; mf < 4; mf++)
#pragma unroll
                for (int nf = 0; nf < 4; nf++)
                    mma_bf16(acc[mf][nf], ah[mf], bl[nf]);
            uint32_t al[4][4];
#pragma unroll
            for (int mf = 0; mf < 4; mf++) {
                int row = wm + mf * 16 + qrow;
                ldm_x4(al[mf], Al32 + sw128((uint32_t)row * 128u + kofs));
            }
#pragma unroll
            for (int mf = 0; mf < 4; mf++)
#pragma unroll
                for (int nf = 0; nf < 4; nf++)
                    mma_bf16(acc[mf][nf], al[mf], bh[nf]);
        }
        __syncthreads();
    }

    const int r0 = lane >> 2, c0 = (lane & 3) * 2;
#pragma unroll
    for (int mf = 0; mf < 4; mf++) {
        const int mA = m0 + wm + mf * 16 + r0;
#pragma unroll
        for (int nf = 0; nf < 4; nf++) {
            const int n = n0 + wn + nf * 8 + c0;
            if (n < N) {
                atomicAdd(&C[(size_t)mA * ldc + n],           acc[mf][nf][0]);
                atomicAdd(&C[(size_t)mA * ldc + n + 1],       acc[mf][nf][1]);
                atomicAdd(&C[(size_t)(mA + 8) * ldc + n],     acc[mf][nf][2]);
                atomicAdd(&C[(size_t)(mA + 8) * ldc + n + 1], acc[mf][nf][3]);
            }
        }
    }
}

// ================= merged weight/x conversion ================================
#define C4_X    131072
#define C4_QD   (C4_X + 393216)
#define C4_QU   (C4_QD + 589824)
#define C4_KVD  (C4_QU + 327680)
#define C4_OUT  (C4_KVD + 1048576)
#define KVD_SRC4 294912
__global__ void conv_all(const float4* __restrict__ x, const float4* __restrict__ wqd,
                         const float4* __restrict__ wqu, const float4* __restrict__ wkvd,
                         const float4* __restrict__ wout) {
    const int i = blockIdx.x * 256 + threadIdx.x;
    if (i < C4_X) {
        split4(x[i], g_xh, g_xl, i);
    } else if (i < C4_QD) {
        const int j = i - C4_X;
        split4(wqd[j], g_wqdh, g_wqdl, j);
    } else if (i < C4_QU) {
        const int j = i - C4_QD;
        split4(wqu[j], g_wquh, g_wqul, j);
    } else if (i < C4_KVD) {
        const int j = i - C4_QU;
        float4 v = (j < KVD_SRC4) ? wkvd[j] : make_float4(0.f, 0.f, 0.f, 0.f);
        split4(v, g_wkvdh, g_wkvdl, j);
    } else if (i < C4_OUT) {
        const int j = i - C4_KVD;
        split4(wout[j], g_wouth, g_woutl, j);
    }
}

// ================= small conversions ========================================
__global__ void conv_split4(const float4* __restrict__ src, __nv_bfloat16* h, __nv_bfloat16* l, int n4) {
    const int i = blockIdx.x * 256 + threadIdx.x;
    if (i < n4) split4(src[i], h, l, i);
}
__global__ void conv_qcat4() {
    const size_t i = (size_t)blockIdx.x * 256 + threadIdx.x;
    split4(*(const float4*)&g_qcat[i * 4], g_qc_h, g_qc_l, i);
}
__global__ void build_kvcat4(const float* __restrict__ kvc, const float* __restrict__ krc) {
    const size_t i4 = (size_t)blockIdx.x * 256 + threadIdx.x;
    const size_t idx = i4 * 4;
    const int c = (int)(idx % CATD);
    const size_t bt = idx / CATD;
    const int t = (int)(bt % MAXT);
    const int b = (int)(bt / MAXT);
    float4 v;
    if (t >= START_P)
        v = *(const float4*)&g_kv[(size_t)((b << 5) + (t - START_P)) * CATD + c];
    else if (c < KVR)
        v = *(const float4*)&kvc[((size_t)b * MAXT + t) * KVR + c];
    else
        v = *(const float4*)&krc[((size_t)b * MAXT + t) * DR + (c - KVR)];
    split4(v, g_kc_h, g_kc_l, i4);
}
__global__ void build_kvt(const float* __restrict__ kvc) {
    __shared__ float tile[32][33];
    const int b = blockIdx.z;
    const int t0 = blockIdx.x * 32, n0 = blockIdx.y * 32;
    const int tx = threadIdx.x, ty = threadIdx.y;
#pragma unroll
    for (int i = 0; i < 4; i++) {
        const int t = t0 + ty + i * 8;
        float v;
        if (t >= START_P)
            v = g_kv[(size_t)((b << 5) + (t - START_P)) * CATD + n0 + tx];
        else
            v = kvc[((size_t)b * MAXT + t) * KVR + n0 + tx];
        tile[ty + i * 8][tx] = v;
    }
    __syncthreads();
#pragma unroll
    for (int i = 0; i < 4; i++) {
        const int n = n0 + ty + i * 8;
        const float x = tile[tx][ty + i * 8];
        const size_t o = ((size_t)(b * KVR + n)) * MAXT + t0 + tx;
        split_write(x, g_kt_h, g_kt_l, o);
    }
}

// ================= RMSNorm ===================================================
__global__ void rms_kernel(const float* __restrict__ w) {
    const int row = blockIdx.x;
    const float* xr = g_qd + row * QR;
    __shared__ float red[256];
    const int tid = threadIdx.x;
    float v[3], s = 0.f;
#pragma unroll
    for (int i = 0; i < 3; i++) { v[i] = xr[tid + i * 256]; s += v[i] * v[i]; }
    red[tid] = s; __syncthreads();
    for (int o = 128; o > 0; o >>= 1) {
        if (tid < o) red[tid] += red[tid + o];
        __syncthreads();
    }
    const float r = rsqrtf(red[0] / (float)QR + 1.1920929e-07f);
    __syncthreads();
#pragma unroll
    for (int i = 0; i < 3; i++) {
        const float y = v[i] * r * w[tid + i * 256];
        split_write(y, g_qnh, g_qnl, (size_t)row * QR + tid + i * 256);
    }
}

// ================= rope ======================================================
__global__ void rope_kernel(const float* __restrict__ fc, const float* __restrict__ fs) {
    const int idx = blockIdx.x * 256 + threadIdx.x;
    const int NQ = BATCH * SEQ_L * NH * (DR / 2);
    if (idx < NQ) {
        const int j = idx & 31, h = (idx >> 5) & 15, l = (idx >> 9) & 31, b = idx >> 14;
        const float* src = &g_q[(size_t)(b * SEQ_L + l) * (NH * QKD) + h * QKD + DNR + 2 * j];
        const float xr = src[0], xi = src[1];
        const float c = fc[l * 32 + j], s = fs[l * 32 + j];
        float* dst = &g_qcat[(size_t)(b * ROWSPB + l * NH + h) * CATD + KVR + 2 * j];
        dst[0] = xr * c - xi * s;
        dst[1] = xr * s + xi * c;
    } else if (idx < NQ + BATCH * SEQ_L * (DR / 2)) {
        const int k = idx - NQ;
        const int j = k & 31, l = (k >> 5) & 31, b = k >> 10;
        float* p = &g_kv[(size_t)(b * SEQ_L + l) * CATD + KVR + 2 * j];
        const float xr = p[0], xi = p[1];
        const float c = fc[l * 32 + j], s = fs[l * 32 + j];
        p[0] = xr * c - xi * s;
        p[1] = xr * s + xi * c;
    }
}

// ================= q_abs (fp32, per-head NN) =================================
__global__ void qabs_kernel(const float* __restrict__ wkv) {
    const int h = blockIdx.z;
    const int m0 = blockIdx.y * 64, n0 = blockIdx.x * 64;
    const float* A = g_q + h * QKD;
    const float* Bm = wkv + (size_t)h * 256 * KVR;
    __shared__ float As[8][64];
    __shared__ float Bs[8][64];
    const int tid = threadIdx.x;
    const int ty = tid >> 4, tx = tid & 15;
    const int lr = tid >> 2, lc = (tid & 3) * 2;
    const int br = tid >> 5, bc = (tid & 31) * 2;
    float acc[4][4] = {};
    for (int k0 = 0; k0 < DNR; k0 += 8) {
        float2 av = *(const float2*)&A[(size_t)(m0 + lr) * (NH * QKD) + k0 + lc];
        As[lc][lr] = av.x; As[lc + 1][lr] = av.y;
        float2 bv = *(const float2*)&Bm[(size_t)(k0 + br) * KVR + n0 + bc];
        Bs[br][bc] = bv.x; Bs[br][bc + 1] = bv.y;
        __syncthreads();
#pragma unroll
        for (int kk = 0; kk < 8; kk++) {
            float a[4], b[4];
#pragma unroll
            for (int i = 0; i < 4; i++) a[i] = As[kk][ty * 4 + i];
#pragma unroll
            for (int j = 0; j < 4; j++) b[j] = Bs[kk][tx * 4 + j];
#pragma unroll
            for (int i = 0; i < 4; i++)
#pragma unroll
                for (int j = 0; j < 4; j++) acc[i][j] += a[i] * b[j];
        }
        __syncthreads();
    }
#pragma unroll
    for (int i = 0; i < 4; i++) {
        const int m = m0 + ty * 4 + i;
        const int row = (m >> 5) * ROWSPB + (m & 31) * NH + h;
#pragma unroll
        for (int j = 0; j < 4; j++)
            g_qcat[(size_t)row * CATD + n0 + tx * 4 + j] = acc[i][j];
    }
}

// ================= softmax -> bf16 hi/lo P ===================================
__global__ void softmax_split() {
    const int row = blockIdx.x;
    float* s = g_S + (size_t)row * MAXT;
    __shared__ float red[256];
    const int tid = threadIdx.x;
    float4 v[4];
    float mx = -INFINITY;
#pragma unroll
    for (int g = 0; g < 4; g++) {
        v[g] = *(float4*)&s[tid * 4 + g * 1024];
        mx = fmaxf(mx, fmaxf(fmaxf(v[g].x, v[g].y), fmaxf(v[g].z, v[g].w)));
    }
    red[tid] = mx; __syncthreads();
    for (int o = 128; o > 0; o >>= 1) {
        if (tid < o) red[tid] = fmaxf(red[tid], red[tid + o]);
        __syncthreads();
    }
    mx = red[0]; __syncthreads();
    float sum = 0.f;
#pragma unroll
    for (int g = 0; g < 4; g++) {
        v[g].x = __expf(v[g].x - mx); v[g].y = __expf(v[g].y - mx);
        v[g].z = __expf(v[g].z - mx); v[g].w = __expf(v[g].w - mx);
        sum += v[g].x + v[g].y + v[g].z + v[g].w;
    }
    red[tid] = sum; __syncthreads();
    for (int o = 128; o > 0; o >>= 1) {
        if (tid < o) red[tid] += red[tid + o];
        __syncthreads();
    }
    const float inv = 1.f / red[0];
#pragma unroll
    for (int g = 0; g < 4; g++) {
        float4 p = make_float4(v[g].x * inv, v[g].y * inv, v[g].z * inv, v[g].w * inv);
        split4(p, g_p_h, g_p_l, ((size_t)row * MAXT + tid * 4 + g * 1024) >> 2);
    }
}

// ================= value up-proj (fp32, per-head NT) =========================
__global__ void oup_kernel(const float* __restrict__ wkv) {
    const int h = blockIdx.z;
    const int m0 = blockIdx.y * 64, n0 = blockIdx.x * 64;
    const float* Bw = wkv + (size_t)(h * 256 + DNR) * KVR;
    __shared__ float As[8][64];
    __shared__ float Bs[8][64];
    const int tid = threadIdx.x;
    const int ty = tid >> 4, tx = tid & 15;
    const int lr = tid >> 2, lc = (tid & 3) * 2;
    float acc[4][4] = {};
    const int mrow = m0 + lr;
    const int arow = (mrow >> 5) * ROWSPB + (mrow & 31) * NH + h;
    for (int k0 = 0; k0 < KVR; k0 += 8) {
        float2 av = *(const float2*)&g_O[(size_t)arow * KVR + k0 + lc];
        float2 bv = *(const float2*)&Bw[(size_t)(n0 + lr) * KVR + k0 + lc];
        As[lc][lr] = av.x; As[lc + 1][lr] = av.y;
        Bs[lc][lr] = bv.x; Bs[lc + 1][lr] = bv.y;
        __syncthreads();
#pragma unroll
        for (int kk = 0; kk < 8; kk++) {
            float a[4], b[4];
#pragma unroll
            for (int i = 0; i < 4; i++) a[i] = As[kk][ty * 4 + i];
#pragma unroll
            for (int j = 0; j < 4; j++) b[j] = Bs[kk][tx * 4 + j];
#pragma unroll
            for (int i = 0; i < 4; i++)
#pragma unroll
                for (int j = 0; j < 4; j++) acc[i][j] += a[i] * b[j];
        }
        __syncthreads();
    }
#pragma unroll
    for (int i = 0; i < 4; i++)
#pragma unroll
        for (int j = 0; j < 4; j++)
            g_o2[(size_t)(m0 + ty * 4 + i) * (NH * DV) + h * DV + n0 + tx * 4 + j] = acc[i][j];
}

// ============================== launcher =====================================
extern "C" void kernel_launch(void* const* d_in, const int* in_sizes, int n_in,
                              void* d_out, int out_size) {
    const float* x      = (const float*)d_in[0];
    const float* fc     = (const float*)d_in[2];
    const float* fs     = (const float*)d_in[3];
    const float* mask   = (const float*)d_in[4];
    const float* kvc    = (const float*)d_in[5];
    const float* krc    = (const float*)d_in[6];
    const float* w_kvd  = (const float*)d_in[7];
    const float* w_qd   = (const float*)d_in[8];
    const float* rms_w  = (const float*)d_in[9];
    const float* w_qu   = (const float*)d_in[10];
    const float* w_kvu  = (const float*)d_in[11];
    const float* w_out  = (const float*)d_in[12];
    float* out = (float*)d_out;

    float *p_qd, *p_q, *p_kv, *p_S, *p_O, *p_o2;
    cudaGetSymbolAddress((void**)&p_qd, g_qd);
    cudaGetSymbolAddress((void**)&p_q,  g_q);
    cudaGetSymbolAddress((void**)&p_kv, g_kv);
    cudaGetSymbolAddress((void**)&p_S, g_S);
    cudaGetSymbolAddress((void**)&p_O, g_O);
    cudaGetSymbolAddress((void**)&p_o2, g_o2);

    __nv_bfloat16 *xh, *xl, *qnh, *qnl, *o2h, *o2l;
    __nv_bfloat16 *wqdh, *wqdl, *wquh, *wqul, *wkvdh, *wkvdl, *wouth, *woutl;
    __nv_bfloat16 *qch, *qcl, *kch, *kcl, *kth, *ktl, *ph, *pl;
    cudaGetSymbolAddress((void**)&xh, g_xh);     cudaGetSymbolAddress((void**)&xl, g_xl);
    cudaGetSymbolAddress((void**)&qnh, g_qnh);   cudaGetSymbolAddress((void**)&qnl, g_qnl);
    cudaGetSymbolAddress((void**)&o2h, g_o2h);   cudaGetSymbolAddress((void**)&o2l, g_o2l);
    cudaGetSymbolAddress((void**)&wqdh, g_wqdh); cudaGetSymbolAddress((void**)&wqdl, g_wqdl);
    cudaGetSymbolAddress((void**)&wquh, g_wquh); cudaGetSymbolAddress((void**)&wqul, g_wqul);
    cudaGetSymbolAddress((void**)&wkvdh, g_wkvdh); cudaGetSymbolAddress((void**)&wkvdl, g_wkvdl);
    cudaGetSymbolAddress((void**)&wouth, g_wouth); cudaGetSymbolAddress((void**)&woutl, g_woutl);
    cudaGetSymbolAddress((void**)&qch, g_qc_h);  cudaGetSymbolAddress((void**)&qcl, g_qc_l);
    cudaGetSymbolAddress((void**)&kch, g_kc_h);  cudaGetSymbolAddress((void**)&kcl, g_kc_l);
    cudaGetSymbolAddress((void**)&kth, g_kt_h);  cudaGetSymbolAddress((void**)&ktl, g_kt_l);
    cudaGetSymbolAddress((void**)&ph, g_p_h);    cudaGetSymbolAddress((void**)&pl, g_p_l);

    cudaFuncSetAttribute(gemm_mma, cudaFuncAttributeMaxDynamicSharedMemorySize, 2 * STAGE_B);
    cudaFuncSetAttribute(gemm_mma_sk, cudaFuncAttributeMaxDynamicSharedMemorySize, 2 * STAGE_B);
    cudaFuncSetAttribute(gemm_mma_wide, cudaFuncAttributeMaxDynamicSharedMemorySize, 2 * WSTAGE_B);
    const int DSM = 2 * STAGE_B;
    const int WDSM = 2 * WSTAGE_B;

    // ---- conversions (merged) ----
    conv_all<<<C4_OUT / 256, 256>>>((const float4*)x, (const float4*)w_qd, (const float4*)w_qu,
                                    (const float4*)w_kvd, (const float4*)w_out);

    // ---- zero split-K outputs ----
    cudaMemsetAsync(p_qd, 0, (size_t)MBL * QR * 4);
    cudaMemsetAsync(p_q, 0, (size_t)MBL * NH * QKD * 4);
    cudaMemsetAsync(p_kv, 0, (size_t)MBL * CATD * 4);

    // ---- q path (split-K projections) ----
    gemm_mma_sk<<<dim3(QR / 128, MBL / 128, 4), 256, DSM>>>(xh, xl, wqdh, wqdl,
        p_qd, QR, DIM, DIM / 4, QR);
    rms_kernel<<<MBL, 256>>>(rms_w);
    gemm_mma_sk<<<dim3(NH * QKD / 128, MBL / 128, 2), 256, DSM>>>(qnh, qnl, wquh, wqul,
        p_q, NH * QKD, QR, QR / 2, NH * QKD);

    // ---- kv path ----
    gemm_mma_sk<<<dim3(KVD_PAD / 128, MBL / 128, 4), 256, DSM>>>(xh, xl, wkvdh, wkvdl,
        p_kv, CATD, DIM, DIM / 4, CATD);

    rope_kernel<<<(BATCH * SEQ_L * NH * 32 + BATCH * SEQ_L * 32 + 255) / 256, 256>>>(fc, fs);
    qabs_kernel<<<dim3(KVR / 64, MBL / 64, NH), 256>>>(w_kvu);

    conv_qcat4<<<(BATCH * ROWSPB * CATD / 4) / 256, 256>>>();
    build_kvcat4<<<(int)(((size_t)BATCH * MAXT * CATD / 4) / 256), 256>>>(kvc, krc);
    build_kvt<<<dim3(MAXT / 32, KVR / 32, BATCH), dim3(32, 8)>>>(kvc);

    // ---- attention ----
    gemm_mma_wide<<<dim3(MAXT / 256, ROWSPB / 128, BATCH), 256, WDSM>>>(
        qch, qcl, (size_t)ROWSPB * CATD, kch, kcl, (size_t)MAXT * CATD,
        p_S, MAXT, (size_t)ROWSPB * MAXT, CATD, mask, SCALE_F);
    softmax_split<<<BATCH * ROWSPB, 256>>>();
    gemm_mma<<<dim3(KVR / 128, ROWSPB / 128, BATCH), 256, DSM>>>(
        ph, pl, (size_t)ROWSPB * MAXT, kth, ktl, (size_t)KVR * MAXT,
        p_O, KVR, (size_t)ROWSPB * KVR, MAXT, KVR, nullptr, 1.f);

    // ---- output path ----
    oup_kernel<<<dim3(DV / 64, MBL / 64, NH), 256>>>(w_kvu);
    conv_split4<<<(MBL * NH * DV / 4 + 255) / 256, 256>>>((const float4*)p_o2, o2h, o2l, MBL * NH * DV / 4);
    cudaMemsetAsync(out, 0, (size_t)MBL * DIM * 4);
    gemm_mma_sk<<<dim3(DIM / 128, MBL / 128, 4), 256, DSM>>>(o2h, o2l, wouth, woutl,
        out, DIM, NH * DV, NH * DV / 4, DIM);
}

// round 6
// speedup vs baseline: 3.0847x; 1.0666x over previous
#include <cuda_runtime.h>
#include <cuda_bf16.h>
#include <math.h>
#include <stdint.h>

// ---------------- problem constants -----------------------------------------
#define BATCH   8
#define SEQ_L   32
#define DIM     2048
#define KVR     512
#define QR      768
#define NH      16
#define DNR     128
#define DR      64
#define DV      128
#define MAXT    4096
#define START_P 4064
#define QKD     192
#define CATD    576
#define MBL     256
#define ROWSPB  512
#define SCALE_F 0.07216878364870323f
#define KVD_PAD 640

// ---------------- fp32 scratch ----------------------------------------------
__device__ __align__(16) float g_qd  [MBL * QR];
__device__ __align__(16) float g_q   [MBL * NH * QKD];
__device__ __align__(16) float g_kv  [MBL * CATD];
__device__ __align__(16) float g_S   [(size_t)BATCH * ROWSPB * MAXT];
// ---------------- bf16 hi/lo operands ----------------------------------------
__device__ __align__(16) __nv_bfloat16 g_qc_h[BATCH * ROWSPB * CATD];
__device__ __align__(16) __nv_bfloat16 g_qc_l[BATCH * ROWSPB * CATD];
__device__ __align__(16) __nv_bfloat16 g_kc_h[(size_t)BATCH * MAXT * CATD];
__device__ __align__(16) __nv_bfloat16 g_kc_l[(size_t)BATCH * MAXT * CATD];
__device__ __align__(16) __nv_bfloat16 g_kt_h[(size_t)BATCH * KVR * MAXT];
__device__ __align__(16) __nv_bfloat16 g_kt_l[(size_t)BATCH * KVR * MAXT];
__device__ __align__(16) __nv_bfloat16 g_p_h [(size_t)BATCH * ROWSPB * MAXT];
__device__ __align__(16) __nv_bfloat16 g_p_l [(size_t)BATCH * ROWSPB * MAXT];
__device__ __align__(16) __nv_bfloat16 g_xh  [MBL * DIM];
__device__ __align__(16) __nv_bfloat16 g_xl  [MBL * DIM];
__device__ __align__(16) __nv_bfloat16 g_qnh [MBL * QR];
__device__ __align__(16) __nv_bfloat16 g_qnl [MBL * QR];
__device__ __align__(16) __nv_bfloat16 g_qh  [MBL * NH * QKD];
__device__ __align__(16) __nv_bfloat16 g_ql  [MBL * NH * QKD];
__device__ __align__(16) __nv_bfloat16 g_Oh  [BATCH * ROWSPB * KVR];
__device__ __align__(16) __nv_bfloat16 g_Ol  [BATCH * ROWSPB * KVR];
__device__ __align__(16) __nv_bfloat16 g_o2h [MBL * NH * DV];
__device__ __align__(16) __nv_bfloat16 g_o2l [MBL * NH * DV];
__device__ __align__(16) __nv_bfloat16 g_wqdh[QR * DIM];
__device__ __align__(16) __nv_bfloat16 g_wqdl[QR * DIM];
__device__ __align__(16) __nv_bfloat16 g_wquh[NH * QKD * QR];
__device__ __align__(16) __nv_bfloat16 g_wqul[NH * QKD * QR];
__device__ __align__(16) __nv_bfloat16 g_wkvdh[KVD_PAD * DIM];
__device__ __align__(16) __nv_bfloat16 g_wkvdl[KVD_PAD * DIM];
__device__ __align__(16) __nv_bfloat16 g_wouth[DIM * NH * DV];
__device__ __align__(16) __nv_bfloat16 g_woutl[DIM * NH * DV];
__device__ __align__(16) __nv_bfloat16 g_wvh [NH * 256 * KVR];   // full w_kvu (NT layout)
__device__ __align__(16) __nv_bfloat16 g_wvl [NH * 256 * KVR];
__device__ __align__(16) __nv_bfloat16 g_wnrth[NH * KVR * DNR];  // transposed nr part
__device__ __align__(16) __nv_bfloat16 g_wnrtl[NH * KVR * DNR];

// ================= helpers ===================================================
__device__ __forceinline__ uint32_t smem_u32(const void* p) {
    uint32_t a;
    asm("{ .reg .u64 t; cvta.to.shared.u64 t, %1; cvt.u32.u64 %0, t; }" : "=r"(a) : "l"(p));
    return a;
}
__device__ __forceinline__ uint32_t sw128(uint32_t o) { return o ^ ((o >> 3) & 0x70); }
__device__ __forceinline__ void cpa16(uint32_t saddr, const void* g) {
    asm volatile("cp.async.cg.shared.global [%0], [%1], 16;" :: "r"(saddr), "l"(g));
}
__device__ __forceinline__ void cpa_commit() { asm volatile("cp.async.commit_group;" ::: "memory"); }
__device__ __forceinline__ void cpa_wait1()  { asm volatile("cp.async.wait_group 1;" ::: "memory"); }
__device__ __forceinline__ void cpa_wait0()  { asm volatile("cp.async.wait_group 0;" ::: "memory"); }
__device__ __forceinline__ void ldm_x4(uint32_t* r, uint32_t addr) {
    asm volatile("ldmatrix.sync.aligned.m8n8.x4.shared.b16 {%0,%1,%2,%3}, [%4];"
                 : "=r"(r[0]), "=r"(r[1]), "=r"(r[2]), "=r"(r[3]) : "r"(addr));
}
__device__ __forceinline__ void mma_bf16(float* c, const uint32_t* a, const uint32_t* b) {
    asm volatile("mma.sync.aligned.m16n8k16.row.col.f32.bf16.bf16.f32 "
                 "{%0,%1,%2,%3}, {%4,%5,%6,%7}, {%8,%9}, {%0,%1,%2,%3};"
                 : "+f"(c[0]), "+f"(c[1]), "+f"(c[2]), "+f"(c[3])
                 : "r"(a[0]), "r"(a[1]), "r"(a[2]), "r"(a[3]), "r"(b[0]), "r"(b[1]));
}
__device__ __forceinline__ void split_write(float x, __nv_bfloat16* h, __nv_bfloat16* l, size_t i) {
    __nv_bfloat16 hv = __float2bfloat16(x);
    h[i] = hv;
    l[i] = __float2bfloat16(x - __bfloat162float(hv));
}
__device__ __forceinline__ void split4(float4 v, __nv_bfloat16* h, __nv_bfloat16* l, size_t i4) {
    __nv_bfloat16 h0 = __float2bfloat16(v.x), h1 = __float2bfloat16(v.y);
    __nv_bfloat16 h2 = __float2bfloat16(v.z), h3 = __float2bfloat16(v.w);
    __nv_bfloat16 l0 = __float2bfloat16(v.x - __bfloat162float(h0));
    __nv_bfloat16 l1 = __float2bfloat16(v.y - __bfloat162float(h1));
    __nv_bfloat16 l2 = __float2bfloat16(v.z - __bfloat162float(h2));
    __nv_bfloat16 l3 = __float2bfloat16(v.w - __bfloat162float(h3));
    __nv_bfloat162 hh0 = {h0, h1}, hh1 = {h2, h3};
    __nv_bfloat162 ll0 = {l0, l1}, ll1 = {l2, l3};
    uint2 hw = make_uint2(*(uint32_t*)&hh0, *(uint32_t*)&hh1);
    uint2 lw = make_uint2(*(uint32_t*)&ll0, *(uint32_t*)&ll1);
    *(uint2*)&h[i4 * 4] = hw;
    *(uint2*)&l[i4 * 4] = lw;
}

#define STAGE_B 65536

// ======== shared mainloop macro body (128x128, 4x 16KB tiles / stage) ========
// Computes acc[4][4][4] for split products. Loader uses precomputed srcs[4]/soff.
#define MAINLOOP_128(NCH)                                                            \
    {                                                                                \
        const int ke0 = lhalf * 32;                                                  \
        _Pragma("unroll") for (int t = 0; t < 4; t++)                                \
            _Pragma("unroll") for (int i = 0; i < 4; i++)                            \
                cpa16(smem32 + soff[t][i], srcs[t] + ke0 + i * 8);                   \
        cpa_commit();                                                                \
    }                                                                                \
    for (int c = 0; c < (NCH); c++) {                                                \
        if (c + 1 < (NCH)) {                                                         \
            const int ke = (c + 1) * 64 + lhalf * 32;                                \
            const uint32_t sb = smem32 + ((c + 1) & 1) * STAGE_B;                    \
            _Pragma("unroll") for (int t = 0; t < 4; t++)                            \
                _Pragma("unroll") for (int i = 0; i < 4; i++)                        \
                    cpa16(sb + soff[t][i], srcs[t] + ke + i * 8);                    \
            cpa_commit();                                                            \
            cpa_wait1();                                                             \
        } else {                                                                     \
            cpa_wait0();                                                             \
        }                                                                            \
        __syncthreads();                                                             \
        const uint32_t st = smem32 + (c & 1) * STAGE_B;                              \
        const uint32_t Ah32 = st, Al32 = st + 16384, Bh32 = st + 32768, Bl32 = st + 49152; \
        _Pragma("unroll") for (int ks = 0; ks < 4; ks++) {                           \
            const uint32_t kofs = ks * 32u + qsel * 16u;                             \
            uint32_t ah[4][4];                                                       \
            _Pragma("unroll") for (int mf = 0; mf < 4; mf++) {                       \
                int row = wm + mf * 16 + qrow;                                       \
                ldm_x4(ah[mf], Ah32 + sw128((uint32_t)row * 128u + kofs));           \
            }                                                                        \
            uint32_t bh[4][2], bl[4][2];                                             \
            _Pragma("unroll") for (int nh = 0; nh < 2; nh++) {                       \
                int row = wn + nh * 16 + qrow;                                       \
                uint32_t t[4];                                                       \
                ldm_x4(t, Bh32 + sw128((uint32_t)row * 128u + kofs));                \
                bh[nh * 2 + 0][0] = t[0]; bh[nh * 2 + 0][1] = t[2];                  \
                bh[nh * 2 + 1][0] = t[1]; bh[nh * 2 + 1][1] = t[3];                  \
                ldm_x4(t, Bl32 + sw128((uint32_t)row * 128u + kofs));                \
                bl[nh * 2 + 0][0] = t[0]; bl[nh * 2 + 0][1] = t[2];                  \
                bl[nh * 2 + 1][0] = t[1]; bl[nh * 2 + 1][1] = t[3];                  \
            }                                                                        \
            _Pragma("unroll") for (int mf = 0; mf < 4; mf++)                         \
                _Pragma("unroll") for (int nf = 0; nf < 4; nf++)                     \
                    mma_bf16(acc[mf][nf], ah[mf], bh[nf]);                           \
            _Pragma("unroll") for (int mf = 0; mf < 4; mf++)                         \
                _Pragma("unroll") for (int nf = 0; nf < 4; nf++)                     \
                    mma_bf16(acc[mf][nf], ah[mf], bl[nf]);                           \
            uint32_t al[4][4];                                                       \
            _Pragma("unroll") for (int mf = 0; mf < 4; mf++) {                       \
                int row = wm + mf * 16 + qrow;                                       \
                ldm_x4(al[mf], Al32 + sw128((uint32_t)row * 128u + kofs));           \
            }                                                                        \
            _Pragma("unroll") for (int mf = 0; mf < 4; mf++)                         \
                _Pragma("unroll") for (int nf = 0; nf < 4; nf++)                     \
                    mma_bf16(acc[mf][nf], al[mf], bh[nf]);                           \
        }                                                                            \
        __syncthreads();                                                             \
    }

#define DECL_COMMON                                                                  \
    const int tid = threadIdx.x;                                                     \
    const int warp = tid >> 5, lane = tid & 31;                                      \
    const int wm = (warp >> 2) * 64, wn = (warp & 3) * 32;                           \
    const int lrow = tid >> 1, lhalf = tid & 1;                                      \
    const uint32_t smem32 = smem_u32(smem);                                          \
    const int qrow = lane & 15, qsel = lane >> 4;                                    \
    float acc[4][4][4];                                                              \
    _Pragma("unroll") for (int i = 0; i < 4; i++)                                    \
        _Pragma("unroll") for (int j = 0; j < 4; j++)                                \
            _Pragma("unroll") for (int r = 0; r < 4; r++) acc[i][j][r] = 0.f;        \
    uint32_t soff[4][4];                                                             \
    _Pragma("unroll") for (int t = 0; t < 4; t++)                                    \
        _Pragma("unroll") for (int i = 0; i < 4; i++)                                \
            soff[t][i] = (uint32_t)t * 16384u + sw128((uint32_t)lrow * 128u + lhalf * 64u + i * 16u);

// ====== ogemm: O = P*KV^T, epilogue -> split bf16 ============================
__global__ void __launch_bounds__(256)
gemm_mma_osplit(const __nv_bfloat16* __restrict__ Ah, const __nv_bfloat16* __restrict__ Al, size_t sAz,
                const __nv_bfloat16* __restrict__ Bh, const __nv_bfloat16* __restrict__ Bl, size_t sBz,
                __nv_bfloat16* __restrict__ Ch, __nv_bfloat16* __restrict__ Cl, int ldc, size_t sCz,
                int K)
{
    extern __shared__ char smem[];
    const int z = blockIdx.z;
    const int m0 = blockIdx.y * 128, n0 = blockIdx.x * 128;
    Ah += (size_t)z * sAz;  Al += (size_t)z * sAz;
    Bh += (size_t)z * sBz;  Bl += (size_t)z * sBz;
    Ch += (size_t)z * sCz;  Cl += (size_t)z * sCz;
    DECL_COMMON
    const __nv_bfloat16* srcs[4];
    srcs[0] = Ah + (size_t)(m0 + lrow) * K;
    srcs[1] = Al + (size_t)(m0 + lrow) * K;
    srcs[2] = Bh + (size_t)(n0 + lrow) * K;
    srcs[3] = Bl + (size_t)(n0 + lrow) * K;
    const int nch = K >> 6;
    MAINLOOP_128(nch)
    const int r0 = lane >> 2, c0 = (lane & 3) * 2;
#pragma unroll
    for (int mf = 0; mf < 4; mf++) {
        const int mA = m0 + wm + mf * 16 + r0;
#pragma unroll
        for (int nf = 0; nf < 4; nf++) {
            const int n = n0 + wn + nf * 8 + c0;
            const size_t i0 = (size_t)mA * ldc + n;
            const size_t i1 = (size_t)(mA + 8) * ldc + n;
            split_write(acc[mf][nf][0], Ch, Cl, i0);
            split_write(acc[mf][nf][1], Ch, Cl, i0 + 1);
            split_write(acc[mf][nf][2], Ch, Cl, i1);
            split_write(acc[mf][nf][3], Ch, Cl, i1 + 1);
        }
    }
}

// ====== qabs: per-head q_nrope @ w_nr^T -> split bf16 into qcat ==============
__global__ void __launch_bounds__(256)
qabs_mma()
{
    extern __shared__ char smem[];
    const int h = blockIdx.z;
    const int m0 = blockIdx.y * 128, n0 = blockIdx.x * 128;
    DECL_COMMON
    const __nv_bfloat16* srcs[4];
    srcs[0] = g_qh + (size_t)(m0 + lrow) * (NH * QKD) + h * QKD;
    srcs[1] = g_ql + (size_t)(m0 + lrow) * (NH * QKD) + h * QKD;
    srcs[2] = g_wnrth + (size_t)h * KVR * DNR + (size_t)(n0 + lrow) * DNR;
    srcs[3] = g_wnrtl + (size_t)h * KVR * DNR + (size_t)(n0 + lrow) * DNR;
    MAINLOOP_128(2)
    const int r0 = lane >> 2, c0 = (lane & 3) * 2;
#pragma unroll
    for (int mf = 0; mf < 4; mf++) {
        const int mA = m0 + wm + mf * 16 + r0;
        const int rowA = ((mA >> 5) * ROWSPB) + (mA & 31) * NH + h;
        const int rowB = (((mA + 8) >> 5) * ROWSPB) + ((mA + 8) & 31) * NH + h;
#pragma unroll
        for (int nf = 0; nf < 4; nf++) {
            const int n = n0 + wn + nf * 8 + c0;
            const size_t i0 = (size_t)rowA * CATD + n;
            const size_t i1 = (size_t)rowB * CATD + n;
            split_write(acc[mf][nf][0], g_qc_h, g_qc_l, i0);
            split_write(acc[mf][nf][1], g_qc_h, g_qc_l, i0 + 1);
            split_write(acc[mf][nf][2], g_qc_h, g_qc_l, i1);
            split_write(acc[mf][nf][3], g_qc_h, g_qc_l, i1 + 1);
        }
    }
}

// ====== oup: per-head O @ w_v^T -> split bf16 into o2 ========================
__global__ void __launch_bounds__(256)
oup_mma()
{
    extern __shared__ char smem[];
    const int h = blockIdx.z;
    const int m0 = blockIdx.y * 128, n0 = 0;
    DECL_COMMON
    const int mrow = m0 + lrow;
    const int arow = (mrow >> 5) * ROWSPB + (mrow & 31) * NH + h;
    const __nv_bfloat16* srcs[4];
    srcs[0] = g_Oh + (size_t)arow * KVR;
    srcs[1] = g_Ol + (size_t)arow * KVR;
    srcs[2] = g_wvh + (size_t)(h * 256 + DNR + n0 + lrow) * KVR;
    srcs[3] = g_wvl + (size_t)(h * 256 + DNR + n0 + lrow) * KVR;
    MAINLOOP_128(8)
    const int r0 = lane >> 2, c0 = (lane & 3) * 2;
#pragma unroll
    for (int mf = 0; mf < 4; mf++) {
        const int mA = m0 + wm + mf * 16 + r0;
#pragma unroll
        for (int nf = 0; nf < 4; nf++) {
            const int n = n0 + wn + nf * 8 + c0;
            const size_t i0 = (size_t)mA * (NH * DV) + h * DV + n;
            const size_t i1 = (size_t)(mA + 8) * (NH * DV) + h * DV + n;
            split_write(acc[mf][nf][0], g_o2h, g_o2l, i0);
            split_write(acc[mf][nf][1], g_o2h, g_o2l, i0 + 1);
            split_write(acc[mf][nf][2], g_o2h, g_o2l, i1);
            split_write(acc[mf][nf][3], g_o2h, g_o2l, i1 + 1);
        }
    }
}

// ====== split-K projections: fp32 atomicAdd epilogue =========================
__global__ void __launch_bounds__(256)
gemm_mma_sk(const __nv_bfloat16* __restrict__ Ah, const __nv_bfloat16* __restrict__ Al,
            const __nv_bfloat16* __restrict__ Bh, const __nv_bfloat16* __restrict__ Bl,
            float* __restrict__ C, int ldc, int K, int kpart, int N)
{
    extern __shared__ char smem[];
    const int m0 = blockIdx.y * 128, n0 = blockIdx.x * 128;
    const int kb = blockIdx.z * kpart;
    DECL_COMMON
    const __nv_bfloat16* srcs[4];
    srcs[0] = Ah + (size_t)(m0 + lrow) * K + kb;
    srcs[1] = Al + (size_t)(m0 + lrow) * K + kb;
    srcs[2] = Bh + (size_t)(n0 + lrow) * K + kb;
    srcs[3] = Bl + (size_t)(n0 + lrow) * K + kb;
    const int nch = kpart >> 6;
    MAINLOOP_128(nch)
    const int r0 = lane >> 2, c0 = (lane & 3) * 2;
#pragma unroll
    for (int mf = 0; mf < 4; mf++) {
        const int mA = m0 + wm + mf * 16 + r0;
#pragma unroll
        for (int nf = 0; nf < 4; nf++) {
            const int n = n0 + wn + nf * 8 + c0;
            if (n < N) {
                atomicAdd(&C[(size_t)mA * ldc + n],           acc[mf][nf][0]);
                atomicAdd(&C[(size_t)mA * ldc + n + 1],       acc[mf][nf][1]);
                atomicAdd(&C[(size_t)(mA + 8) * ldc + n],     acc[mf][nf][2]);
                atomicAdd(&C[(size_t)(mA + 8) * ldc + n + 1], acc[mf][nf][3]);
            }
        }
    }
}

// ====== wide 128x256 scores kernel ===========================================
#define WSTAGE_B 98304
__global__ void __launch_bounds__(256)
gemm_mma_wide(const __nv_bfloat16* __restrict__ Ah, const __nv_bfloat16* __restrict__ Al, size_t sAz,
              const __nv_bfloat16* __restrict__ Bh, const __nv_bfloat16* __restrict__ Bl, size_t sBz,
              float* __restrict__ C, int ldc, size_t sCz,
              int K, const float* __restrict__ mask, float scale)
{
    extern __shared__ char smem[];
    const int z = blockIdx.z;
    const int m0 = blockIdx.y * 128, n0 = blockIdx.x * 256;
    Ah += (size_t)z * sAz;  Al += (size_t)z * sAz;
    Bh += (size_t)z * sBz;  Bl += (size_t)z * sBz;
    C  += (size_t)z * sCz;

    const int tid = threadIdx.x;
    const int warp = tid >> 5, lane = tid & 31;
    const int wm = (warp >> 2) * 64, wn = (warp & 3) * 64;

    const __nv_bfloat16* gsrc[6];
    uint32_t swb[6];
#pragma unroll
    for (int j = 0; j < 6; j++) {
        const int h = tid + j * 256;
        int t, r;
        if (h < 256)       { t = 0; r = h >> 1; }
        else if (h < 512)  { t = 1; r = (h - 256) >> 1; }
        else if (h < 1024) { t = 2; r = (h - 512) >> 1; }
        else               { t = 3; r = (h - 1024) >> 1; }
        const int half = h & 1;
        const uint32_t tbase = (t == 0) ? 0u : (t == 1) ? 16384u : (t == 2) ? 32768u : 65536u;
        swb[j] = tbase + sw128((uint32_t)r * 128u + half * 64u);
        const __nv_bfloat16* base =
            (t == 0) ? Ah + (size_t)(m0 + r) * K :
            (t == 1) ? Al + (size_t)(m0 + r) * K :
            (t == 2) ? Bh + (size_t)(n0 + r) * K :
                       Bl + (size_t)(n0 + r) * K;
        gsrc[j] = base + half * 32;
    }
    const uint32_t smem32 = smem_u32(smem);
    const int qrow = lane & 15, qsel = lane >> 4;

    float acc[4][8][4];
#pragma unroll
    for (int i = 0; i < 4; i++)
#pragma unroll
        for (int j = 0; j < 8; j++)
#pragma unroll
            for (int r = 0; r < 4; r++) acc[i][j][r] = 0.f;

    const int nch = K >> 6;
    {
#pragma unroll
        for (int j = 0; j < 6; j++)
#pragma unroll
            for (int i = 0; i < 4; i++)
                cpa16(smem32 + (swb[j] ^ (i * 16u)), gsrc[j] + i * 8);
        cpa_commit();
    }
    for (int c = 0; c < nch; c++) {
        if (c + 1 < nch) {
            const int ke = (c + 1) * 64;
            const uint32_t sb = smem32 + ((c + 1) & 1) * WSTAGE_B;
#pragma unroll
            for (int j = 0; j < 6; j++)
#pragma unroll
                for (int i = 0; i < 4; i++)
                    cpa16(sb + (swb[j] ^ (i * 16u)), gsrc[j] + ke + i * 8);
            cpa_commit();
            cpa_wait1();
        } else {
            cpa_wait0();
        }
        __syncthreads();

        const uint32_t st = smem32 + (c & 1) * WSTAGE_B;
        const uint32_t Ah32 = st, Al32 = st + 16384, Bh32 = st + 32768, Bl32 = st + 65536;
#pragma unroll
        for (int ks = 0; ks < 4; ks++) {
            const uint32_t kofs = ks * 32u + qsel * 16u;
            uint32_t ah[4][4];
#pragma unroll
            for (int mf = 0; mf < 4; mf++) {
                int row = wm + mf * 16 + qrow;
                ldm_x4(ah[mf], Ah32 + sw128((uint32_t)row * 128u + kofs));
            }
            uint32_t bh[8][2], bl[8][2];
#pragma unroll
            for (int nh = 0; nh < 4; nh++) {
                int row = wn + nh * 16 + qrow;
                uint32_t t[4];
                ldm_x4(t, Bh32 + sw128((uint32_t)row * 128u + kofs));
                bh[nh * 2 + 0][0] = t[0]; bh[nh * 2 + 0][1] = t[2];
                bh[nh * 2 + 1][0] = t[1]; bh[nh * 2 + 1][1] = t[3];
                ldm_x4(t, Bl32 + sw128((uint32_t)row * 128u + kofs));
                bl[nh * 2 + 0][0] = t[0]; bl[nh * 2 + 0][1] = t[2];
                bl[nh * 2 + 1][0] = t[1]; bl[nh * 2 + 1][1] = t[3];
            }
#pragma unroll
            for (int mf = 0; mf < 4; mf++)
#pragma unroll
                for (int nf = 0; nf < 8; nf++)
                    mma_bf16(acc[mf][nf], ah[mf], bh[nf]);
#pragma unroll
            for (int mf = 0; mf < 4; mf++)
#pragma unroll
                for (int nf = 0; nf < 8; nf++)
                    mma_bf16(acc[mf][nf], ah[mf], bl[nf]);
            uint32_t al[4][4];
#pragma unroll
            for (int mf = 0; mf < 4; mf++) {
                int row = wm + mf * 16 + qrow;
                ldm_x4(al[mf], Al32 + sw128((uint32_t)row * 128u + kofs));
            }
#pragma unroll
            for (int mf = 0; mf < 4; mf++)
#pragma unroll
                for (int nf = 0; nf < 8; nf++)
                    mma_bf16(acc[mf][nf], al[mf], bh[nf]);
        }
        __syncthreads();
    }

    const int r0 = lane >> 2, c0 = (lane & 3) * 2;
#pragma unroll
    for (int mf = 0; mf < 4; mf++) {
        const int mA = m0 + wm + mf * 16 + r0;
        const float* mrow = mask + (size_t)(mA >> 4) * MAXT;
#pragma unroll
        for (int nf = 0; nf < 8; nf++) {
            const int n = n0 + wn + nf * 8 + c0;
            float v0 = acc[mf][nf][0] * scale + mrow[n];
            float v1 = acc[mf][nf][1] * scale + mrow[n + 1];
            float v2 = acc[mf][nf][2] * scale + mrow[n];
            float v3 = acc[mf][nf][3] * scale + mrow[n + 1];
            *(float2*)&C[(size_t)mA * ldc + n]       = make_float2(v0, v1);
            *(float2*)&C[(size_t)(mA + 8) * ldc + n] = make_float2(v2, v3);
        }
    }
}

// ================= merged weight/x conversion ================================
#define C4_X    131072
#define C4_QD   (C4_X + 393216)
#define C4_QU   (C4_QD + 589824)
#define C4_KVD  (C4_QU + 327680)
#define C4_OUT  (C4_KVD + 1048576)
#define C4_WKVU (C4_OUT + 524288)
#define KVD_SRC4 294912
__global__ void conv_all(const float4* __restrict__ x, const float4* __restrict__ wqd,
                         const float4* __restrict__ wqu, const float4* __restrict__ wkvd,
                         const float4* __restrict__ wout, const float4* __restrict__ wkvu) {
    const int i = blockIdx.x * 256 + threadIdx.x;
    if (i < C4_X) {
        split4(x[i], g_xh, g_xl, i);
    } else if (i < C4_QD) {
        const int j = i - C4_X;
        split4(wqd[j], g_wqdh, g_wqdl, j);
    } else if (i < C4_QU) {
        const int j = i - C4_QD;
        split4(wqu[j], g_wquh, g_wqul, j);
    } else if (i < C4_KVD) {
        const int j = i - C4_QU;
        float4 v = (j < KVD_SRC4) ? wkvd[j] : make_float4(0.f, 0.f, 0.f, 0.f);
        split4(v, g_wkvdh, g_wkvdl, j);
    } else if (i < C4_OUT) {
        const int j = i - C4_KVD;
        split4(wout[j], g_wouth, g_woutl, j);
    } else if (i < C4_WKVU) {
        const int j = i - C4_OUT;
        split4(wkvu[j], g_wvh, g_wvl, j);
    }
}

// transpose nr part of w_kvu: out[h][n][d] = w_kvu[(h*256+d)*512 + n]
__global__ void build_wnrt(const float* __restrict__ wkvu) {
    __shared__ float tile[32][33];
    const int h = blockIdx.z;
    const int n0 = blockIdx.x * 32, d0 = blockIdx.y * 32;
    const int tx = threadIdx.x, ty = threadIdx.y;
#pragma unroll
    for (int i = 0; i < 4; i++) {
        const int d = d0 + ty + i * 8;
        tile[ty + i * 8][tx] = wkvu[(size_t)(h * 256 + d) * KVR + n0 + tx];
    }
    __syncthreads();
#pragma unroll
    for (int i = 0; i < 4; i++) {
        const int n = n0 + ty + i * 8;
        const float v = tile[tx][ty + i * 8];
        const size_t o = (size_t)h * KVR * DNR + (size_t)n * DNR + d0 + tx;
        split_write(v, g_wnrth, g_wnrtl, o);
    }
}

// ================= small conversions ========================================
__global__ void conv_split4(const float4* __restrict__ src, __nv_bfloat16* h, __nv_bfloat16* l, int n4) {
    const int i = blockIdx.x * 256 + threadIdx.x;
    if (i < n4) split4(src[i], h, l, i);
}
__global__ void build_kvcat4(const float* __restrict__ kvc, const float* __restrict__ krc) {
    const size_t i4 = (size_t)blockIdx.x * 256 + threadIdx.x;
    const size_t idx = i4 * 4;
    const int c = (int)(idx % CATD);
    const size_t bt = idx / CATD;
    const int t = (int)(bt % MAXT);
    const int b = (int)(bt / MAXT);
    float4 v;
    if (t >= START_P)
        v = *(const float4*)&g_kv[(size_t)((b << 5) + (t - START_P)) * CATD + c];
    else if (c < KVR)
        v = *(const float4*)&kvc[((size_t)b * MAXT + t) * KVR + c];
    else
        v = *(const float4*)&krc[((size_t)b * MAXT + t) * DR + (c - KVR)];
    split4(v, g_kc_h, g_kc_l, i4);
}
__global__ void build_kvt(const float* __restrict__ kvc) {
    __shared__ float tile[32][33];
    const int b = blockIdx.z;
    const int t0 = blockIdx.x * 32, n0 = blockIdx.y * 32;
    const int tx = threadIdx.x, ty = threadIdx.y;
#pragma unroll
    for (int i = 0; i < 4; i++) {
        const int t = t0 + ty + i * 8;
        float v;
        if (t >= START_P)
            v = g_kv[(size_t)((b << 5) + (t - START_P)) * CATD + n0 + tx];
        else
            v = kvc[((size_t)b * MAXT + t) * KVR + n0 + tx];
        tile[ty + i * 8][tx] = v;
    }
    __syncthreads();
#pragma unroll
    for (int i = 0; i < 4; i++) {
        const int n = n0 + ty + i * 8;
        const float x = tile[tx][ty + i * 8];
        const size_t o = ((size_t)(b * KVR + n)) * MAXT + t0 + tx;
        split_write(x, g_kt_h, g_kt_l, o);
    }
}

// ================= RMSNorm ===================================================
__global__ void rms_kernel(const float* __restrict__ w) {
    const int row = blockIdx.x;
    const float* xr = g_qd + row * QR;
    __shared__ float red[256];
    const int tid = threadIdx.x;
    float v[3], s = 0.f;
#pragma unroll
    for (int i = 0; i < 3; i++) { v[i] = xr[tid + i * 256]; s += v[i] * v[i]; }
    red[tid] = s; __syncthreads();
    for (int o = 128; o > 0; o >>= 1) {
        if (tid < o) red[tid] += red[tid + o];
        __syncthreads();
    }
    const float r = rsqrtf(red[0] / (float)QR + 1.1920929e-07f);
    __syncthreads();
#pragma unroll
    for (int i = 0; i < 3; i++) {
        const float y = v[i] * r * w[tid + i * 256];
        split_write(y, g_qnh, g_qnl, (size_t)row * QR + tid + i * 256);
    }
}

// ================= rope: q -> qcat tail split; k in place ====================
__global__ void rope_kernel(const float* __restrict__ fc, const float* __restrict__ fs) {
    const int idx = blockIdx.x * 256 + threadIdx.x;
    const int NQ = BATCH * SEQ_L * NH * (DR / 2);
    if (idx < NQ) {
        const int j = idx & 31, h = (idx >> 5) & 15, l = (idx >> 9) & 31, b = idx >> 14;
        const float* src = &g_q[(size_t)(b * SEQ_L + l) * (NH * QKD) + h * QKD + DNR + 2 * j];
        const float xr = src[0], xi = src[1];
        const float c = fc[l * 32 + j], s = fs[l * 32 + j];
        const size_t o = (size_t)(b * ROWSPB + l * NH + h) * CATD + KVR + 2 * j;
        split_write(xr * c - xi * s, g_qc_h, g_qc_l, o);
        split_write(xr * s + xi * c, g_qc_h, g_qc_l, o + 1);
    } else if (idx < NQ + BATCH * SEQ_L * (DR / 2)) {
        const int k = idx - NQ;
        const int j = k & 31, l = (k >> 5) & 31, b = k >> 10;
        float* p = &g_kv[(size_t)(b * SEQ_L + l) * CATD + KVR + 2 * j];
        const float xr = p[0], xi = p[1];
        const float c = fc[l * 32 + j], s = fs[l * 32 + j];
        p[0] = xr * c - xi * s;
        p[1] = xr * s + xi * c;
    }
}

// ================= softmax -> bf16 hi/lo P ===================================
__global__ void softmax_split() {
    const int row = blockIdx.x;
    float* s = g_S + (size_t)row * MAXT;
    __shared__ float red[256];
    const int tid = threadIdx.x;
    float4 v[4];
    float mx = -INFINITY;
#pragma unroll
    for (int g = 0; g < 4; g++) {
        v[g] = *(float4*)&s[tid * 4 + g * 1024];
        mx = fmaxf(mx, fmaxf(fmaxf(v[g].x, v[g].y), fmaxf(v[g].z, v[g].w)));
    }
    red[tid] = mx; __syncthreads();
    for (int o = 128; o > 0; o >>= 1) {
        if (tid < o) red[tid] = fmaxf(red[tid], red[tid + o]);
        __syncthreads();
    }
    mx = red[0]; __syncthreads();
    float sum = 0.f;
#pragma unroll
    for (int g = 0; g < 4; g++) {
        v[g].x = __expf(v[g].x - mx); v[g].y = __expf(v[g].y - mx);
        v[g].z = __expf(v[g].z - mx); v[g].w = __expf(v[g].w - mx);
        sum += v[g].x + v[g].y + v[g].z + v[g].w;
    }
    red[tid] = sum; __syncthreads();
    for (int o = 128; o > 0; o >>= 1) {
        if (tid < o) red[tid] += red[tid + o];
        __syncthreads();
    }
    const float inv = 1.f / red[0];
#pragma unroll
    for (int g = 0; g < 4; g++) {
        float4 p = make_float4(v[g].x * inv, v[g].y * inv, v[g].z * inv, v[g].w * inv);
        split4(p, g_p_h, g_p_l, ((size_t)row * MAXT + tid * 4 + g * 1024) >> 2);
    }
}

// ============================== launcher =====================================
extern "C" void kernel_launch(void* const* d_in, const int* in_sizes, int n_in,
                              void* d_out, int out_size) {
    const float* x      = (const float*)d_in[0];
    const float* fc     = (const float*)d_in[2];
    const float* fs     = (const float*)d_in[3];
    const float* mask   = (const float*)d_in[4];
    const float* kvc    = (const float*)d_in[5];
    const float* krc    = (const float*)d_in[6];
    const float* w_kvd  = (const float*)d_in[7];
    const float* w_qd   = (const float*)d_in[8];
    const float* rms_w  = (const float*)d_in[9];
    const float* w_qu   = (const float*)d_in[10];
    const float* w_kvu  = (const float*)d_in[11];
    const float* w_out  = (const float*)d_in[12];
    float* out = (float*)d_out;

    float *p_qd, *p_q, *p_kv, *p_S;
    cudaGetSymbolAddress((void**)&p_qd, g_qd);
    cudaGetSymbolAddress((void**)&p_q,  g_q);
    cudaGetSymbolAddress((void**)&p_kv, g_kv);
    cudaGetSymbolAddress((void**)&p_S, g_S);

    __nv_bfloat16 *xh, *xl, *qnh, *qnl, *qh, *ql, *o2h, *o2l, *Oh, *Ol;
    __nv_bfloat16 *wqdh, *wqdl, *wquh, *wqul, *wkvdh, *wkvdl, *wouth, *woutl;
    __nv_bfloat16 *qch, *qcl, *kch, *kcl, *kth, *ktl, *ph, *pl;
    cudaGetSymbolAddress((void**)&xh, g_xh);     cudaGetSymbolAddress((void**)&xl, g_xl);
    cudaGetSymbolAddress((void**)&qnh, g_qnh);   cudaGetSymbolAddress((void**)&qnl, g_qnl);
    cudaGetSymbolAddress((void**)&qh, g_qh);     cudaGetSymbolAddress((void**)&ql, g_ql);
    cudaGetSymbolAddress((void**)&o2h, g_o2h);   cudaGetSymbolAddress((void**)&o2l, g_o2l);
    cudaGetSymbolAddress((void**)&Oh, g_Oh);     cudaGetSymbolAddress((void**)&Ol, g_Ol);
    cudaGetSymbolAddress((void**)&wqdh, g_wqdh); cudaGetSymbolAddress((void**)&wqdl, g_wqdl);
    cudaGetSymbolAddress((void**)&wquh, g_wquh); cudaGetSymbolAddress((void**)&wqul, g_wqul);
    cudaGetSymbolAddress((void**)&wkvdh, g_wkvdh); cudaGetSymbolAddress((void**)&wkvdl, g_wkvdl);
    cudaGetSymbolAddress((void**)&wouth, g_wouth); cudaGetSymbolAddress((void**)&woutl, g_woutl);
    cudaGetSymbolAddress((void**)&qch, g_qc_h);  cudaGetSymbolAddress((void**)&qcl, g_qc_l);
    cudaGetSymbolAddress((void**)&kch, g_kc_h);  cudaGetSymbolAddress((void**)&kcl, g_kc_l);
    cudaGetSymbolAddress((void**)&kth, g_kt_h);  cudaGetSymbolAddress((void**)&ktl, g_kt_l);
    cudaGetSymbolAddress((void**)&ph, g_p_h);    cudaGetSymbolAddress((void**)&pl, g_p_l);

    cudaFuncSetAttribute(gemm_mma_osplit, cudaFuncAttributeMaxDynamicSharedMemorySize, 2 * STAGE_B);
    cudaFuncSetAttribute(gemm_mma_sk, cudaFuncAttributeMaxDynamicSharedMemorySize, 2 * STAGE_B);
    cudaFuncSetAttribute(qabs_mma, cudaFuncAttributeMaxDynamicSharedMemorySize, 2 * STAGE_B);
    cudaFuncSetAttribute(oup_mma, cudaFuncAttributeMaxDynamicSharedMemorySize, 2 * STAGE_B);
    cudaFuncSetAttribute(gemm_mma_wide, cudaFuncAttributeMaxDynamicSharedMemorySize, 2 * WSTAGE_B);
    const int DSM = 2 * STAGE_B;
    const int WDSM = 2 * WSTAGE_B;

    // ---- conversions ----
    conv_all<<<C4_WKVU / 256, 256>>>((const float4*)x, (const float4*)w_qd, (const float4*)w_qu,
                                     (const float4*)w_kvd, (const float4*)w_out, (const float4*)w_kvu);
    build_wnrt<<<dim3(KVR / 32, DNR / 32, NH), dim3(32, 8)>>>(w_kvu);

    // ---- zero split-K outputs ----
    cudaMemsetAsync(p_qd, 0, (size_t)MBL * QR * 4);
    cudaMemsetAsync(p_q, 0, (size_t)MBL * NH * QKD * 4);
    cudaMemsetAsync(p_kv, 0, (size_t)MBL * CATD * 4);

    // ---- q path ----
    gemm_mma_sk<<<dim3(QR / 128, MBL / 128, 8), 256, DSM>>>(xh, xl, wqdh, wqdl,
        p_qd, QR, DIM, DIM / 8, QR);
    rms_kernel<<<MBL, 256>>>(rms_w);
    gemm_mma_sk<<<dim3(NH * QKD / 128, MBL / 128, 2), 256, DSM>>>(qnh, qnl, wquh, wqul,
        p_q, NH * QKD, QR, QR / 2, NH * QKD);
    conv_split4<<<(MBL * NH * QKD / 4 + 255) / 256, 256>>>((const float4*)p_q, qh, ql, MBL * NH * QKD / 4);

    // ---- kv path ----
    gemm_mma_sk<<<dim3(KVD_PAD / 128, MBL / 128, 8), 256, DSM>>>(xh, xl, wkvdh, wkvdl,
        p_kv, CATD, DIM, DIM / 8, CATD);

    rope_kernel<<<(BATCH * SEQ_L * NH * 32 + BATCH * SEQ_L * 32 + 255) / 256, 256>>>(fc, fs);
    qabs_mma<<<dim3(KVR / 128, MBL / 128, NH), 256, DSM>>>();

    build_kvcat4<<<(int)(((size_t)BATCH * MAXT * CATD / 4) / 256), 256>>>(kvc, krc);
    build_kvt<<<dim3(MAXT / 32, KVR / 32, BATCH), dim3(32, 8)>>>(kvc);

    // ---- attention ----
    gemm_mma_wide<<<dim3(MAXT / 256, ROWSPB / 128, BATCH), 256, WDSM>>>(
        qch, qcl, (size_t)ROWSPB * CATD, kch, kcl, (size_t)MAXT * CATD,
        p_S, MAXT, (size_t)ROWSPB * MAXT, CATD, mask, SCALE_F);
    softmax_split<<<BATCH * ROWSPB, 256>>>();
    gemm_mma_osplit<<<dim3(KVR / 128, ROWSPB / 128, BATCH), 256, DSM>>>(
        ph, pl, (size_t)ROWSPB * MAXT, kth, ktl, (size_t)KVR * MAXT,
        Oh, Ol, KVR, (size_t)ROWSPB * KVR, MAXT);

    // ---- output path ----
    oup_mma<<<dim3(1, MBL / 128, NH), 256, DSM>>>();
    cudaMemsetAsync(out, 0, (size_t)MBL * DIM * 4);
    gemm_mma_sk<<<dim3(DIM / 128, MBL / 128, 8), 256, DSM>>>(o2h, o2l, wouth, woutl,
        out, DIM, NH * DV, NH * DV / 8, DIM);
}

// round 7
// speedup vs baseline: 3.1554x; 1.0229x over previous
#include <cuda_runtime.h>
#include <cuda_bf16.h>
#include <math.h>
#include <stdint.h>

// ---------------- problem constants -----------------------------------------
#define BATCH   8
#define SEQ_L   32
#define DIM     2048
#define KVR     512
#define QR      768
#define NH      16
#define DNR     128
#define DR      64
#define DV      128
#define MAXT    4096
#define START_P 4064
#define QKD     192
#define CATD    576
#define MBL     256
#define ROWSPB  512
#define SCALE_F 0.07216878364870323f
#define KVD_PAD 640

// ---------------- fp32 scratch ----------------------------------------------
__device__ __align__(16) float g_qd  [MBL * QR];
__device__ __align__(16) float g_q   [MBL * NH * QKD];
__device__ __align__(16) float g_kv  [MBL * CATD];
__device__ __align__(16) float g_S   [(size_t)BATCH * ROWSPB * MAXT];
// ---------------- bf16 hi/lo operands ----------------------------------------
__device__ __align__(16) __nv_bfloat16 g_qc_h[BATCH * ROWSPB * CATD];
__device__ __align__(16) __nv_bfloat16 g_qc_l[BATCH * ROWSPB * CATD];
__device__ __align__(16) __nv_bfloat16 g_kc_h[(size_t)BATCH * MAXT * CATD];
__device__ __align__(16) __nv_bfloat16 g_kc_l[(size_t)BATCH * MAXT * CATD];
__device__ __align__(16) __nv_bfloat16 g_kt_h[(size_t)BATCH * KVR * MAXT];
__device__ __align__(16) __nv_bfloat16 g_kt_l[(size_t)BATCH * KVR * MAXT];
__device__ __align__(16) __nv_bfloat16 g_p_h [(size_t)BATCH * ROWSPB * MAXT];
__device__ __align__(16) __nv_bfloat16 g_p_l [(size_t)BATCH * ROWSPB * MAXT];
__device__ __align__(16) __nv_bfloat16 g_xh  [MBL * DIM];
__device__ __align__(16) __nv_bfloat16 g_xl  [MBL * DIM];
__device__ __align__(16) __nv_bfloat16 g_qnh [MBL * QR];
__device__ __align__(16) __nv_bfloat16 g_qnl [MBL * QR];
__device__ __align__(16) __nv_bfloat16 g_qh  [MBL * NH * QKD];
__device__ __align__(16) __nv_bfloat16 g_ql  [MBL * NH * QKD];
__device__ __align__(16) __nv_bfloat16 g_Oh  [BATCH * ROWSPB * KVR];
__device__ __align__(16) __nv_bfloat16 g_Ol  [BATCH * ROWSPB * KVR];
__device__ __align__(16) __nv_bfloat16 g_o2h [MBL * NH * DV];
__device__ __align__(16) __nv_bfloat16 g_o2l [MBL * NH * DV];
__device__ __align__(16) __nv_bfloat16 g_wqdh[QR * DIM];
__device__ __align__(16) __nv_bfloat16 g_wqdl[QR * DIM];
__device__ __align__(16) __nv_bfloat16 g_wquh[NH * QKD * QR];
__device__ __align__(16) __nv_bfloat16 g_wqul[NH * QKD * QR];
__device__ __align__(16) __nv_bfloat16 g_wkvdh[KVD_PAD * DIM];
__device__ __align__(16) __nv_bfloat16 g_wkvdl[KVD_PAD * DIM];
__device__ __align__(16) __nv_bfloat16 g_wouth[DIM * NH * DV];
__device__ __align__(16) __nv_bfloat16 g_woutl[DIM * NH * DV];
__device__ __align__(16) __nv_bfloat16 g_wvh [NH * 256 * KVR];
__device__ __align__(16) __nv_bfloat16 g_wvl [NH * 256 * KVR];
__device__ __align__(16) __nv_bfloat16 g_wnrth[NH * KVR * DNR];
__device__ __align__(16) __nv_bfloat16 g_wnrtl[NH * KVR * DNR];

// ================= helpers ===================================================
__device__ __forceinline__ uint32_t smem_u32(const void* p) {
    uint32_t a;
    asm("{ .reg .u64 t; cvta.to.shared.u64 t, %1; cvt.u32.u64 %0, t; }" : "=r"(a) : "l"(p));
    return a;
}
__device__ __forceinline__ uint32_t sw128(uint32_t o) { return o ^ ((o >> 3) & 0x70); }
__device__ __forceinline__ void cpa16(uint32_t saddr, const void* g) {
    asm volatile("cp.async.cg.shared.global [%0], [%1], 16;" :: "r"(saddr), "l"(g));
}
__device__ __forceinline__ void cpa_commit() { asm volatile("cp.async.commit_group;" ::: "memory"); }
__device__ __forceinline__ void cpa_wait2()  { asm volatile("cp.async.wait_group 2;" ::: "memory"); }
__device__ __forceinline__ void cpa_wait1()  { asm volatile("cp.async.wait_group 1;" ::: "memory"); }
__device__ __forceinline__ void cpa_wait0()  { asm volatile("cp.async.wait_group 0;" ::: "memory"); }
__device__ __forceinline__ void ldm_x4(uint32_t* r, uint32_t addr) {
    asm volatile("ldmatrix.sync.aligned.m8n8.x4.shared.b16 {%0,%1,%2,%3}, [%4];"
                 : "=r"(r[0]), "=r"(r[1]), "=r"(r[2]), "=r"(r[3]) : "r"(addr));
}
__device__ __forceinline__ void mma_bf16(float* c, const uint32_t* a, const uint32_t* b) {
    asm volatile("mma.sync.aligned.m16n8k16.row.col.f32.bf16.bf16.f32 "
                 "{%0,%1,%2,%3}, {%4,%5,%6,%7}, {%8,%9}, {%0,%1,%2,%3};"
                 : "+f"(c[0]), "+f"(c[1]), "+f"(c[2]), "+f"(c[3])
                 : "r"(a[0]), "r"(a[1]), "r"(a[2]), "r"(a[3]), "r"(b[0]), "r"(b[1]));
}
__device__ __forceinline__ void split_write(float x, __nv_bfloat16* h, __nv_bfloat16* l, size_t i) {
    __nv_bfloat16 hv = __float2bfloat16(x);
    h[i] = hv;
    l[i] = __float2bfloat16(x - __bfloat162float(hv));
}
__device__ __forceinline__ void split4(float4 v, __nv_bfloat16* h, __nv_bfloat16* l, size_t i4) {
    __nv_bfloat16 h0 = __float2bfloat16(v.x), h1 = __float2bfloat16(v.y);
    __nv_bfloat16 h2 = __float2bfloat16(v.z), h3 = __float2bfloat16(v.w);
    __nv_bfloat16 l0 = __float2bfloat16(v.x - __bfloat162float(h0));
    __nv_bfloat16 l1 = __float2bfloat16(v.y - __bfloat162float(h1));
    __nv_bfloat16 l2 = __float2bfloat16(v.z - __bfloat162float(h2));
    __nv_bfloat16 l3 = __float2bfloat16(v.w - __bfloat162float(h3));
    __nv_bfloat162 hh0 = {h0, h1}, hh1 = {h2, h3};
    __nv_bfloat162 ll0 = {l0, l1}, ll1 = {l2, l3};
    uint2 hw = make_uint2(*(uint32_t*)&hh0, *(uint32_t*)&hh1);
    uint2 lw = make_uint2(*(uint32_t*)&ll0, *(uint32_t*)&ll1);
    *(uint2*)&h[i4 * 4] = hw;
    *(uint2*)&l[i4 * 4] = lw;
}

#define STAGE_B 65536

// ======== 3-stage pipelined mainloop (128x128, 4x16KB tiles / stage) =========
#define PREFETCH_CHUNK(SB, KE)                                                       \
    _Pragma("unroll") for (int t = 0; t < 4; t++)                                    \
        _Pragma("unroll") for (int i = 0; i < 4; i++)                                \
            cpa16((SB) + soff[t][i], srcs[t] + (KE) + i * 8);                        \
    cpa_commit();

#define MAINLOOP_128(NCH)                                                            \
    {                                                                                \
        const int pre = ((NCH) < 2) ? (NCH) : 2;                                     \
        for (int s = 0; s < pre; s++) {                                              \
            const int ke = s * 64 + lhalf * 32;                                      \
            const uint32_t sb = smem32 + (uint32_t)s * STAGE_B;                      \
            PREFETCH_CHUNK(sb, ke)                                                   \
        }                                                                            \
    }                                                                                \
    for (int c = 0; c < (NCH); c++) {                                                \
        if (c + 2 < (NCH)) {                                                         \
            const int ke = (c + 2) * 64 + lhalf * 32;                                \
            const uint32_t sb = smem32 + (uint32_t)((c + 2) % 3) * STAGE_B;          \
            PREFETCH_CHUNK(sb, ke)                                                   \
            cpa_wait2();                                                             \
        } else if (c + 1 < (NCH)) {                                                  \
            cpa_wait1();                                                             \
        } else {                                                                     \
            cpa_wait0();                                                             \
        }                                                                            \
        __syncthreads();                                                             \
        const uint32_t st = smem32 + (uint32_t)(c % 3) * STAGE_B;                    \
        const uint32_t Ah32 = st, Al32 = st + 16384, Bh32 = st + 32768, Bl32 = st + 49152; \
        _Pragma("unroll") for (int ks = 0; ks < 4; ks++) {                           \
            const uint32_t kofs = ks * 32u + qsel * 16u;                             \
            uint32_t ah[4][4];                                                       \
            _Pragma("unroll") for (int mf = 0; mf < 4; mf++) {                       \
                int row = wm + mf * 16 + qrow;                                       \
                ldm_x4(ah[mf], Ah32 + sw128((uint32_t)row * 128u + kofs));           \
            }                                                                        \
            uint32_t bh[4][2], bl[4][2];                                             \
            _Pragma("unroll") for (int nh = 0; nh < 2; nh++) {                       \
                int row = wn + nh * 16 + qrow;                                       \
                uint32_t t[4];                                                       \
                ldm_x4(t, Bh32 + sw128((uint32_t)row * 128u + kofs));                \
                bh[nh * 2 + 0][0] = t[0]; bh[nh * 2 + 0][1] = t[2];                  \
                bh[nh * 2 + 1][0] = t[1]; bh[nh * 2 + 1][1] = t[3];                  \
                ldm_x4(t, Bl32 + sw128((uint32_t)row * 128u + kofs));                \
                bl[nh * 2 + 0][0] = t[0]; bl[nh * 2 + 0][1] = t[2];                  \
                bl[nh * 2 + 1][0] = t[1]; bl[nh * 2 + 1][1] = t[3];                  \
            }                                                                        \
            _Pragma("unroll") for (int mf = 0; mf < 4; mf++)                         \
                _Pragma("unroll") for (int nf = 0; nf < 4; nf++)                     \
                    mma_bf16(acc[mf][nf], ah[mf], bh[nf]);                           \
            _Pragma("unroll") for (int mf = 0; mf < 4; mf++)                         \
                _Pragma("unroll") for (int nf = 0; nf < 4; nf++)                     \
                    mma_bf16(acc[mf][nf], ah[mf], bl[nf]);                           \
            uint32_t al[4][4];                                                       \
            _Pragma("unroll") for (int mf = 0; mf < 4; mf++) {                       \
                int row = wm + mf * 16 + qrow;                                       \
                ldm_x4(al[mf], Al32 + sw128((uint32_t)row * 128u + kofs));           \
            }                                                                        \
            _Pragma("unroll") for (int mf = 0; mf < 4; mf++)                         \
                _Pragma("unroll") for (int nf = 0; nf < 4; nf++)                     \
                    mma_bf16(acc[mf][nf], al[mf], bh[nf]);                           \
        }                                                                            \
        __syncthreads();                                                             \
    }

#define DECL_COMMON                                                                  \
    const int tid = threadIdx.x;                                                     \
    const int warp = tid >> 5, lane = tid & 31;                                      \
    const int wm = (warp >> 2) * 64, wn = (warp & 3) * 32;                           \
    const int lrow = tid >> 1, lhalf = tid & 1;                                      \
    const uint32_t smem32 = smem_u32(smem);                                          \
    const int qrow = lane & 15, qsel = lane >> 4;                                    \
    float acc[4][4][4];                                                              \
    _Pragma("unroll") for (int i = 0; i < 4; i++)                                    \
        _Pragma("unroll") for (int j = 0; j < 4; j++)                                \
            _Pragma("unroll") for (int r = 0; r < 4; r++) acc[i][j][r] = 0.f;        \
    uint32_t soff[4][4];                                                             \
    _Pragma("unroll") for (int t = 0; t < 4; t++)                                    \
        _Pragma("unroll") for (int i = 0; i < 4; i++)                                \
            soff[t][i] = (uint32_t)t * 16384u + sw128((uint32_t)lrow * 128u + lhalf * 64u + i * 16u);

// ====== ogemm: O = P*KV^T, epilogue -> split bf16 ============================
__global__ void __launch_bounds__(256)
gemm_mma_osplit(const __nv_bfloat16* __restrict__ Ah, const __nv_bfloat16* __restrict__ Al, size_t sAz,
                const __nv_bfloat16* __restrict__ Bh, const __nv_bfloat16* __restrict__ Bl, size_t sBz,
                __nv_bfloat16* __restrict__ Ch, __nv_bfloat16* __restrict__ Cl, int ldc, size_t sCz,
                int K)
{
    extern __shared__ char smem[];
    const int z = blockIdx.z;
    const int m0 = blockIdx.y * 128, n0 = blockIdx.x * 128;
    Ah += (size_t)z * sAz;  Al += (size_t)z * sAz;
    Bh += (size_t)z * sBz;  Bl += (size_t)z * sBz;
    Ch += (size_t)z * sCz;  Cl += (size_t)z * sCz;
    DECL_COMMON
    const __nv_bfloat16* srcs[4];
    srcs[0] = Ah + (size_t)(m0 + lrow) * K;
    srcs[1] = Al + (size_t)(m0 + lrow) * K;
    srcs[2] = Bh + (size_t)(n0 + lrow) * K;
    srcs[3] = Bl + (size_t)(n0 + lrow) * K;
    const int nch = K >> 6;
    MAINLOOP_128(nch)
    const int r0 = lane >> 2, c0 = (lane & 3) * 2;
#pragma unroll
    for (int mf = 0; mf < 4; mf++) {
        const int mA = m0 + wm + mf * 16 + r0;
#pragma unroll
        for (int nf = 0; nf < 4; nf++) {
            const int n = n0 + wn + nf * 8 + c0;
            const size_t i0 = (size_t)mA * ldc + n;
            const size_t i1 = (size_t)(mA + 8) * ldc + n;
            split_write(acc[mf][nf][0], Ch, Cl, i0);
            split_write(acc[mf][nf][1], Ch, Cl, i0 + 1);
            split_write(acc[mf][nf][2], Ch, Cl, i1);
            split_write(acc[mf][nf][3], Ch, Cl, i1 + 1);
        }
    }
}

// ====== qabs: per-head q_nrope @ w_nr^T -> split bf16 into qcat ==============
__global__ void __launch_bounds__(256)
qabs_mma()
{
    extern __shared__ char smem[];
    const int h = blockIdx.z;
    const int m0 = blockIdx.y * 128, n0 = blockIdx.x * 128;
    DECL_COMMON
    const __nv_bfloat16* srcs[4];
    srcs[0] = g_qh + (size_t)(m0 + lrow) * (NH * QKD) + h * QKD;
    srcs[1] = g_ql + (size_t)(m0 + lrow) * (NH * QKD) + h * QKD;
    srcs[2] = g_wnrth + (size_t)h * KVR * DNR + (size_t)(n0 + lrow) * DNR;
    srcs[3] = g_wnrtl + (size_t)h * KVR * DNR + (size_t)(n0 + lrow) * DNR;
    MAINLOOP_128(2)
    const int r0 = lane >> 2, c0 = (lane & 3) * 2;
#pragma unroll
    for (int mf = 0; mf < 4; mf++) {
        const int mA = m0 + wm + mf * 16 + r0;
        const int rowA = ((mA >> 5) * ROWSPB) + (mA & 31) * NH + h;
        const int rowB = (((mA + 8) >> 5) * ROWSPB) + ((mA + 8) & 31) * NH + h;
#pragma unroll
        for (int nf = 0; nf < 4; nf++) {
            const int n = n0 + wn + nf * 8 + c0;
            const size_t i0 = (size_t)rowA * CATD + n;
            const size_t i1 = (size_t)rowB * CATD + n;
            split_write(acc[mf][nf][0], g_qc_h, g_qc_l, i0);
            split_write(acc[mf][nf][1], g_qc_h, g_qc_l, i0 + 1);
            split_write(acc[mf][nf][2], g_qc_h, g_qc_l, i1);
            split_write(acc[mf][nf][3], g_qc_h, g_qc_l, i1 + 1);
        }
    }
}

// ====== oup: per-head O @ w_v^T -> split bf16 into o2 ========================
__global__ void __launch_bounds__(256)
oup_mma()
{
    extern __shared__ char smem[];
    const int h = blockIdx.z;
    const int m0 = blockIdx.y * 128, n0 = 0;
    DECL_COMMON
    const int mrow = m0 + lrow;
    const int arow = (mrow >> 5) * ROWSPB + (mrow & 31) * NH + h;
    const __nv_bfloat16* srcs[4];
    srcs[0] = g_Oh + (size_t)arow * KVR;
    srcs[1] = g_Ol + (size_t)arow * KVR;
    srcs[2] = g_wvh + (size_t)(h * 256 + DNR + n0 + lrow) * KVR;
    srcs[3] = g_wvl + (size_t)(h * 256 + DNR + n0 + lrow) * KVR;
    MAINLOOP_128(8)
    const int r0 = lane >> 2, c0 = (lane & 3) * 2;
#pragma unroll
    for (int mf = 0; mf < 4; mf++) {
        const int mA = m0 + wm + mf * 16 + r0;
#pragma unroll
        for (int nf = 0; nf < 4; nf++) {
            const int n = n0 + wn + nf * 8 + c0;
            const size_t i0 = (size_t)mA * (NH * DV) + h * DV + n;
            const size_t i1 = (size_t)(mA + 8) * (NH * DV) + h * DV + n;
            split_write(acc[mf][nf][0], g_o2h, g_o2l, i0);
            split_write(acc[mf][nf][1], g_o2h, g_o2l, i0 + 1);
            split_write(acc[mf][nf][2], g_o2h, g_o2l, i1);
            split_write(acc[mf][nf][3], g_o2h, g_o2l, i1 + 1);
        }
    }
}

// ====== split-K projections: fp32 atomicAdd epilogue =========================
__global__ void __launch_bounds__(256)
gemm_mma_sk(const __nv_bfloat16* __restrict__ Ah, const __nv_bfloat16* __restrict__ Al,
            const __nv_bfloat16* __restrict__ Bh, const __nv_bfloat16* __restrict__ Bl,
            float* __restrict__ C, int ldc, int K, int kpart, int N)
{
    extern __shared__ char smem[];
    const int m0 = blockIdx.y * 128, n0 = blockIdx.x * 128;
    const int kb = blockIdx.z * kpart;
    DECL_COMMON
    const __nv_bfloat16* srcs[4];
    srcs[0] = Ah + (size_t)(m0 + lrow) * K + kb;
    srcs[1] = Al + (size_t)(m0 + lrow) * K + kb;
    srcs[2] = Bh + (size_t)(n0 + lrow) * K + kb;
    srcs[3] = Bl + (size_t)(n0 + lrow) * K + kb;
    const int nch = kpart >> 6;
    MAINLOOP_128(nch)
    const int r0 = lane >> 2, c0 = (lane & 3) * 2;
#pragma unroll
    for (int mf = 0; mf < 4; mf++) {
        const int mA = m0 + wm + mf * 16 + r0;
#pragma unroll
        for (int nf = 0; nf < 4; nf++) {
            const int n = n0 + wn + nf * 8 + c0;
            if (n < N) {
                atomicAdd(&C[(size_t)mA * ldc + n],           acc[mf][nf][0]);
                atomicAdd(&C[(size_t)mA * ldc + n + 1],       acc[mf][nf][1]);
                atomicAdd(&C[(size_t)(mA + 8) * ldc + n],     acc[mf][nf][2]);
                atomicAdd(&C[(size_t)(mA + 8) * ldc + n + 1], acc[mf][nf][3]);
            }
        }
    }
}

// ====== wide 128x256 scores kernel (2-stage, 192KB) ==========================
#define WSTAGE_B 98304
__global__ void __launch_bounds__(256)
gemm_mma_wide(const __nv_bfloat16* __restrict__ Ah, const __nv_bfloat16* __restrict__ Al, size_t sAz,
              const __nv_bfloat16* __restrict__ Bh, const __nv_bfloat16* __restrict__ Bl, size_t sBz,
              float* __restrict__ C, int ldc, size_t sCz,
              int K, const float* __restrict__ mask, float scale)
{
    extern __shared__ char smem[];
    const int z = blockIdx.z;
    const int m0 = blockIdx.y * 128, n0 = blockIdx.x * 256;
    Ah += (size_t)z * sAz;  Al += (size_t)z * sAz;
    Bh += (size_t)z * sBz;  Bl += (size_t)z * sBz;
    C  += (size_t)z * sCz;

    const int tid = threadIdx.x;
    const int warp = tid >> 5, lane = tid & 31;
    const int wm = (warp >> 2) * 64, wn = (warp & 3) * 64;

    const __nv_bfloat16* gsrc[6];
    uint32_t swb[6];
#pragma unroll
    for (int j = 0; j < 6; j++) {
        const int h = tid + j * 256;
        int t, r;
        if (h < 256)       { t = 0; r = h >> 1; }
        else if (h < 512)  { t = 1; r = (h - 256) >> 1; }
        else if (h < 1024) { t = 2; r = (h - 512) >> 1; }
        else               { t = 3; r = (h - 1024) >> 1; }
        const int half = h & 1;
        const uint32_t tbase = (t == 0) ? 0u : (t == 1) ? 16384u : (t == 2) ? 32768u : 65536u;
        swb[j] = tbase + sw128((uint32_t)r * 128u + half * 64u);
        const __nv_bfloat16* base =
            (t == 0) ? Ah + (size_t)(m0 + r) * K :
            (t == 1) ? Al + (size_t)(m0 + r) * K :
            (t == 2) ? Bh + (size_t)(n0 + r) * K :
                       Bl + (size_t)(n0 + r) * K;
        gsrc[j] = base + half * 32;
    }
    const uint32_t smem32 = smem_u32(smem);
    const int qrow = lane & 15, qsel = lane >> 4;

    float acc[4][8][4];
#pragma unroll
    for (int i = 0; i < 4; i++)
#pragma unroll
        for (int j = 0; j < 8; j++)
#pragma unroll
            for (int r = 0; r < 4; r++) acc[i][j][r] = 0.f;

    const int nch = K >> 6;
    {
#pragma unroll
        for (int j = 0; j < 6; j++)
#pragma unroll
            for (int i = 0; i < 4; i++)
                cpa16(smem32 + (swb[j] ^ (i * 16u)), gsrc[j] + i * 8);
        cpa_commit();
    }
    for (int c = 0; c < nch; c++) {
        if (c + 1 < nch) {
            const int ke = (c + 1) * 64;
            const uint32_t sb = smem32 + ((c + 1) & 1) * WSTAGE_B;
#pragma unroll
            for (int j = 0; j < 6; j++)
#pragma unroll
                for (int i = 0; i < 4; i++)
                    cpa16(sb + (swb[j] ^ (i * 16u)), gsrc[j] + ke + i * 8);
            cpa_commit();
            cpa_wait1();
        } else {
            cpa_wait0();
        }
        __syncthreads();

        const uint32_t st = smem32 + (c & 1) * WSTAGE_B;
        const uint32_t Ah32 = st, Al32 = st + 16384, Bh32 = st + 32768, Bl32 = st + 65536;
#pragma unroll
        for (int ks = 0; ks < 4; ks++) {
            const uint32_t kofs = ks * 32u + qsel * 16u;
            uint32_t ah[4][4];
#pragma unroll
            for (int mf = 0; mf < 4; mf++) {
                int row = wm + mf * 16 + qrow;
                ldm_x4(ah[mf], Ah32 + sw128((uint32_t)row * 128u + kofs));
            }
            uint32_t bh[8][2], bl[8][2];
#pragma unroll
            for (int nh = 0; nh < 4; nh++) {
                int row = wn + nh * 16 + qrow;
                uint32_t t[4];
                ldm_x4(t, Bh32 + sw128((uint32_t)row * 128u + kofs));
                bh[nh * 2 + 0][0] = t[0]; bh[nh * 2 + 0][1] = t[2];
                bh[nh * 2 + 1][0] = t[1]; bh[nh * 2 + 1][1] = t[3];
                ldm_x4(t, Bl32 + sw128((uint32_t)row * 128u + kofs));
                bl[nh * 2 + 0][0] = t[0]; bl[nh * 2 + 0][1] = t[2];
                bl[nh * 2 + 1][0] = t[1]; bl[nh * 2 + 1][1] = t[3];
            }
#pragma unroll
            for (int mf = 0; mf < 4; mf++)
#pragma unroll
                for (int nf = 0; nf < 8; nf++)
                    mma_bf16(acc[mf][nf], ah[mf], bh[nf]);
#pragma unroll
            for (int mf = 0; mf < 4; mf++)
#pragma unroll
                for (int nf = 0; nf < 8; nf++)
                    mma_bf16(acc[mf][nf], ah[mf], bl[nf]);
            uint32_t al[4][4];
#pragma unroll
            for (int mf = 0; mf < 4; mf++) {
                int row = wm + mf * 16 + qrow;
                ldm_x4(al[mf], Al32 + sw128((uint32_t)row * 128u + kofs));
            }
#pragma unroll
            for (int mf = 0; mf < 4; mf++)
#pragma unroll
                for (int nf = 0; nf < 8; nf++)
                    mma_bf16(acc[mf][nf], al[mf], bh[nf]);
        }
        __syncthreads();
    }

    const int r0 = lane >> 2, c0 = (lane & 3) * 2;
#pragma unroll
    for (int mf = 0; mf < 4; mf++) {
        const int mA = m0 + wm + mf * 16 + r0;
        const float* mrow = mask + (size_t)(mA >> 4) * MAXT;
#pragma unroll
        for (int nf = 0; nf < 8; nf++) {
            const int n = n0 + wn + nf * 8 + c0;
            float v0 = acc[mf][nf][0] * scale + mrow[n];
            float v1 = acc[mf][nf][1] * scale + mrow[n + 1];
            float v2 = acc[mf][nf][2] * scale + mrow[n];
            float v3 = acc[mf][nf][3] * scale + mrow[n + 1];
            *(float2*)&C[(size_t)mA * ldc + n]       = make_float2(v0, v1);
            *(float2*)&C[(size_t)(mA + 8) * ldc + n] = make_float2(v2, v3);
        }
    }
}

// ================= merged weight/x conversion ================================
#define C4_X    131072
#define C4_QD   (C4_X + 393216)
#define C4_QU   (C4_QD + 589824)
#define C4_KVD  (C4_QU + 327680)
#define C4_OUT  (C4_KVD + 1048576)
#define C4_WKVU (C4_OUT + 524288)
#define KVD_SRC4 294912
__global__ void conv_all(const float4* __restrict__ x, const float4* __restrict__ wqd,
                         const float4* __restrict__ wqu, const float4* __restrict__ wkvd,
                         const float4* __restrict__ wout, const float4* __restrict__ wkvu) {
    const int i = blockIdx.x * 256 + threadIdx.x;
    if (i < C4_X) {
        split4(x[i], g_xh, g_xl, i);
    } else if (i < C4_QD) {
        const int j = i - C4_X;
        split4(wqd[j], g_wqdh, g_wqdl, j);
    } else if (i < C4_QU) {
        const int j = i - C4_QD;
        split4(wqu[j], g_wquh, g_wqul, j);
    } else if (i < C4_KVD) {
        const int j = i - C4_QU;
        float4 v = (j < KVD_SRC4) ? wkvd[j] : make_float4(0.f, 0.f, 0.f, 0.f);
        split4(v, g_wkvdh, g_wkvdl, j);
    } else if (i < C4_OUT) {
        const int j = i - C4_KVD;
        split4(wout[j], g_wouth, g_woutl, j);
    } else if (i < C4_WKVU) {
        const int j = i - C4_OUT;
        split4(wkvu[j], g_wvh, g_wvl, j);
    }
}

// transpose nr part of w_kvu: out[h][n][d] = w_kvu[(h*256+d)*512 + n]
__global__ void build_wnrt(const float* __restrict__ wkvu) {
    __shared__ float tile[32][33];
    const int h = blockIdx.z;
    const int n0 = blockIdx.x * 32, d0 = blockIdx.y * 32;
    const int tx = threadIdx.x, ty = threadIdx.y;
#pragma unroll
    for (int i = 0; i < 4; i++) {
        const int d = d0 + ty + i * 8;
        tile[ty + i * 8][tx] = wkvu[(size_t)(h * 256 + d) * KVR + n0 + tx];
    }
    __syncthreads();
#pragma unroll
    for (int i = 0; i < 4; i++) {
        const int n = n0 + ty + i * 8;
        const float v = tile[tx][ty + i * 8];
        const size_t o = (size_t)h * KVR * DNR + (size_t)n * DNR + d0 + tx;
        split_write(v, g_wnrth, g_wnrtl, o);
    }
}

// ================= small conversions ========================================
__global__ void conv_split4(const float4* __restrict__ src, __nv_bfloat16* h, __nv_bfloat16* l, int n4) {
    const int i = blockIdx.x * 256 + threadIdx.x;
    if (i < n4) split4(src[i], h, l, i);
}
__global__ void build_kvcat4(const float* __restrict__ kvc, const float* __restrict__ krc) {
    const size_t i4 = (size_t)blockIdx.x * 256 + threadIdx.x;
    const size_t idx = i4 * 4;
    const int c = (int)(idx % CATD);
    const size_t bt = idx / CATD;
    const int t = (int)(bt % MAXT);
    const int b = (int)(bt / MAXT);
    float4 v;
    if (t >= START_P)
        v = *(const float4*)&g_kv[(size_t)((b << 5) + (t - START_P)) * CATD + c];
    else if (c < KVR)
        v = *(const float4*)&kvc[((size_t)b * MAXT + t) * KVR + c];
    else
        v = *(const float4*)&krc[((size_t)b * MAXT + t) * DR + (c - KVR)];
    split4(v, g_kc_h, g_kc_l, i4);
}
__global__ void build_kvt(const float* __restrict__ kvc) {
    __shared__ float tile[32][33];
    const int b = blockIdx.z;
    const int t0 = blockIdx.x * 32, n0 = blockIdx.y * 32;
    const int tx = threadIdx.x, ty = threadIdx.y;
#pragma unroll
    for (int i = 0; i < 4; i++) {
        const int t = t0 + ty + i * 8;
        float v;
        if (t >= START_P)
            v = g_kv[(size_t)((b << 5) + (t - START_P)) * CATD + n0 + tx];
        else
            v = kvc[((size_t)b * MAXT + t) * KVR + n0 + tx];
        tile[ty + i * 8][tx] = v;
    }
    __syncthreads();
#pragma unroll
    for (int i = 0; i < 4; i++) {
        const int n = n0 + ty + i * 8;
        const float x = tile[tx][ty + i * 8];
        const size_t o = ((size_t)(b * KVR + n)) * MAXT + t0 + tx;
        split_write(x, g_kt_h, g_kt_l, o);
    }
}

// ================= RMSNorm ===================================================
__global__ void rms_kernel(const float* __restrict__ w) {
    const int row = blockIdx.x;
    const float* xr = g_qd + row * QR;
    __shared__ float red[256];
    const int tid = threadIdx.x;
    float v[3], s = 0.f;
#pragma unroll
    for (int i = 0; i < 3; i++) { v[i] = xr[tid + i * 256]; s += v[i] * v[i]; }
    red[tid] = s; __syncthreads();
    for (int o = 128; o > 0; o >>= 1) {
        if (tid < o) red[tid] += red[tid + o];
        __syncthreads();
    }
    const float r = rsqrtf(red[0] / (float)QR + 1.1920929e-07f);
    __syncthreads();
#pragma unroll
    for (int i = 0; i < 3; i++) {
        const float y = v[i] * r * w[tid + i * 256];
        split_write(y, g_qnh, g_qnl, (size_t)row * QR + tid + i * 256);
    }
}

// ================= rope (split into q and k parts) ===========================
__global__ void rope_q(const float* __restrict__ fc, const float* __restrict__ fs) {
    const int idx = blockIdx.x * 256 + threadIdx.x;   // 131072 threads
    const int j = idx & 31, h = (idx >> 5) & 15, l = (idx >> 9) & 31, b = idx >> 14;
    const float* src = &g_q[(size_t)(b * SEQ_L + l) * (NH * QKD) + h * QKD + DNR + 2 * j];
    const float xr = src[0], xi = src[1];
    const float c = fc[l * 32 + j], s = fs[l * 32 + j];
    const size_t o = (size_t)(b * ROWSPB + l * NH + h) * CATD + KVR + 2 * j;
    split_write(xr * c - xi * s, g_qc_h, g_qc_l, o);
    split_write(xr * s + xi * c, g_qc_h, g_qc_l, o + 1);
}
__global__ void rope_k(const float* __restrict__ fc, const float* __restrict__ fs) {
    const int k = blockIdx.x * 256 + threadIdx.x;     // 8192 threads
    const int j = k & 31, l = (k >> 5) & 31, b = k >> 10;
    float* p = &g_kv[(size_t)(b * SEQ_L + l) * CATD + KVR + 2 * j];
    const float xr = p[0], xi = p[1];
    const float c = fc[l * 32 + j], s = fs[l * 32 + j];
    p[0] = xr * c - xi * s;
    p[1] = xr * s + xi * c;
}

// ================= softmax -> bf16 hi/lo P ===================================
__global__ void softmax_split() {
    const int row = blockIdx.x;
    float* s = g_S + (size_t)row * MAXT;
    __shared__ float red[256];
    const int tid = threadIdx.x;
    float4 v[4];
    float mx = -INFINITY;
#pragma unroll
    for (int g = 0; g < 4; g++) {
        v[g] = *(float4*)&s[tid * 4 + g * 1024];
        mx = fmaxf(mx, fmaxf(fmaxf(v[g].x, v[g].y), fmaxf(v[g].z, v[g].w)));
    }
    red[tid] = mx; __syncthreads();
    for (int o = 128; o > 0; o >>= 1) {
        if (tid < o) red[tid] = fmaxf(red[tid], red[tid + o]);
        __syncthreads();
    }
    mx = red[0]; __syncthreads();
    float sum = 0.f;
#pragma unroll
    for (int g = 0; g < 4; g++) {
        v[g].x = __expf(v[g].x - mx); v[g].y = __expf(v[g].y - mx);
        v[g].z = __expf(v[g].z - mx); v[g].w = __expf(v[g].w - mx);
        sum += v[g].x + v[g].y + v[g].z + v[g].w;
    }
    red[tid] = sum; __syncthreads();
    for (int o = 128; o > 0; o >>= 1) {
        if (tid < o) red[tid] += red[tid + o];
        __syncthreads();
    }
    const float inv = 1.f / red[0];
#pragma unroll
    for (int g = 0; g < 4; g++) {
        float4 p = make_float4(v[g].x * inv, v[g].y * inv, v[g].z * inv, v[g].w * inv);
        split4(p, g_p_h, g_p_l, ((size_t)row * MAXT + tid * 4 + g * 1024) >> 2);
    }
}

// ============================== launcher =====================================
extern "C" void kernel_launch(void* const* d_in, const int* in_sizes, int n_in,
                              void* d_out, int out_size) {
    const float* x      = (const float*)d_in[0];
    const float* fc     = (const float*)d_in[2];
    const float* fs     = (const float*)d_in[3];
    const float* mask   = (const float*)d_in[4];
    const float* kvc    = (const float*)d_in[5];
    const float* krc    = (const float*)d_in[6];
    const float* w_kvd  = (const float*)d_in[7];
    const float* w_qd   = (const float*)d_in[8];
    const float* rms_w  = (const float*)d_in[9];
    const float* w_qu   = (const float*)d_in[10];
    const float* w_kvu  = (const float*)d_in[11];
    const float* w_out  = (const float*)d_in[12];
    float* out = (float*)d_out;

    float *p_qd, *p_q, *p_kv, *p_S;
    cudaGetSymbolAddress((void**)&p_qd, g_qd);
    cudaGetSymbolAddress((void**)&p_q,  g_q);
    cudaGetSymbolAddress((void**)&p_kv, g_kv);
    cudaGetSymbolAddress((void**)&p_S, g_S);

    __nv_bfloat16 *xh, *xl, *qnh, *qnl, *qh, *ql, *o2h, *o2l, *Oh, *Ol;
    __nv_bfloat16 *wqdh, *wqdl, *wquh, *wqul, *wkvdh, *wkvdl, *wouth, *woutl;
    __nv_bfloat16 *qch, *qcl, *kch, *kcl, *kth, *ktl, *ph, *pl;
    cudaGetSymbolAddress((void**)&xh, g_xh);     cudaGetSymbolAddress((void**)&xl, g_xl);
    cudaGetSymbolAddress((void**)&qnh, g_qnh);   cudaGetSymbolAddress((void**)&qnl, g_qnl);
    cudaGetSymbolAddress((void**)&qh, g_qh);     cudaGetSymbolAddress((void**)&ql, g_ql);
    cudaGetSymbolAddress((void**)&o2h, g_o2h);   cudaGetSymbolAddress((void**)&o2l, g_o2l);
    cudaGetSymbolAddress((void**)&Oh, g_Oh);     cudaGetSymbolAddress((void**)&Ol, g_Ol);
    cudaGetSymbolAddress((void**)&wqdh, g_wqdh); cudaGetSymbolAddress((void**)&wqdl, g_wqdl);
    cudaGetSymbolAddress((void**)&wquh, g_wquh); cudaGetSymbolAddress((void**)&wqul, g_wqul);
    cudaGetSymbolAddress((void**)&wkvdh, g_wkvdh); cudaGetSymbolAddress((void**)&wkvdl, g_wkvdl);
    cudaGetSymbolAddress((void**)&wouth, g_wouth); cudaGetSymbolAddress((void**)&woutl, g_woutl);
    cudaGetSymbolAddress((void**)&qch, g_qc_h);  cudaGetSymbolAddress((void**)&qcl, g_qc_l);
    cudaGetSymbolAddress((void**)&kch, g_kc_h);  cudaGetSymbolAddress((void**)&kcl, g_kc_l);
    cudaGetSymbolAddress((void**)&kth, g_kt_h);  cudaGetSymbolAddress((void**)&ktl, g_kt_l);
    cudaGetSymbolAddress((void**)&ph, g_p_h);    cudaGetSymbolAddress((void**)&pl, g_p_l);

    // one-time resources (created on the uncaptured correctness call)
    static cudaStream_t s_kv = nullptr;
    static cudaEvent_t ev_fork = nullptr, ev_join = nullptr;
    if (!s_kv) {
        cudaStreamCreateWithFlags(&s_kv, cudaStreamNonBlocking);
        cudaEventCreateWithFlags(&ev_fork, cudaEventDisableTiming);
        cudaEventCreateWithFlags(&ev_join, cudaEventDisableTiming);
        cudaFuncSetAttribute(gemm_mma_osplit, cudaFuncAttributeMaxDynamicSharedMemorySize, 3 * STAGE_B);
        cudaFuncSetAttribute(gemm_mma_sk, cudaFuncAttributeMaxDynamicSharedMemorySize, 3 * STAGE_B);
        cudaFuncSetAttribute(qabs_mma, cudaFuncAttributeMaxDynamicSharedMemorySize, 3 * STAGE_B);
        cudaFuncSetAttribute(oup_mma, cudaFuncAttributeMaxDynamicSharedMemorySize, 3 * STAGE_B);
        cudaFuncSetAttribute(gemm_mma_wide, cudaFuncAttributeMaxDynamicSharedMemorySize, 2 * WSTAGE_B);
    }
    const int DSM = 3 * STAGE_B;
    const int WDSM = 2 * WSTAGE_B;

    // ---- root: conversions everything depends on ----
    conv_all<<<C4_WKVU / 256, 256>>>((const float4*)x, (const float4*)w_qd, (const float4*)w_qu,
                                     (const float4*)w_kvd, (const float4*)w_out, (const float4*)w_kvu);
    build_wnrt<<<dim3(KVR / 32, DNR / 32, NH), dim3(32, 8)>>>(w_kvu);

    // ---- fork: kv-path on s_kv, q-path on default stream ----
    cudaEventRecord(ev_fork, 0);
    cudaStreamWaitEvent(s_kv, ev_fork, 0);

    // kv path (s_kv)
    cudaMemsetAsync(p_kv, 0, (size_t)MBL * CATD * 4, s_kv);
    gemm_mma_sk<<<dim3(KVD_PAD / 128, MBL / 128, 8), 256, DSM, s_kv>>>(xh, xl, wkvdh, wkvdl,
        p_kv, CATD, DIM, DIM / 8, CATD);
    rope_k<<<BATCH * SEQ_L * 32 / 256, 256, 0, s_kv>>>(fc, fs);
    build_kvcat4<<<(int)(((size_t)BATCH * MAXT * CATD / 4) / 256), 256, 0, s_kv>>>(kvc, krc);
    build_kvt<<<dim3(MAXT / 32, KVR / 32, BATCH), dim3(32, 8), 0, s_kv>>>(kvc);
    cudaEventRecord(ev_join, s_kv);

    // q path (default stream)
    cudaMemsetAsync(p_qd, 0, (size_t)MBL * QR * 4);
    cudaMemsetAsync(p_q, 0, (size_t)MBL * NH * QKD * 4);
    gemm_mma_sk<<<dim3(QR / 128, MBL / 128, 8), 256, DSM>>>(xh, xl, wqdh, wqdl,
        p_qd, QR, DIM, DIM / 8, QR);
    rms_kernel<<<MBL, 256>>>(rms_w);
    gemm_mma_sk<<<dim3(NH * QKD / 128, MBL / 128, 2), 256, DSM>>>(qnh, qnl, wquh, wqul,
        p_q, NH * QKD, QR, QR / 2, NH * QKD);
    conv_split4<<<(MBL * NH * QKD / 4 + 255) / 256, 256>>>((const float4*)p_q, qh, ql, MBL * NH * QKD / 4);
    rope_q<<<BATCH * SEQ_L * NH * 32 / 256, 256>>>(fc, fs);
    qabs_mma<<<dim3(KVR / 128, MBL / 128, NH), 256, DSM>>>();

    // ---- join ----
    cudaStreamWaitEvent(0, ev_join, 0);

    // ---- attention ----
    gemm_mma_wide<<<dim3(MAXT / 256, ROWSPB / 128, BATCH), 256, WDSM>>>(
        qch, qcl, (size_t)ROWSPB * CATD, kch, kcl, (size_t)MAXT * CATD,
        p_S, MAXT, (size_t)ROWSPB * MAXT, CATD, mask, SCALE_F);
    softmax_split<<<BATCH * ROWSPB, 256>>>();
    gemm_mma_osplit<<<dim3(KVR / 128, ROWSPB / 128, BATCH), 256, DSM>>>(
        ph, pl, (size_t)ROWSPB * MAXT, kth, ktl, (size_t)KVR * MAXT,
        Oh, Ol, KVR, (size_t)ROWSPB * KVR, MAXT);

    // ---- output path ----
    oup_mma<<<dim3(1, MBL / 128, NH), 256, DSM>>>();
    cudaMemsetAsync(out, 0, (size_t)MBL * DIM * 4);
    gemm_mma_sk<<<dim3(DIM / 128, MBL / 128, 8), 256, DSM>>>(o2h, o2l, wouth, woutl,
        out, DIM, NH * DV, NH * DV / 8, DIM);
}